// round 9
// baseline (speedup 1.0000x reference)
#include <cuda_runtime.h>
#include <cuda_fp16.h>
#include <stdint.h>
#include <math.h>

// Problem constants
#define Bb    2
#define Ss    2048
#define HIDD  2048
#define Hh    16
#define DHh   128
#define NBLK  32        // 2048 / 64
#define MROWS 4096      // B*S
#define SCALE_F 0.08838834764831845f   // 1/sqrt(128)

// ---------------- scratch (static device allocations) ----------------
__device__ __half g_xhi[(size_t)MROWS * HIDD];
__device__ __half g_xlo[(size_t)MROWS * HIDD];
__device__ __half g_qhi[(size_t)MROWS * HIDD];
__device__ __half g_qlo[(size_t)MROWS * HIDD];
__device__ __half g_khi[(size_t)MROWS * HIDD];
__device__ __half g_vh [(size_t)MROWS * HIDD];    // V projection, [m][n] fp16
__device__ __half g_vthi[(size_t)MROWS * HIDD];   // [b][h*dh][s]
__device__ __half g_chi[(size_t)MROWS * HIDD];
__device__ __half g_clo[(size_t)MROWS * HIDD];
__device__ __half g_wthi[4][(size_t)HIDD * HIDD];   // W^T [N][K] fp16
__device__ unsigned char g_mask[(size_t)Ss * Ss];
__device__ unsigned char g_bany[NBLK * NBLK];
__device__ int g_flag;

// ======================= PTX helpers (family-portable) =======================
__device__ __forceinline__ uint32_t smem_u32(const void* p) {
    uint32_t a;
    asm("{ .reg .u64 t; cvta.to.shared.u64 t, %1; cvt.u32.u64 %0, t; }"
        : "=r"(a) : "l"(p));
    return a;
}
__device__ __forceinline__ void cp_async16(uint32_t dst, const void* src) {
    asm volatile("cp.async.cg.shared.global [%0], [%1], 16;"
                 :: "r"(dst), "l"(src) : "memory");
}
#define CP_COMMIT() asm volatile("cp.async.commit_group;" ::: "memory")
#define CP_WAIT(n)  asm volatile("cp.async.wait_group %0;" :: "n"(n) : "memory")

__device__ __forceinline__ void ldsm4(uint32_t* r, uint32_t addr) {
    asm volatile("ldmatrix.sync.aligned.m8n8.x4.shared.b16 {%0,%1,%2,%3}, [%4];"
                 : "=r"(r[0]), "=r"(r[1]), "=r"(r[2]), "=r"(r[3]) : "r"(addr));
}
__device__ __forceinline__ void mma16816(float* c, const uint32_t* a, const uint32_t* b) {
    asm volatile(
        "mma.sync.aligned.m16n8k16.row.col.f32.f16.f16.f32 "
        "{%0,%1,%2,%3}, {%4,%5,%6,%7}, {%8,%9}, {%0,%1,%2,%3};"
        : "+f"(c[0]), "+f"(c[1]), "+f"(c[2]), "+f"(c[3])
        : "r"(a[0]), "r"(a[1]), "r"(a[2]), "r"(a[3]), "r"(b[0]), "r"(b[1]));
}

#define SW128(o) ((o) ^ (((o) >> 3) & 0x70))

__device__ __forceinline__ uint32_t pack_h2(float a, float b) {
    __half2 t = __floats2half2_rn(a, b);
    return *(uint32_t*)&t;
}

// ---------------- mask dtype detection + canonicalization ----------------
__global__ void detect_kernel(const unsigned char* __restrict__ raw) {
    int f;
    if (raw[0] == 1 && raw[1] == 1) f = 0;       // u8 / bool
    else if (raw[0] == 1)           f = 1;       // int32
    else                            f = 2;       // float32
    g_flag = f;
}

__global__ void expand_kernel(const void* __restrict__ raw) {
    size_t idx = (size_t)blockIdx.x * blockDim.x + threadIdx.x;
    if (idx >= (size_t)Ss * Ss) return;
    int f = g_flag;
    unsigned char v;
    if (f == 0)      v = ((const unsigned char*)raw)[idx] != 0;
    else if (f == 1) v = ((const int*)raw)[idx] != 0;
    else             v = ((const float*)raw)[idx] != 0.0f;
    g_mask[idx] = v;
}

__global__ void bany_kernel() {
    int qb = blockIdx.y, kb = blockIdx.x;
    int r = threadIdx.x;   // 64 threads
    const unsigned char* row = &g_mask[(size_t)(qb * 64 + r) * Ss + kb * 64];
    int any = 0;
    #pragma unroll 8
    for (int c = 0; c < 64; c++) any |= row[c];
    int res = __syncthreads_or(any);
    if (r == 0) g_bany[qb * NBLK + kb] = res ? 1 : 0;
}

// ---------------- fp32 -> fp16 hi/lo split ----------------
__global__ void split_kernel(const float* __restrict__ in,
                             __half* __restrict__ hi,
                             __half* __restrict__ lo, int n4) {
    int i = blockIdx.x * blockDim.x + threadIdx.x;
    if (i >= n4) return;
    float4 v = ((const float4*)in)[i];
    __half h0 = __float2half_rn(v.x), h1 = __float2half_rn(v.y);
    __half h2 = __float2half_rn(v.z), h3 = __float2half_rn(v.w);
    __half l0 = __float2half_rn(v.x - __half2float(h0));
    __half l1 = __float2half_rn(v.y - __half2float(h1));
    __half l2 = __float2half_rn(v.z - __half2float(h2));
    __half l3 = __float2half_rn(v.w - __half2float(h3));
    ushort4 hv = make_ushort4(__half_as_ushort(h0), __half_as_ushort(h1),
                              __half_as_ushort(h2), __half_as_ushort(h3));
    ushort4 lv = make_ushort4(__half_as_ushort(l0), __half_as_ushort(l1),
                              __half_as_ushort(l2), __half_as_ushort(l3));
    ((ushort4*)hi)[i] = hv;
    ((ushort4*)lo)[i] = lv;
}

// ---------------- batched transpose: W[K][N] -> T[N][K] fp16, z = which W ----
__global__ void tsplit4_kernel(const float* __restrict__ W0,
                               const float* __restrict__ W1,
                               const float* __restrict__ W2,
                               const float* __restrict__ W3) {
    __shared__ float t[32][33];
    int z = blockIdx.z;
    const float* W = (z == 0) ? W0 : (z == 1) ? W1 : (z == 2) ? W2 : W3;
    __half* Thi = g_wthi[z];
    int n0 = blockIdx.x * 32, k0 = blockIdx.y * 32;
    int tx = threadIdx.x, ty = threadIdx.y;   // block (32, 8)
    #pragma unroll
    for (int i = 0; i < 4; i++)
        t[ty + i * 8][tx] = W[(size_t)(k0 + ty + i * 8) * HIDD + n0 + tx];
    __syncthreads();
    #pragma unroll
    for (int i = 0; i < 4; i++)
        Thi[(size_t)(n0 + ty + i * 8) * HIDD + k0 + tx] =
            __float2half_rn(t[tx][ty + i * 8]);
}

// ---------------- transpose V (fp16): g_vh[m][n] -> vt[(b*2048+n)][s] ---------
__global__ void vtsplit_kernel() {
    __shared__ __half t[32][34];
    int n0 = blockIdx.x * 32, m0 = blockIdx.y * 32;
    int tx = threadIdx.x, ty = threadIdx.y;   // block (32, 8)
    #pragma unroll
    for (int i = 0; i < 4; i++)
        t[ty + i * 8][tx] = g_vh[(size_t)(m0 + ty + i * 8) * HIDD + n0 + tx];
    __syncthreads();
    int b = m0 >> 11;
    int s0 = m0 & 2047;
    #pragma unroll
    for (int i = 0; i < 4; i++) {
        size_t o = ((size_t)b * 2048 + n0 + ty + i * 8) * 2048 + s0 + tx;
        g_vthi[o] = t[tx][ty + i * 8];
    }
}

// ---------------- HMMA fp16x2 GEMM core (128x256 CTA tile, 512 thr) ----------
// C = A @ B^T;  A [M][K] split fp16 hi/lo, B [N][K] K-major fp16.
// C += Ahi*B + Alo*B  (fp32 accum).  3-stage cp.async pipeline.
// 16 warps: warp_m = wid&3 (4), warp_n = wid>>2 (4); warp tile 32x64.
#define GK 2048
#define GN 2048
#define NIT 32
#define GTB_A 16384                       // 128 rows x 128 B
#define GTB_B 32768                       // 256 rows x 128 B
#define GSTAGE (2 * GTB_A + GTB_B)        // 65536
#define GSMEM_TOTAL (3 * GSTAGE)          // 196608

__device__ __forceinline__
void gemm_body(const __half* __restrict__ Ahi,
               const __half* __restrict__ Alo,
               const __half* __restrict__ Bh,
               float* __restrict__ C,
               __half* __restrict__ Chi,
               __half* __restrict__ Clo,
               char* smem) {
    uint32_t sb = smem_u32(smem);
    int tid = threadIdx.x, l = tid & 31, wid = tid >> 5;
    int warp_m = wid & 3, warp_n = wid >> 2;
    int bm = blockIdx.y * 128, bn = blockIdx.x * 256;

    const char* srcAh = (const char*)(Ahi + (size_t)bm * GK);
    const char* srcAl = (const char*)(Alo + (size_t)bm * GK);
    const char* srcB  = (const char*)(Bh + (size_t)bn * GK);

    float c[2][8][4];
    #pragma unroll
    for (int i = 0; i < 2; i++)
        #pragma unroll
        for (int j = 0; j < 8; j++)
            #pragma unroll
            for (int k = 0; k < 4; k++) c[i][j][k] = 0.0f;

    auto stage_load = [&](int ci, int st) {
        int koff = ci * 128;
        uint32_t dstA = sb + st * GSTAGE;
        #pragma unroll
        for (int j = 0; j < 2; j++) {              // Ahi, Alo: 2 vec each
            int vec = tid + j * 512;
            int row = vec >> 3, col = (vec & 7) * 16;
            uint32_t so = SW128(row * 128 + col);
            cp_async16(dstA + so, srcAh + (size_t)row * (GK * 2) + koff + col);
            cp_async16(dstA + GTB_A + so, srcAl + (size_t)row * (GK * 2) + koff + col);
        }
        uint32_t dstB = dstA + 2 * GTB_A;
        #pragma unroll
        for (int j = 0; j < 4; j++) {              // B: 4 vec
            int vec = tid + j * 512;
            int row = vec >> 3, col = (vec & 7) * 16;
            cp_async16(dstB + SW128(row * 128 + col),
                       srcB + (size_t)row * (GK * 2) + koff + col);
        }
    };

    int rrA = (l & 7) + ((l >> 3) & 1) * 8;
    int kbA = ((l >> 4) & 1) * 16;
    int rrB = (l & 7) + ((l >> 4) & 1) * 8;
    int kbB = ((l >> 3) & 1) * 16;

    stage_load(0, 0);
    CP_COMMIT();
    stage_load(1, 1);
    CP_COMMIT();

    for (int i = 0; i < NIT; i++) {
        __syncthreads();   // protect slot (i+2)%3 (consumed at iter i-1)
        if (i + 2 < NIT) {
            stage_load(i + 2, (i + 2) % 3);
            CP_COMMIT();
            CP_WAIT(2);
        } else if (i + 1 < NIT) {
            CP_WAIT(1);
        } else {
            CP_WAIT(0);
        }
        __syncthreads();

        uint32_t bAh = sb + (i % 3) * GSTAGE;
        uint32_t bAl = bAh + GTB_A;
        uint32_t bBh = bAh + 2 * GTB_A;

        #pragma unroll
        for (int ks = 0; ks < 4; ks++) {
            int kk = ks * 32;
            // B fragments first (held across mt loop)
            uint32_t bf[8][2];
            #pragma unroll
            for (int np = 0; np < 4; np++) {
                int rb = (warp_n * 64 + np * 16 + rrB) * 128;
                uint32_t off = rb + ((kk + kbB) ^ ((rb >> 3) & 0x70));
                uint32_t t[4];
                ldsm4(t, bBh + off);
                bf[np * 2][0] = t[0]; bf[np * 2][1] = t[1];
                bf[np * 2 + 1][0] = t[2]; bf[np * 2 + 1][1] = t[3];
            }
            // A fragments per mt (keeps register peak low)
            #pragma unroll
            for (int mt = 0; mt < 2; mt++) {
                int rb = (warp_m * 32 + mt * 16 + rrA) * 128;
                uint32_t off = rb + ((kk + kbA) ^ ((rb >> 3) & 0x70));
                uint32_t afh[4], afl[4];
                ldsm4(afh, bAh + off);
                ldsm4(afl, bAl + off);
                #pragma unroll
                for (int nt = 0; nt < 8; nt++) {
                    mma16816(c[mt][nt], afh, bf[nt]);
                    mma16816(c[mt][nt], afl, bf[nt]);
                }
            }
        }
    }

    // epilogue
    #pragma unroll
    for (int mt = 0; mt < 2; mt++) {
        #pragma unroll
        for (int nt = 0; nt < 8; nt++) {
            int m0 = bm + warp_m * 32 + mt * 16 + (l >> 2);
            int cn = bn + warp_n * 64 + nt * 8 + (l & 3) * 2;
            size_t i0 = (size_t)m0 * GN + cn, i1 = (size_t)(m0 + 8) * GN + cn;
            float v0 = c[mt][nt][0], v1 = c[mt][nt][1];
            float v2 = c[mt][nt][2], v3 = c[mt][nt][3];
            if (Chi) {
                __half h0 = __float2half_rn(v0), h1 = __float2half_rn(v1);
                __half h2 = __float2half_rn(v2), h3 = __float2half_rn(v3);
                *(uint32_t*)&Chi[i0] = pack_h2(__half2float(h0), __half2float(h1));
                *(uint32_t*)&Chi[i1] = pack_h2(__half2float(h2), __half2float(h3));
                if (Clo) {
                    *(uint32_t*)&Clo[i0] = pack_h2(v0 - __half2float(h0), v1 - __half2float(h1));
                    *(uint32_t*)&Clo[i1] = pack_h2(v2 - __half2float(h2), v3 - __half2float(h3));
                }
            } else {
                *(float2*)&C[i0] = make_float2(v0, v1);
                *(float2*)&C[i1] = make_float2(v2, v3);
            }
        }
    }
}

// batched QKV projection: z=0 -> Q (hi/lo), z=1 -> K (hi), z=2 -> V (hi)
__global__ __launch_bounds__(512, 1)
void gemm_qkv() {
    extern __shared__ char smem[];
    int z = blockIdx.z;
    const __half* B = g_wthi[z];
    __half* Chi = (z == 0) ? g_qhi : (z == 1) ? g_khi : g_vh;
    __half* Clo = (z == 0) ? g_qlo : nullptr;
    gemm_body(g_xhi, g_xlo, B, nullptr, Chi, Clo, smem);
}

// output projection: fp32 out
__global__ __launch_bounds__(512, 1)
void gemm_out(float* __restrict__ C) {
    extern __shared__ char smem[];
    gemm_body(g_chi, g_clo, g_wthi[3], C, nullptr, nullptr, smem);
}

// ---------------- HMMA fp16x2 flash attention ----------------
// grid (qb=32, h=16, b=2), 128 threads (4 warps). Warp w owns q rows [w*16, w*16+16).
// S = Qhi·K + Qlo·K ; O += Phi·V + Plo·V (K, V fp16 hi only)
#define A_SQ       0                       // Q: hi c0, hi c1, lo c0, lo c1 (4 x 8KB)
#define A_KV(st)   (32768 + (st) * 32768)  // Khi c0 (8KB), Khi c1 (8KB), Vhi (16KB)
#define A_P        98304                   // Phi 8KB, Plo 8KB
#define A_MASK(st) (114688 + (st) * 4096)
#define A_LIST     122880                  // int count + int[32]
#define ATTN2_SMEM 123136

__global__ __launch_bounds__(128, 1)
void attn_mma() {
    extern __shared__ char sm[];
    uint32_t sb = smem_u32(sm);
    int tid = threadIdx.x, l = tid & 31, w = tid >> 5;
    int qb = blockIdx.x, h = blockIdx.y, b = blockIdx.z;

    int rrA = (l & 7) + ((l >> 3) & 1) * 8;
    int kbA = ((l >> 4) & 1) * 16;
    int rrB = (l & 7) + ((l >> 4) & 1) * 8;
    int kbB = ((l >> 3) & 1) * 16;

    const size_t qrow_base = ((size_t)b * Ss + qb * 64) * HIDD;   // elements
    const size_t colb_base = (size_t)h * 256;                     // bytes within row

    // ---- load Q tiles (hi c0, hi c1, lo c0, lo c1) ----
    {
        #pragma unroll
        for (int t = 0; t < 4; t++) {
            const char* base = (const char*)((t < 2) ? g_qhi : g_qlo) + qrow_base * 2
                               + colb_base + (t & 1) * 128;
            uint32_t dst = sb + A_SQ + t * 8192;
            #pragma unroll
            for (int j = 0; j < 4; j++) {
                int vec = tid + j * 128;
                int row = vec >> 3, cbt = (vec & 7) * 16;
                cp_async16(dst + SW128(row * 128 + cbt),
                           base + (size_t)row * 4096 + cbt);
            }
        }
        CP_COMMIT();
    }

    // ---- build visible-kb list ----
    int* sList = (int*)(sm + A_LIST);
    if (tid == 0) {
        int c = 0;
        for (int kb = 0; kb < NBLK; kb++)
            if (g_bany[qb * NBLK + kb]) sList[1 + c++] = kb;
        sList[0] = c;
    }
    __syncthreads();
    int cnt = sList[0];

    // ---- KV + mask prefetch ----
    auto prefetch = [&](int kb, int st) {
        uint32_t kvb = sb + A_KV(st);
        size_t krow = ((size_t)b * Ss + kb * 64) * HIDD * 2;   // bytes
        #pragma unroll
        for (int t = 0; t < 2; t++) {     // Khi chunk 0, chunk 1
            const char* base = (const char*)g_khi + krow + colb_base + t * 128;
            uint32_t dst = kvb + t * 8192;
            #pragma unroll
            for (int j = 0; j < 4; j++) {
                int vec = tid + j * 128;
                int row = vec >> 3, cbt = (vec & 7) * 16;
                cp_async16(dst + SW128(row * 128 + cbt),
                           base + (size_t)row * 4096 + cbt);
            }
        }
        size_t vrow = ((size_t)b * 2048 + h * 128) * 2048 * 2;  // bytes; +dh*4096
        {
            const char* base = (const char*)g_vthi + vrow + kb * 128;
            uint32_t dst = kvb + 16384;
            #pragma unroll
            for (int j = 0; j < 8; j++) {
                int vec = tid + j * 128;
                int row = vec >> 3, cbt = (vec & 7) * 16;
                cp_async16(dst + SW128(row * 128 + cbt),
                           base + (size_t)row * 4096 + cbt);
            }
        }
        {
            const char* base = (const char*)g_mask + (size_t)(qb * 64) * Ss + kb * 64;
            uint32_t dst = sb + A_MASK(st);
            #pragma unroll
            for (int j = 0; j < 2; j++) {
                int vec = tid + j * 128;
                int row = vec >> 2, cbt = (vec & 3) * 16;
                cp_async16(dst + row * 64 + cbt, base + (size_t)row * Ss + cbt);
            }
        }
    };

    prefetch(sList[1], 0);
    CP_COMMIT();

    // ---- state ----
    float o[16][4];
    #pragma unroll
    for (int i = 0; i < 16; i++)
        #pragma unroll
        for (int j = 0; j < 4; j++) o[i][j] = 0.0f;
    float m0r = -1e30f, m1r = -1e30f, l0r = 0.0f, l1r = 0.0f;

    int qrow0 = w * 16;
    int r0l = qrow0 + (l >> 2);

    for (int i = 0; i < cnt; i++) {
        int st = i & 1;
        __syncthreads();   // all warps done with stage st^1 (iter i-1) before refill
        if (i + 1 < cnt) {
            prefetch(sList[1 + i + 1], st ^ 1);
            CP_COMMIT();
            CP_WAIT(1);
        } else {
            CP_WAIT(0);
        }
        __syncthreads();

        uint32_t kvb = sb + A_KV(st);

        // ---- S = Q @ K^T (fp16x2) ----
        float s[8][4];
        #pragma unroll
        for (int nt = 0; nt < 8; nt++)
            #pragma unroll
            for (int j = 0; j < 4; j++) s[nt][j] = 0.0f;

        #pragma unroll
        for (int chunk = 0; chunk < 2; chunk++) {
            uint32_t bQh = sb + A_SQ + chunk * 8192;
            uint32_t bQl = sb + A_SQ + 16384 + chunk * 8192;
            uint32_t bKh = kvb + chunk * 8192;
            #pragma unroll
            for (int ks = 0; ks < 4; ks++) {
                int kk = ks * 32;
                int rowA = qrow0 + rrA;
                uint32_t offA = rowA * 128 + ((kk + kbA) ^ ((rowA & 7) << 4));
                uint32_t ah[4], al[4];
                ldsm4(ah, bQh + offA);
                ldsm4(al, bQl + offA);
                #pragma unroll
                for (int np = 0; np < 4; np++) {
                    int rowB = np * 16 + rrB;
                    uint32_t offB = rowB * 128 + ((kk + kbB) ^ ((rowB & 7) << 4));
                    uint32_t th[4];
                    ldsm4(th, bKh + offB);
                    uint32_t bh0[2] = {th[0], th[1]}, bh1[2] = {th[2], th[3]};
                    mma16816(s[np * 2], ah, bh0);
                    mma16816(s[np * 2], al, bh0);
                    mma16816(s[np * 2 + 1], ah, bh1);
                    mma16816(s[np * 2 + 1], al, bh1);
                }
            }
        }

        // ---- mask + scale + online softmax ----
        const unsigned char* mk = (const unsigned char*)(sm + A_MASK(st))
                                  + r0l * 64 + (l & 3) * 2;
        float mx0 = -1e30f, mx1 = -1e30f;
        #pragma unroll
        for (int nt = 0; nt < 8; nt++) {
            int cb = nt * 8;
            float t00 = mk[cb]       ? s[nt][0] * SCALE_F : -1e30f;
            float t01 = mk[cb + 1]   ? s[nt][1] * SCALE_F : -1e30f;
            float t10 = mk[cb + 512] ? s[nt][2] * SCALE_F : -1e30f;
            float t11 = mk[cb + 513] ? s[nt][3] * SCALE_F : -1e30f;
            s[nt][0] = t00; s[nt][1] = t01; s[nt][2] = t10; s[nt][3] = t11;
            mx0 = fmaxf(mx0, fmaxf(t00, t01));
            mx1 = fmaxf(mx1, fmaxf(t10, t11));
        }
        mx0 = fmaxf(mx0, __shfl_xor_sync(0xffffffffu, mx0, 1));
        mx0 = fmaxf(mx0, __shfl_xor_sync(0xffffffffu, mx0, 2));
        mx1 = fmaxf(mx1, __shfl_xor_sync(0xffffffffu, mx1, 1));
        mx1 = fmaxf(mx1, __shfl_xor_sync(0xffffffffu, mx1, 2));
        float mn0 = fmaxf(m0r, mx0), mn1 = fmaxf(m1r, mx1);
        float sc0 = __expf(m0r - mn0), sc1 = __expf(m1r - mn1);
        m0r = mn0; m1r = mn1;

        // ---- P = exp(S - m), write hi/lo fp16 to smem (full-column swizzle) ----
        float sum0 = 0.0f, sum1 = 0.0f;
        int colb = (l & 3) * 4;
        int sw0 = (r0l & 7) << 4;                 // same for r0l and r0l+8
        uint32_t rb0 = r0l * 128;
        uint32_t rb1 = (r0l + 8) * 128;
        #pragma unroll
        for (int nt = 0; nt < 8; nt++) {
            float p00 = __expf(s[nt][0] - mn0);
            float p01 = __expf(s[nt][1] - mn0);
            float p10 = __expf(s[nt][2] - mn1);
            float p11 = __expf(s[nt][3] - mn1);
            sum0 += p00 + p01;
            sum1 += p10 + p11;
            __half h00 = __float2half_rn(p00), h01 = __float2half_rn(p01);
            __half h10 = __float2half_rn(p10), h11 = __float2half_rn(p11);
            uint32_t colsw = (uint32_t)((nt * 16 + colb) ^ sw0);
            uint32_t a0 = rb0 + colsw;
            uint32_t a1 = rb1 + colsw;
            *(uint32_t*)(sm + A_P + a0) = pack_h2(__half2float(h00), __half2float(h01));
            *(uint32_t*)(sm + A_P + a1) = pack_h2(__half2float(h10), __half2float(h11));
            *(uint32_t*)(sm + A_P + 8192 + a0) =
                pack_h2(p00 - __half2float(h00), p01 - __half2float(h01));
            *(uint32_t*)(sm + A_P + 8192 + a1) =
                pack_h2(p10 - __half2float(h10), p11 - __half2float(h11));
        }
        sum0 += __shfl_xor_sync(0xffffffffu, sum0, 1);
        sum0 += __shfl_xor_sync(0xffffffffu, sum0, 2);
        sum1 += __shfl_xor_sync(0xffffffffu, sum1, 1);
        sum1 += __shfl_xor_sync(0xffffffffu, sum1, 2);
        l0r = l0r * sc0 + sum0;
        l1r = l1r * sc1 + sum1;

        // ---- O rescale + O += P @ Vt (fp16x2) ----
        #pragma unroll
        for (int nt = 0; nt < 16; nt++) {
            o[nt][0] *= sc0; o[nt][1] *= sc0;
            o[nt][2] *= sc1; o[nt][3] *= sc1;
        }
        __syncwarp();

        uint32_t bPh = sb + A_P, bPl = sb + A_P + 8192;
        uint32_t bVh = kvb + 16384;
        #pragma unroll
        for (int ks = 0; ks < 4; ks++) {
            int kk = ks * 32;
            int rowA = qrow0 + rrA;
            uint32_t offA = rowA * 128 + ((kk + kbA) ^ ((rowA & 7) << 4));
            uint32_t ph[4], pl[4];
            ldsm4(ph, bPh + offA);
            ldsm4(pl, bPl + offA);
            #pragma unroll
            for (int np = 0; np < 8; np++) {
                int rowB = np * 16 + rrB;
                uint32_t offB = rowB * 128 + ((kk + kbB) ^ ((rowB & 7) << 4));
                uint32_t th[4];
                ldsm4(th, bVh + offB);
                uint32_t vh0[2] = {th[0], th[1]}, vh1[2] = {th[2], th[3]};
                mma16816(o[np * 2], ph, vh0);
                mma16816(o[np * 2], pl, vh0);
                mma16816(o[np * 2 + 1], ph, vh1);
                mma16816(o[np * 2 + 1], pl, vh1);
            }
        }
    }

    // ---- epilogue: O /= l, write ctx hi/lo fp16 ----
    float inv0 = 1.0f / l0r, inv1 = 1.0f / l1r;
    size_t row0 = (size_t)b * Ss + qb * 64 + qrow0 + (l >> 2);
    size_t row1 = row0 + 8;
    int cn0 = h * 128 + (l & 3) * 2;
    #pragma unroll
    for (int nt = 0; nt < 16; nt++) {
        int cn = cn0 + nt * 8;
        float v0 = o[nt][0] * inv0, v1 = o[nt][1] * inv0;
        float v2 = o[nt][2] * inv1, v3 = o[nt][3] * inv1;
        __half h0 = __float2half_rn(v0), h1 = __float2half_rn(v1);
        __half h2 = __float2half_rn(v2), h3 = __float2half_rn(v3);
        size_t i0 = row0 * HIDD + cn, i1 = row1 * HIDD + cn;
        *(uint32_t*)&g_chi[i0] = pack_h2(__half2float(h0), __half2float(h1));
        *(uint32_t*)&g_chi[i1] = pack_h2(__half2float(h2), __half2float(h3));
        *(uint32_t*)&g_clo[i0] = pack_h2(v0 - __half2float(h0), v1 - __half2float(h1));
        *(uint32_t*)&g_clo[i1] = pack_h2(v2 - __half2float(h2), v3 - __half2float(h3));
    }
}

// ---------------- launch ----------------
extern "C" void kernel_launch(void* const* d_in, const int* in_sizes, int n_in,
                              void* d_out, int out_size) {
    const float* X  = (const float*)d_in[0];
    const float* Wq = (const float*)d_in[1];
    const float* Wk = (const float*)d_in[2];
    const float* Wv = (const float*)d_in[3];
    const float* Wo = (const float*)d_in[4];
    const void*  Mraw = d_in[5];
    float* out = (float*)d_out;

    cudaFuncSetAttribute(gemm_qkv,
                         cudaFuncAttributeMaxDynamicSharedMemorySize, GSMEM_TOTAL);
    cudaFuncSetAttribute(gemm_out,
                         cudaFuncAttributeMaxDynamicSharedMemorySize, GSMEM_TOTAL);
    cudaFuncSetAttribute(attn_mma,
                         cudaFuncAttributeMaxDynamicSharedMemorySize, ATTN2_SMEM);

    __half *pxhi, *pxlo;
    cudaGetSymbolAddress((void**)&pxhi, g_xhi);
    cudaGetSymbolAddress((void**)&pxlo, g_xlo);

    // 1: mask detect, 2: expand, 3: bany
    detect_kernel<<<1, 1>>>((const unsigned char*)Mraw);
    expand_kernel<<<(Ss * Ss) / 256, 256>>>(Mraw);
    bany_kernel<<<dim3(NBLK, NBLK), 64>>>();

    // 4: X split, 5: W transposes (batched)
    split_kernel<<<(MROWS * HIDD / 4 + 255) / 256, 256>>>(X, pxhi, pxlo, MROWS * HIDD / 4);
    tsplit4_kernel<<<dim3(HIDD / 32, HIDD / 32, 4), dim3(32, 8)>>>(Wq, Wk, Wv, Wo);

    // 6: batched Q/K/V projections (fp16x2 HMMA, 128x256 tiles, 512 thr)
    gemm_qkv<<<dim3(GN / 256, MROWS / 128, 3), 512, GSMEM_TOTAL>>>();

    // 7: V transpose (fp16)
    vtsplit_kernel<<<dim3(HIDD / 32, MROWS / 32), dim3(32, 8)>>>();

    // 8: attention
    attn_mma<<<dim3(NBLK, Hh, Bb), 128, ATTN2_SMEM>>>();

    // 9: output projection
    gemm_out<<<dim3(GN / 256, MROWS / 128), 512, GSMEM_TOTAL>>>(out);
}

// round 10
// speedup vs baseline: 1.4634x; 1.4634x over previous
#include <cuda_runtime.h>
#include <cuda_fp16.h>
#include <stdint.h>
#include <math.h>

// Problem constants
#define Bb    2
#define Ss    2048
#define HIDD  2048
#define Hh    16
#define DHh   128
#define NBLK  32        // 2048 / 64
#define MROWS 4096      // B*S
#define SCALE_F 0.08838834764831845f   // 1/sqrt(128)

// ---------------- scratch (static device allocations) ----------------
__device__ __half g_xh [(size_t)MROWS * HIDD];    // X fp16
__device__ __half g_qhi[(size_t)MROWS * HIDD];
__device__ __half g_qlo[(size_t)MROWS * HIDD];
__device__ __half g_khi[(size_t)MROWS * HIDD];
__device__ __half g_vh [(size_t)MROWS * HIDD];    // V projection, [m][n] fp16
__device__ __half g_vthi[(size_t)MROWS * HIDD];   // [b][h*dh][s]
__device__ __half g_chi[(size_t)MROWS * HIDD];    // ctx fp16
__device__ __half g_wthi[4][(size_t)HIDD * HIDD]; // W^T [N][K] fp16
__device__ unsigned char g_mask[(size_t)Ss * Ss];
__device__ unsigned char g_bany[NBLK * NBLK];
__device__ int g_flag;

// ======================= PTX helpers (family-portable) =======================
__device__ __forceinline__ uint32_t smem_u32(const void* p) {
    uint32_t a;
    asm("{ .reg .u64 t; cvta.to.shared.u64 t, %1; cvt.u32.u64 %0, t; }"
        : "=r"(a) : "l"(p));
    return a;
}
__device__ __forceinline__ void cp_async16(uint32_t dst, const void* src) {
    asm volatile("cp.async.cg.shared.global [%0], [%1], 16;"
                 :: "r"(dst), "l"(src) : "memory");
}
#define CP_COMMIT() asm volatile("cp.async.commit_group;" ::: "memory")
#define CP_WAIT(n)  asm volatile("cp.async.wait_group %0;" :: "n"(n) : "memory")

__device__ __forceinline__ void ldsm4(uint32_t* r, uint32_t addr) {
    asm volatile("ldmatrix.sync.aligned.m8n8.x4.shared.b16 {%0,%1,%2,%3}, [%4];"
                 : "=r"(r[0]), "=r"(r[1]), "=r"(r[2]), "=r"(r[3]) : "r"(addr));
}
__device__ __forceinline__ void mma16816(float* c, const uint32_t* a, const uint32_t* b) {
    asm volatile(
        "mma.sync.aligned.m16n8k16.row.col.f32.f16.f16.f32 "
        "{%0,%1,%2,%3}, {%4,%5,%6,%7}, {%8,%9}, {%0,%1,%2,%3};"
        : "+f"(c[0]), "+f"(c[1]), "+f"(c[2]), "+f"(c[3])
        : "r"(a[0]), "r"(a[1]), "r"(a[2]), "r"(a[3]), "r"(b[0]), "r"(b[1]));
}

#define SW128(o) ((o) ^ (((o) >> 3) & 0x70))

__device__ __forceinline__ uint32_t pack_h2(float a, float b) {
    __half2 t = __floats2half2_rn(a, b);
    return *(uint32_t*)&t;
}

// ---------------- mask dtype detection + canonicalization ----------------
__global__ void detect_kernel(const unsigned char* __restrict__ raw) {
    int f;
    if (raw[0] == 1 && raw[1] == 1) f = 0;       // u8 / bool
    else if (raw[0] == 1)           f = 1;       // int32
    else                            f = 2;       // float32
    g_flag = f;
}

__global__ void expand_kernel(const void* __restrict__ raw) {
    size_t idx = (size_t)blockIdx.x * blockDim.x + threadIdx.x;
    if (idx >= (size_t)Ss * Ss) return;
    int f = g_flag;
    unsigned char v;
    if (f == 0)      v = ((const unsigned char*)raw)[idx] != 0;
    else if (f == 1) v = ((const int*)raw)[idx] != 0;
    else             v = ((const float*)raw)[idx] != 0.0f;
    g_mask[idx] = v;
}

__global__ void bany_kernel() {
    int qb = blockIdx.y, kb = blockIdx.x;
    int r = threadIdx.x;   // 64 threads
    const unsigned char* row = &g_mask[(size_t)(qb * 64 + r) * Ss + kb * 64];
    int any = 0;
    #pragma unroll 8
    for (int c = 0; c < 64; c++) any |= row[c];
    int res = __syncthreads_or(any);
    if (r == 0) g_bany[qb * NBLK + kb] = res ? 1 : 0;
}

// ---------------- fp32 -> fp16 convert ----------------
__global__ void cvt_kernel(const float* __restrict__ in,
                           __half* __restrict__ hi, int n4) {
    int i = blockIdx.x * blockDim.x + threadIdx.x;
    if (i >= n4) return;
    float4 v = ((const float4*)in)[i];
    ushort4 hv = make_ushort4(__half_as_ushort(__float2half_rn(v.x)),
                              __half_as_ushort(__float2half_rn(v.y)),
                              __half_as_ushort(__float2half_rn(v.z)),
                              __half_as_ushort(__float2half_rn(v.w)));
    ((ushort4*)hi)[i] = hv;
}

// ---------------- batched transpose: W[K][N] -> T[N][K] fp16, z = which W ----
__global__ void tsplit4_kernel(const float* __restrict__ W0,
                               const float* __restrict__ W1,
                               const float* __restrict__ W2,
                               const float* __restrict__ W3) {
    __shared__ float t[32][33];
    int z = blockIdx.z;
    const float* W = (z == 0) ? W0 : (z == 1) ? W1 : (z == 2) ? W2 : W3;
    __half* Thi = g_wthi[z];
    int n0 = blockIdx.x * 32, k0 = blockIdx.y * 32;
    int tx = threadIdx.x, ty = threadIdx.y;   // block (32, 8)
    #pragma unroll
    for (int i = 0; i < 4; i++)
        t[ty + i * 8][tx] = W[(size_t)(k0 + ty + i * 8) * HIDD + n0 + tx];
    __syncthreads();
    #pragma unroll
    for (int i = 0; i < 4; i++)
        Thi[(size_t)(n0 + ty + i * 8) * HIDD + k0 + tx] =
            __float2half_rn(t[tx][ty + i * 8]);
}

// ---------------- transpose V (fp16): g_vh[m][n] -> vt[(b*2048+n)][s] ---------
__global__ void vtsplit_kernel() {
    __shared__ __half t[32][34];
    int n0 = blockIdx.x * 32, m0 = blockIdx.y * 32;
    int tx = threadIdx.x, ty = threadIdx.y;   // block (32, 8)
    #pragma unroll
    for (int i = 0; i < 4; i++)
        t[ty + i * 8][tx] = g_vh[(size_t)(m0 + ty + i * 8) * HIDD + n0 + tx];
    __syncthreads();
    int b = m0 >> 11;
    int s0 = m0 & 2047;
    #pragma unroll
    for (int i = 0; i < 4; i++) {
        size_t o = ((size_t)b * 2048 + n0 + ty + i * 8) * 2048 + s0 + tx;
        g_vthi[o] = t[tx][ty + i * 8];
    }
}

// ---------------- HMMA fp16 GEMM core (128x256 CTA tile, 256 thr) ------------
// C = A @ B^T;  A [M][K] fp16, B [N][K] K-major fp16.  Single product, fp32 accum.
// 8 warps: warp_m = wid&1 (2), warp_n = wid>>1 (4); warp tile 64x64.
#define GK 2048
#define GN 2048
#define NIT 32
#define GTB_A 16384                       // 128 rows x 128 B
#define GTB_B 32768                       // 256 rows x 128 B
#define GSTAGE (GTB_A + GTB_B)            // 49152
#define GSMEM_TOTAL (3 * GSTAGE)          // 147456

__device__ __forceinline__
void gemm_body(const __half* __restrict__ Ah,
               const __half* __restrict__ Bh,
               float* __restrict__ C,
               __half* __restrict__ Chi,
               __half* __restrict__ Clo,
               char* smem) {
    uint32_t sb = smem_u32(smem);
    int tid = threadIdx.x, l = tid & 31, wid = tid >> 5;
    int warp_m = wid & 1, warp_n = wid >> 1;
    int bm = blockIdx.y * 128, bn = blockIdx.x * 256;

    const char* srcA = (const char*)(Ah + (size_t)bm * GK);
    const char* srcB = (const char*)(Bh + (size_t)bn * GK);

    float c[4][8][4];
    #pragma unroll
    for (int i = 0; i < 4; i++)
        #pragma unroll
        for (int j = 0; j < 8; j++)
            #pragma unroll
            for (int k = 0; k < 4; k++) c[i][j][k] = 0.0f;

    auto stage_load = [&](int ci, int st) {
        int koff = ci * 128;
        uint32_t dstA = sb + st * GSTAGE;
        #pragma unroll
        for (int j = 0; j < 4; j++) {              // A: 4 vec
            int vec = tid + j * 256;
            int row = vec >> 3, col = (vec & 7) * 16;
            cp_async16(dstA + SW128(row * 128 + col),
                       srcA + (size_t)row * (GK * 2) + koff + col);
        }
        uint32_t dstB = dstA + GTB_A;
        #pragma unroll
        for (int j = 0; j < 8; j++) {              // B: 8 vec
            int vec = tid + j * 256;
            int row = vec >> 3, col = (vec & 7) * 16;
            cp_async16(dstB + SW128(row * 128 + col),
                       srcB + (size_t)row * (GK * 2) + koff + col);
        }
    };

    int rrA = (l & 7) + ((l >> 3) & 1) * 8;
    int kbA = ((l >> 4) & 1) * 16;
    int rrB = (l & 7) + ((l >> 4) & 1) * 8;
    int kbB = ((l >> 3) & 1) * 16;

    stage_load(0, 0);
    CP_COMMIT();
    stage_load(1, 1);
    CP_COMMIT();

    for (int i = 0; i < NIT; i++) {
        __syncthreads();   // protect slot (i+2)%3 (consumed at iter i-1)
        if (i + 2 < NIT) {
            stage_load(i + 2, (i + 2) % 3);
            CP_COMMIT();
            CP_WAIT(2);
        } else if (i + 1 < NIT) {
            CP_WAIT(1);
        } else {
            CP_WAIT(0);
        }
        __syncthreads();

        uint32_t bA = sb + (i % 3) * GSTAGE;
        uint32_t bB = bA + GTB_A;

        #pragma unroll
        for (int ks = 0; ks < 4; ks++) {
            int kk = ks * 32;
            uint32_t bf[8][2];
            #pragma unroll
            for (int np = 0; np < 4; np++) {
                int rb = (warp_n * 64 + np * 16 + rrB) * 128;
                uint32_t off = rb + ((kk + kbB) ^ ((rb >> 3) & 0x70));
                uint32_t t[4];
                ldsm4(t, bB + off);
                bf[np * 2][0] = t[0]; bf[np * 2][1] = t[1];
                bf[np * 2 + 1][0] = t[2]; bf[np * 2 + 1][1] = t[3];
            }
            #pragma unroll
            for (int mt = 0; mt < 4; mt++) {
                int rb = (warp_m * 64 + mt * 16 + rrA) * 128;
                uint32_t off = rb + ((kk + kbA) ^ ((rb >> 3) & 0x70));
                uint32_t af[4];
                ldsm4(af, bA + off);
                #pragma unroll
                for (int nt = 0; nt < 8; nt++)
                    mma16816(c[mt][nt], af, bf[nt]);
            }
        }
    }

    // epilogue
    #pragma unroll
    for (int mt = 0; mt < 4; mt++) {
        #pragma unroll
        for (int nt = 0; nt < 8; nt++) {
            int m0 = bm + warp_m * 64 + mt * 16 + (l >> 2);
            int cn = bn + warp_n * 64 + nt * 8 + (l & 3) * 2;
            size_t i0 = (size_t)m0 * GN + cn, i1 = (size_t)(m0 + 8) * GN + cn;
            float v0 = c[mt][nt][0], v1 = c[mt][nt][1];
            float v2 = c[mt][nt][2], v3 = c[mt][nt][3];
            if (Chi) {
                __half h0 = __float2half_rn(v0), h1 = __float2half_rn(v1);
                __half h2 = __float2half_rn(v2), h3 = __float2half_rn(v3);
                *(uint32_t*)&Chi[i0] = pack_h2(__half2float(h0), __half2float(h1));
                *(uint32_t*)&Chi[i1] = pack_h2(__half2float(h2), __half2float(h3));
                if (Clo) {
                    *(uint32_t*)&Clo[i0] = pack_h2(v0 - __half2float(h0), v1 - __half2float(h1));
                    *(uint32_t*)&Clo[i1] = pack_h2(v2 - __half2float(h2), v3 - __half2float(h3));
                }
            } else {
                *(float2*)&C[i0] = make_float2(v0, v1);
                *(float2*)&C[i1] = make_float2(v2, v3);
            }
        }
    }
}

// batched QKV projection: z=0 -> Q (hi/lo), z=1 -> K (hi), z=2 -> V (hi)
__global__ __launch_bounds__(256, 1)
void gemm_qkv() {
    extern __shared__ char smem[];
    int z = blockIdx.z;
    const __half* B = g_wthi[z];
    __half* Chi = (z == 0) ? g_qhi : (z == 1) ? g_khi : g_vh;
    __half* Clo = (z == 0) ? g_qlo : nullptr;
    gemm_body(g_xh, B, nullptr, Chi, Clo, smem);
}

// output projection: fp32 out
__global__ __launch_bounds__(256, 1)
void gemm_out(float* __restrict__ C) {
    extern __shared__ char smem[];
    gemm_body(g_chi, g_wthi[3], C, nullptr, nullptr, smem);
}

// ---------------- HMMA fp16x2 flash attention (unchanged numerics) ----------
// grid (qb=32, h=16, b=2), 128 threads (4 warps). Warp w owns q rows [w*16, w*16+16).
// S = Qhi·K + Qlo·K ; O += Phi·V + Plo·V (K, V fp16 hi only)
#define A_SQ       0                       // Q: hi c0, hi c1, lo c0, lo c1 (4 x 8KB)
#define A_KV(st)   (32768 + (st) * 32768)  // Khi c0 (8KB), Khi c1 (8KB), Vhi (16KB)
#define A_P        98304                   // Phi 8KB, Plo 8KB
#define A_MASK(st) (114688 + (st) * 4096)
#define A_LIST     122880                  // int count + int[32]
#define ATTN2_SMEM 123136

__global__ __launch_bounds__(128, 1)
void attn_mma() {
    extern __shared__ char sm[];
    uint32_t sb = smem_u32(sm);
    int tid = threadIdx.x, l = tid & 31, w = tid >> 5;
    int qb = blockIdx.x, h = blockIdx.y, b = blockIdx.z;

    int rrA = (l & 7) + ((l >> 3) & 1) * 8;
    int kbA = ((l >> 4) & 1) * 16;
    int rrB = (l & 7) + ((l >> 4) & 1) * 8;
    int kbB = ((l >> 3) & 1) * 16;

    const size_t qrow_base = ((size_t)b * Ss + qb * 64) * HIDD;   // elements
    const size_t colb_base = (size_t)h * 256;                     // bytes within row

    // ---- load Q tiles (hi c0, hi c1, lo c0, lo c1) ----
    {
        #pragma unroll
        for (int t = 0; t < 4; t++) {
            const char* base = (const char*)((t < 2) ? g_qhi : g_qlo) + qrow_base * 2
                               + colb_base + (t & 1) * 128;
            uint32_t dst = sb + A_SQ + t * 8192;
            #pragma unroll
            for (int j = 0; j < 4; j++) {
                int vec = tid + j * 128;
                int row = vec >> 3, cbt = (vec & 7) * 16;
                cp_async16(dst + SW128(row * 128 + cbt),
                           base + (size_t)row * 4096 + cbt);
            }
        }
        CP_COMMIT();
    }

    // ---- build visible-kb list ----
    int* sList = (int*)(sm + A_LIST);
    if (tid == 0) {
        int c = 0;
        for (int kb = 0; kb < NBLK; kb++)
            if (g_bany[qb * NBLK + kb]) sList[1 + c++] = kb;
        sList[0] = c;
    }
    __syncthreads();
    int cnt = sList[0];

    // ---- KV + mask prefetch ----
    auto prefetch = [&](int kb, int st) {
        uint32_t kvb = sb + A_KV(st);
        size_t krow = ((size_t)b * Ss + kb * 64) * HIDD * 2;   // bytes
        #pragma unroll
        for (int t = 0; t < 2; t++) {     // Khi chunk 0, chunk 1
            const char* base = (const char*)g_khi + krow + colb_base + t * 128;
            uint32_t dst = kvb + t * 8192;
            #pragma unroll
            for (int j = 0; j < 4; j++) {
                int vec = tid + j * 128;
                int row = vec >> 3, cbt = (vec & 7) * 16;
                cp_async16(dst + SW128(row * 128 + cbt),
                           base + (size_t)row * 4096 + cbt);
            }
        }
        size_t vrow = ((size_t)b * 2048 + h * 128) * 2048 * 2;  // bytes; +dh*4096
        {
            const char* base = (const char*)g_vthi + vrow + kb * 128;
            uint32_t dst = kvb + 16384;
            #pragma unroll
            for (int j = 0; j < 8; j++) {
                int vec = tid + j * 128;
                int row = vec >> 3, cbt = (vec & 7) * 16;
                cp_async16(dst + SW128(row * 128 + cbt),
                           base + (size_t)row * 4096 + cbt);
            }
        }
        {
            const char* base = (const char*)g_mask + (size_t)(qb * 64) * Ss + kb * 64;
            uint32_t dst = sb + A_MASK(st);
            #pragma unroll
            for (int j = 0; j < 2; j++) {
                int vec = tid + j * 128;
                int row = vec >> 2, cbt = (vec & 3) * 16;
                cp_async16(dst + row * 64 + cbt, base + (size_t)row * Ss + cbt);
            }
        }
    };

    prefetch(sList[1], 0);
    CP_COMMIT();

    // ---- state ----
    float o[16][4];
    #pragma unroll
    for (int i = 0; i < 16; i++)
        #pragma unroll
        for (int j = 0; j < 4; j++) o[i][j] = 0.0f;
    float m0r = -1e30f, m1r = -1e30f, l0r = 0.0f, l1r = 0.0f;

    int qrow0 = w * 16;
    int r0l = qrow0 + (l >> 2);

    for (int i = 0; i < cnt; i++) {
        int st = i & 1;
        __syncthreads();   // all warps done with stage st^1 (iter i-1) before refill
        if (i + 1 < cnt) {
            prefetch(sList[1 + i + 1], st ^ 1);
            CP_COMMIT();
            CP_WAIT(1);
        } else {
            CP_WAIT(0);
        }
        __syncthreads();

        uint32_t kvb = sb + A_KV(st);

        // ---- S = Q @ K^T (fp16x2) ----
        float s[8][4];
        #pragma unroll
        for (int nt = 0; nt < 8; nt++)
            #pragma unroll
            for (int j = 0; j < 4; j++) s[nt][j] = 0.0f;

        #pragma unroll
        for (int chunk = 0; chunk < 2; chunk++) {
            uint32_t bQh = sb + A_SQ + chunk * 8192;
            uint32_t bQl = sb + A_SQ + 16384 + chunk * 8192;
            uint32_t bKh = kvb + chunk * 8192;
            #pragma unroll
            for (int ks = 0; ks < 4; ks++) {
                int kk = ks * 32;
                int rowA = qrow0 + rrA;
                uint32_t offA = rowA * 128 + ((kk + kbA) ^ ((rowA & 7) << 4));
                uint32_t ah[4], al[4];
                ldsm4(ah, bQh + offA);
                ldsm4(al, bQl + offA);
                #pragma unroll
                for (int np = 0; np < 4; np++) {
                    int rowB = np * 16 + rrB;
                    uint32_t offB = rowB * 128 + ((kk + kbB) ^ ((rowB & 7) << 4));
                    uint32_t th[4];
                    ldsm4(th, bKh + offB);
                    uint32_t bh0[2] = {th[0], th[1]}, bh1[2] = {th[2], th[3]};
                    mma16816(s[np * 2], ah, bh0);
                    mma16816(s[np * 2], al, bh0);
                    mma16816(s[np * 2 + 1], ah, bh1);
                    mma16816(s[np * 2 + 1], al, bh1);
                }
            }
        }

        // ---- mask + scale + online softmax ----
        const unsigned char* mk = (const unsigned char*)(sm + A_MASK(st))
                                  + r0l * 64 + (l & 3) * 2;
        float mx0 = -1e30f, mx1 = -1e30f;
        #pragma unroll
        for (int nt = 0; nt < 8; nt++) {
            int cb = nt * 8;
            float t00 = mk[cb]       ? s[nt][0] * SCALE_F : -1e30f;
            float t01 = mk[cb + 1]   ? s[nt][1] * SCALE_F : -1e30f;
            float t10 = mk[cb + 512] ? s[nt][2] * SCALE_F : -1e30f;
            float t11 = mk[cb + 513] ? s[nt][3] * SCALE_F : -1e30f;
            s[nt][0] = t00; s[nt][1] = t01; s[nt][2] = t10; s[nt][3] = t11;
            mx0 = fmaxf(mx0, fmaxf(t00, t01));
            mx1 = fmaxf(mx1, fmaxf(t10, t11));
        }
        mx0 = fmaxf(mx0, __shfl_xor_sync(0xffffffffu, mx0, 1));
        mx0 = fmaxf(mx0, __shfl_xor_sync(0xffffffffu, mx0, 2));
        mx1 = fmaxf(mx1, __shfl_xor_sync(0xffffffffu, mx1, 1));
        mx1 = fmaxf(mx1, __shfl_xor_sync(0xffffffffu, mx1, 2));
        float mn0 = fmaxf(m0r, mx0), mn1 = fmaxf(m1r, mx1);
        float sc0 = __expf(m0r - mn0), sc1 = __expf(m1r - mn1);
        m0r = mn0; m1r = mn1;

        // ---- P = exp(S - m), write hi/lo fp16 to smem (full-column swizzle) ----
        float sum0 = 0.0f, sum1 = 0.0f;
        int colb = (l & 3) * 4;
        int sw0 = (r0l & 7) << 4;                 // same for r0l and r0l+8
        uint32_t rb0 = r0l * 128;
        uint32_t rb1 = (r0l + 8) * 128;
        #pragma unroll
        for (int nt = 0; nt < 8; nt++) {
            float p00 = __expf(s[nt][0] - mn0);
            float p01 = __expf(s[nt][1] - mn0);
            float p10 = __expf(s[nt][2] - mn1);
            float p11 = __expf(s[nt][3] - mn1);
            sum0 += p00 + p01;
            sum1 += p10 + p11;
            __half h00 = __float2half_rn(p00), h01 = __float2half_rn(p01);
            __half h10 = __float2half_rn(p10), h11 = __float2half_rn(p11);
            uint32_t colsw = (uint32_t)((nt * 16 + colb) ^ sw0);
            uint32_t a0 = rb0 + colsw;
            uint32_t a1 = rb1 + colsw;
            *(uint32_t*)(sm + A_P + a0) = pack_h2(__half2float(h00), __half2float(h01));
            *(uint32_t*)(sm + A_P + a1) = pack_h2(__half2float(h10), __half2float(h11));
            *(uint32_t*)(sm + A_P + 8192 + a0) =
                pack_h2(p00 - __half2float(h00), p01 - __half2float(h01));
            *(uint32_t*)(sm + A_P + 8192 + a1) =
                pack_h2(p10 - __half2float(h10), p11 - __half2float(h11));
        }
        sum0 += __shfl_xor_sync(0xffffffffu, sum0, 1);
        sum0 += __shfl_xor_sync(0xffffffffu, sum0, 2);
        sum1 += __shfl_xor_sync(0xffffffffu, sum1, 1);
        sum1 += __shfl_xor_sync(0xffffffffu, sum1, 2);
        l0r = l0r * sc0 + sum0;
        l1r = l1r * sc1 + sum1;

        // ---- O rescale + O += P @ Vt (fp16x2) ----
        #pragma unroll
        for (int nt = 0; nt < 16; nt++) {
            o[nt][0] *= sc0; o[nt][1] *= sc0;
            o[nt][2] *= sc1; o[nt][3] *= sc1;
        }
        __syncwarp();

        uint32_t bPh = sb + A_P, bPl = sb + A_P + 8192;
        uint32_t bVh = kvb + 16384;
        #pragma unroll
        for (int ks = 0; ks < 4; ks++) {
            int kk = ks * 32;
            int rowA = qrow0 + rrA;
            uint32_t offA = rowA * 128 + ((kk + kbA) ^ ((rowA & 7) << 4));
            uint32_t ph[4], pl[4];
            ldsm4(ph, bPh + offA);
            ldsm4(pl, bPl + offA);
            #pragma unroll
            for (int np = 0; np < 8; np++) {
                int rowB = np * 16 + rrB;
                uint32_t offB = rowB * 128 + ((kk + kbB) ^ ((rowB & 7) << 4));
                uint32_t th[4];
                ldsm4(th, bVh + offB);
                uint32_t vh0[2] = {th[0], th[1]}, vh1[2] = {th[2], th[3]};
                mma16816(o[np * 2], ph, vh0);
                mma16816(o[np * 2], pl, vh0);
                mma16816(o[np * 2 + 1], ph, vh1);
                mma16816(o[np * 2 + 1], pl, vh1);
            }
        }
    }

    // ---- epilogue: O /= l, write ctx fp16 (hi only) ----
    float inv0 = 1.0f / l0r, inv1 = 1.0f / l1r;
    size_t row0 = (size_t)b * Ss + qb * 64 + qrow0 + (l >> 2);
    size_t row1 = row0 + 8;
    int cn0 = h * 128 + (l & 3) * 2;
    #pragma unroll
    for (int nt = 0; nt < 16; nt++) {
        int cn = cn0 + nt * 8;
        float v0 = o[nt][0] * inv0, v1 = o[nt][1] * inv0;
        float v2 = o[nt][2] * inv1, v3 = o[nt][3] * inv1;
        size_t i0 = row0 * HIDD + cn, i1 = row1 * HIDD + cn;
        *(uint32_t*)&g_chi[i0] = pack_h2(v0, v1);
        *(uint32_t*)&g_chi[i1] = pack_h2(v2, v3);
    }
}

// ---------------- launch ----------------
extern "C" void kernel_launch(void* const* d_in, const int* in_sizes, int n_in,
                              void* d_out, int out_size) {
    const float* X  = (const float*)d_in[0];
    const float* Wq = (const float*)d_in[1];
    const float* Wk = (const float*)d_in[2];
    const float* Wv = (const float*)d_in[3];
    const float* Wo = (const float*)d_in[4];
    const void*  Mraw = d_in[5];
    float* out = (float*)d_out;

    cudaFuncSetAttribute(gemm_qkv,
                         cudaFuncAttributeMaxDynamicSharedMemorySize, GSMEM_TOTAL);
    cudaFuncSetAttribute(gemm_out,
                         cudaFuncAttributeMaxDynamicSharedMemorySize, GSMEM_TOTAL);
    cudaFuncSetAttribute(attn_mma,
                         cudaFuncAttributeMaxDynamicSharedMemorySize, ATTN2_SMEM);

    __half* pxh;
    cudaGetSymbolAddress((void**)&pxh, g_xh);

    // 1: mask detect, 2: expand, 3: bany
    detect_kernel<<<1, 1>>>((const unsigned char*)Mraw);
    expand_kernel<<<(Ss * Ss) / 256, 256>>>(Mraw);
    bany_kernel<<<dim3(NBLK, NBLK), 64>>>();

    // 4: X convert, 5: W transposes (batched)
    cvt_kernel<<<(MROWS * HIDD / 4 + 255) / 256, 256>>>(X, pxh, MROWS * HIDD / 4);
    tsplit4_kernel<<<dim3(HIDD / 32, HIDD / 32, 4), dim3(32, 8)>>>(Wq, Wk, Wv, Wo);

    // 6: batched Q/K/V projections (fp16 HMMA, 128x256 tiles)
    gemm_qkv<<<dim3(GN / 256, MROWS / 128, 3), 256, GSMEM_TOTAL>>>();

    // 7: V transpose (fp16)
    vtsplit_kernel<<<dim3(HIDD / 32, MROWS / 32), dim3(32, 8)>>>();

    // 8: attention
    attn_mma<<<dim3(NBLK, Hh, Bb), 128, ATTN2_SMEM>>>();

    // 9: output projection
    gemm_out<<<dim3(GN / 256, MROWS / 128), 256, GSMEM_TOTAL>>>(out);
}

// round 11
// speedup vs baseline: 1.6246x; 1.1102x over previous
#include <cuda_runtime.h>
#include <cuda_fp16.h>
#include <stdint.h>
#include <math.h>

// Problem constants
#define Bb    2
#define Ss    2048
#define HIDD  2048
#define Hh    16
#define DHh   128
#define NBLK  32        // 2048 / 64
#define MROWS 4096      // B*S
#define SCALE_F 0.08838834764831845f   // 1/sqrt(128)

// ---------------- scratch (static device allocations) ----------------
__device__ __half g_xh [(size_t)MROWS * HIDD];    // X fp16
__device__ __half g_qhi[(size_t)MROWS * HIDD];
__device__ __half g_khi[(size_t)MROWS * HIDD];
__device__ __half g_vh [(size_t)MROWS * HIDD];    // V projection, [m][n] fp16
__device__ __half g_vthi[(size_t)MROWS * HIDD];   // [b][h*dh][s]
__device__ __half g_chi[(size_t)MROWS * HIDD];    // ctx fp16
__device__ __half g_wthi[4][(size_t)HIDD * HIDD]; // W^T [N][K] fp16
__device__ unsigned char g_mask[(size_t)Ss * Ss];
__device__ unsigned char g_bany[NBLK * NBLK];
__device__ int g_flag;

// ======================= PTX helpers (family-portable) =======================
__device__ __forceinline__ uint32_t smem_u32(const void* p) {
    uint32_t a;
    asm("{ .reg .u64 t; cvta.to.shared.u64 t, %1; cvt.u32.u64 %0, t; }"
        : "=r"(a) : "l"(p));
    return a;
}
__device__ __forceinline__ void cp_async16(uint32_t dst, const void* src) {
    asm volatile("cp.async.cg.shared.global [%0], [%1], 16;"
                 :: "r"(dst), "l"(src) : "memory");
}
#define CP_COMMIT() asm volatile("cp.async.commit_group;" ::: "memory")
#define CP_WAIT(n)  asm volatile("cp.async.wait_group %0;" :: "n"(n) : "memory")

__device__ __forceinline__ void ldsm4(uint32_t* r, uint32_t addr) {
    asm volatile("ldmatrix.sync.aligned.m8n8.x4.shared.b16 {%0,%1,%2,%3}, [%4];"
                 : "=r"(r[0]), "=r"(r[1]), "=r"(r[2]), "=r"(r[3]) : "r"(addr));
}
__device__ __forceinline__ void mma16816(float* c, const uint32_t* a, const uint32_t* b) {
    asm volatile(
        "mma.sync.aligned.m16n8k16.row.col.f32.f16.f16.f32 "
        "{%0,%1,%2,%3}, {%4,%5,%6,%7}, {%8,%9}, {%0,%1,%2,%3};"
        : "+f"(c[0]), "+f"(c[1]), "+f"(c[2]), "+f"(c[3])
        : "r"(a[0]), "r"(a[1]), "r"(a[2]), "r"(a[3]), "r"(b[0]), "r"(b[1]));
}

#define SW128(o) ((o) ^ (((o) >> 3) & 0x70))

__device__ __forceinline__ uint32_t pack_h2(float a, float b) {
    __half2 t = __floats2half2_rn(a, b);
    return *(uint32_t*)&t;
}

// ---------------- mask dtype detection + canonicalization ----------------
__global__ void detect_kernel(const unsigned char* __restrict__ raw) {
    int f;
    if (raw[0] == 1 && raw[1] == 1) f = 0;       // u8 / bool
    else if (raw[0] == 1)           f = 1;       // int32
    else                            f = 2;       // float32
    g_flag = f;
}

__global__ void expand_kernel(const void* __restrict__ raw) {
    size_t idx = (size_t)blockIdx.x * blockDim.x + threadIdx.x;
    if (idx >= (size_t)Ss * Ss) return;
    int f = g_flag;
    unsigned char v;
    if (f == 0)      v = ((const unsigned char*)raw)[idx] != 0;
    else if (f == 1) v = ((const int*)raw)[idx] != 0;
    else             v = ((const float*)raw)[idx] != 0.0f;
    g_mask[idx] = v;
}

__global__ void bany_kernel() {
    int qb = blockIdx.y, kb = blockIdx.x;
    int r = threadIdx.x;   // 64 threads
    const unsigned char* row = &g_mask[(size_t)(qb * 64 + r) * Ss + kb * 64];
    int any = 0;
    #pragma unroll 8
    for (int c = 0; c < 64; c++) any |= row[c];
    int res = __syncthreads_or(any);
    if (r == 0) g_bany[qb * NBLK + kb] = res ? 1 : 0;
}

// ---------------- fp32 -> fp16 convert ----------------
__global__ void cvt_kernel(const float* __restrict__ in,
                           __half* __restrict__ hi, int n4) {
    int i = blockIdx.x * blockDim.x + threadIdx.x;
    if (i >= n4) return;
    float4 v = ((const float4*)in)[i];
    ushort4 hv = make_ushort4(__half_as_ushort(__float2half_rn(v.x)),
                              __half_as_ushort(__float2half_rn(v.y)),
                              __half_as_ushort(__float2half_rn(v.z)),
                              __half_as_ushort(__float2half_rn(v.w)));
    ((ushort4*)hi)[i] = hv;
}

// ---------------- batched transpose: W[K][N] -> T[N][K] fp16, z = which W ----
__global__ void tsplit4_kernel(const float* __restrict__ W0,
                               const float* __restrict__ W1,
                               const float* __restrict__ W2,
                               const float* __restrict__ W3) {
    __shared__ float t[32][33];
    int z = blockIdx.z;
    const float* W = (z == 0) ? W0 : (z == 1) ? W1 : (z == 2) ? W2 : W3;
    __half* Thi = g_wthi[z];
    int n0 = blockIdx.x * 32, k0 = blockIdx.y * 32;
    int tx = threadIdx.x, ty = threadIdx.y;   // block (32, 8)
    #pragma unroll
    for (int i = 0; i < 4; i++)
        t[ty + i * 8][tx] = W[(size_t)(k0 + ty + i * 8) * HIDD + n0 + tx];
    __syncthreads();
    #pragma unroll
    for (int i = 0; i < 4; i++)
        Thi[(size_t)(n0 + ty + i * 8) * HIDD + k0 + tx] =
            __float2half_rn(t[tx][ty + i * 8]);
}

// ---------------- transpose V (fp16): g_vh[m][n] -> vt[(b*2048+n)][s] ---------
__global__ void vtsplit_kernel() {
    __shared__ __half t[32][34];
    int n0 = blockIdx.x * 32, m0 = blockIdx.y * 32;
    int tx = threadIdx.x, ty = threadIdx.y;   // block (32, 8)
    #pragma unroll
    for (int i = 0; i < 4; i++)
        t[ty + i * 8][tx] = g_vh[(size_t)(m0 + ty + i * 8) * HIDD + n0 + tx];
    __syncthreads();
    int b = m0 >> 11;
    int s0 = m0 & 2047;
    #pragma unroll
    for (int i = 0; i < 4; i++) {
        size_t o = ((size_t)b * 2048 + n0 + ty + i * 8) * 2048 + s0 + tx;
        g_vthi[o] = t[tx][ty + i * 8];
    }
}

// ---------------- HMMA fp16 GEMM core (128x256 CTA tile, 256 thr) ------------
// C = A @ B^T;  A [M][K] fp16, B [N][K] K-major fp16.  Single product, fp32 accum.
// 8 warps: warp_m = wid&1 (2), warp_n = wid>>1 (4); warp tile 64x64.
#define GK 2048
#define GN 2048
#define NIT 32
#define GTB_A 16384                       // 128 rows x 128 B
#define GTB_B 32768                       // 256 rows x 128 B
#define GSTAGE (GTB_A + GTB_B)            // 49152
#define GSMEM_TOTAL (3 * GSTAGE)          // 147456

__device__ __forceinline__
void gemm_body(const __half* __restrict__ Ah,
               const __half* __restrict__ Bh,
               float* __restrict__ C,
               __half* __restrict__ Chi,
               char* smem) {
    uint32_t sb = smem_u32(smem);
    int tid = threadIdx.x, l = tid & 31, wid = tid >> 5;
    int warp_m = wid & 1, warp_n = wid >> 1;
    int bm = blockIdx.y * 128, bn = blockIdx.x * 256;

    const char* srcA = (const char*)(Ah + (size_t)bm * GK);
    const char* srcB = (const char*)(Bh + (size_t)bn * GK);

    float c[4][8][4];
    #pragma unroll
    for (int i = 0; i < 4; i++)
        #pragma unroll
        for (int j = 0; j < 8; j++)
            #pragma unroll
            for (int k = 0; k < 4; k++) c[i][j][k] = 0.0f;

    auto stage_load = [&](int ci, int st) {
        int koff = ci * 128;
        uint32_t dstA = sb + st * GSTAGE;
        #pragma unroll
        for (int j = 0; j < 4; j++) {              // A: 4 vec
            int vec = tid + j * 256;
            int row = vec >> 3, col = (vec & 7) * 16;
            cp_async16(dstA + SW128(row * 128 + col),
                       srcA + (size_t)row * (GK * 2) + koff + col);
        }
        uint32_t dstB = dstA + GTB_A;
        #pragma unroll
        for (int j = 0; j < 8; j++) {              // B: 8 vec
            int vec = tid + j * 256;
            int row = vec >> 3, col = (vec & 7) * 16;
            cp_async16(dstB + SW128(row * 128 + col),
                       srcB + (size_t)row * (GK * 2) + koff + col);
        }
    };

    int rrA = (l & 7) + ((l >> 3) & 1) * 8;
    int kbA = ((l >> 4) & 1) * 16;
    int rrB = (l & 7) + ((l >> 4) & 1) * 8;
    int kbB = ((l >> 3) & 1) * 16;

    stage_load(0, 0);
    CP_COMMIT();
    stage_load(1, 1);
    CP_COMMIT();

    for (int i = 0; i < NIT; i++) {
        __syncthreads();   // protect slot (i+2)%3 (consumed at iter i-1)
        if (i + 2 < NIT) {
            stage_load(i + 2, (i + 2) % 3);
            CP_COMMIT();
            CP_WAIT(2);
        } else if (i + 1 < NIT) {
            CP_WAIT(1);
        } else {
            CP_WAIT(0);
        }
        __syncthreads();

        uint32_t bA = sb + (i % 3) * GSTAGE;
        uint32_t bB = bA + GTB_A;

        #pragma unroll
        for (int ks = 0; ks < 4; ks++) {
            int kk = ks * 32;
            uint32_t bf[8][2];
            #pragma unroll
            for (int np = 0; np < 4; np++) {
                int rb = (warp_n * 64 + np * 16 + rrB) * 128;
                uint32_t off = rb + ((kk + kbB) ^ ((rb >> 3) & 0x70));
                uint32_t t[4];
                ldsm4(t, bB + off);
                bf[np * 2][0] = t[0]; bf[np * 2][1] = t[1];
                bf[np * 2 + 1][0] = t[2]; bf[np * 2 + 1][1] = t[3];
            }
            #pragma unroll
            for (int mt = 0; mt < 4; mt++) {
                int rb = (warp_m * 64 + mt * 16 + rrA) * 128;
                uint32_t off = rb + ((kk + kbA) ^ ((rb >> 3) & 0x70));
                uint32_t af[4];
                ldsm4(af, bA + off);
                #pragma unroll
                for (int nt = 0; nt < 8; nt++)
                    mma16816(c[mt][nt], af, bf[nt]);
            }
        }
    }

    // epilogue
    #pragma unroll
    for (int mt = 0; mt < 4; mt++) {
        #pragma unroll
        for (int nt = 0; nt < 8; nt++) {
            int m0 = bm + warp_m * 64 + mt * 16 + (l >> 2);
            int cn = bn + warp_n * 64 + nt * 8 + (l & 3) * 2;
            size_t i0 = (size_t)m0 * GN + cn, i1 = (size_t)(m0 + 8) * GN + cn;
            float v0 = c[mt][nt][0], v1 = c[mt][nt][1];
            float v2 = c[mt][nt][2], v3 = c[mt][nt][3];
            if (Chi) {
                *(uint32_t*)&Chi[i0] = pack_h2(v0, v1);
                *(uint32_t*)&Chi[i1] = pack_h2(v2, v3);
            } else {
                *(float2*)&C[i0] = make_float2(v0, v1);
                *(float2*)&C[i1] = make_float2(v2, v3);
            }
        }
    }
}

// batched QKV projection: z=0 -> Q, z=1 -> K, z=2 -> V (all fp16 hi)
__global__ __launch_bounds__(256, 1)
void gemm_qkv() {
    extern __shared__ char smem[];
    int z = blockIdx.z;
    const __half* B = g_wthi[z];
    __half* Chi = (z == 0) ? g_qhi : (z == 1) ? g_khi : g_vh;
    gemm_body(g_xh, B, nullptr, Chi, smem);
}

// output projection: fp32 out
__global__ __launch_bounds__(256, 1)
void gemm_out(float* __restrict__ C) {
    extern __shared__ char smem[];
    gemm_body(g_chi, g_wthi[3], C, nullptr, smem);
}

// ---------------- HMMA fp16 flash attention (single product) ----------------
// grid (qb=32, h=16, b=2), 128 threads (4 warps). Warp w owns q rows [w*16, w*16+16).
// S = Q·K ; O += P·V (all fp16 hi, fp32 accum)
#define A_SQ       0                       // Q: c0, c1 (2 x 8KB)
#define A_KV(st)   (16384 + (st) * 32768)  // K c0 (8KB), K c1 (8KB), V (16KB)
#define A_P        81920                   // P 8KB
#define A_MASK(st) (90112 + (st) * 4096)
#define A_LIST     98304                   // int count + int[32]
#define ATTN2_SMEM 98560

__global__ __launch_bounds__(128, 1)
void attn_mma() {
    extern __shared__ char sm[];
    uint32_t sb = smem_u32(sm);
    int tid = threadIdx.x, l = tid & 31, w = tid >> 5;
    int qb = blockIdx.x, h = blockIdx.y, b = blockIdx.z;

    int rrA = (l & 7) + ((l >> 3) & 1) * 8;
    int kbA = ((l >> 4) & 1) * 16;
    int rrB = (l & 7) + ((l >> 4) & 1) * 8;
    int kbB = ((l >> 3) & 1) * 16;

    const size_t qrow_base = ((size_t)b * Ss + qb * 64) * HIDD;   // elements
    const size_t colb_base = (size_t)h * 256;                     // bytes within row

    // ---- load Q tiles (c0, c1) ----
    {
        #pragma unroll
        for (int t = 0; t < 2; t++) {
            const char* base = (const char*)g_qhi + qrow_base * 2
                               + colb_base + t * 128;
            uint32_t dst = sb + A_SQ + t * 8192;
            #pragma unroll
            for (int j = 0; j < 4; j++) {
                int vec = tid + j * 128;
                int row = vec >> 3, cbt = (vec & 7) * 16;
                cp_async16(dst + SW128(row * 128 + cbt),
                           base + (size_t)row * 4096 + cbt);
            }
        }
        CP_COMMIT();
    }

    // ---- build visible-kb list ----
    int* sList = (int*)(sm + A_LIST);
    if (tid == 0) {
        int c = 0;
        for (int kb = 0; kb < NBLK; kb++)
            if (g_bany[qb * NBLK + kb]) sList[1 + c++] = kb;
        sList[0] = c;
    }
    __syncthreads();
    int cnt = sList[0];

    // ---- KV + mask prefetch ----
    auto prefetch = [&](int kb, int st) {
        uint32_t kvb = sb + A_KV(st);
        size_t krow = ((size_t)b * Ss + kb * 64) * HIDD * 2;   // bytes
        #pragma unroll
        for (int t = 0; t < 2; t++) {     // K chunk 0, chunk 1
            const char* base = (const char*)g_khi + krow + colb_base + t * 128;
            uint32_t dst = kvb + t * 8192;
            #pragma unroll
            for (int j = 0; j < 4; j++) {
                int vec = tid + j * 128;
                int row = vec >> 3, cbt = (vec & 7) * 16;
                cp_async16(dst + SW128(row * 128 + cbt),
                           base + (size_t)row * 4096 + cbt);
            }
        }
        size_t vrow = ((size_t)b * 2048 + h * 128) * 2048 * 2;  // bytes; +dh*4096
        {
            const char* base = (const char*)g_vthi + vrow + kb * 128;
            uint32_t dst = kvb + 16384;
            #pragma unroll
            for (int j = 0; j < 8; j++) {
                int vec = tid + j * 128;
                int row = vec >> 3, cbt = (vec & 7) * 16;
                cp_async16(dst + SW128(row * 128 + cbt),
                           base + (size_t)row * 4096 + cbt);
            }
        }
        {
            const char* base = (const char*)g_mask + (size_t)(qb * 64) * Ss + kb * 64;
            uint32_t dst = sb + A_MASK(st);
            #pragma unroll
            for (int j = 0; j < 2; j++) {
                int vec = tid + j * 128;
                int row = vec >> 2, cbt = (vec & 3) * 16;
                cp_async16(dst + row * 64 + cbt, base + (size_t)row * Ss + cbt);
            }
        }
    };

    prefetch(sList[1], 0);
    CP_COMMIT();

    // ---- state ----
    float o[16][4];
    #pragma unroll
    for (int i = 0; i < 16; i++)
        #pragma unroll
        for (int j = 0; j < 4; j++) o[i][j] = 0.0f;
    float m0r = -1e30f, m1r = -1e30f, l0r = 0.0f, l1r = 0.0f;

    int qrow0 = w * 16;
    int r0l = qrow0 + (l >> 2);

    for (int i = 0; i < cnt; i++) {
        int st = i & 1;
        __syncthreads();   // all warps done with stage st^1 (iter i-1) before refill
        if (i + 1 < cnt) {
            prefetch(sList[1 + i + 1], st ^ 1);
            CP_COMMIT();
            CP_WAIT(1);
        } else {
            CP_WAIT(0);
        }
        __syncthreads();

        uint32_t kvb = sb + A_KV(st);

        // ---- S = Q @ K^T (fp16) ----
        float s[8][4];
        #pragma unroll
        for (int nt = 0; nt < 8; nt++)
            #pragma unroll
            for (int j = 0; j < 4; j++) s[nt][j] = 0.0f;

        #pragma unroll
        for (int chunk = 0; chunk < 2; chunk++) {
            uint32_t bQh = sb + A_SQ + chunk * 8192;
            uint32_t bKh = kvb + chunk * 8192;
            #pragma unroll
            for (int ks = 0; ks < 4; ks++) {
                int kk = ks * 32;
                int rowA = qrow0 + rrA;
                uint32_t offA = rowA * 128 + ((kk + kbA) ^ ((rowA & 7) << 4));
                uint32_t ah[4];
                ldsm4(ah, bQh + offA);
                #pragma unroll
                for (int np = 0; np < 4; np++) {
                    int rowB = np * 16 + rrB;
                    uint32_t offB = rowB * 128 + ((kk + kbB) ^ ((rowB & 7) << 4));
                    uint32_t th[4];
                    ldsm4(th, bKh + offB);
                    uint32_t bh0[2] = {th[0], th[1]}, bh1[2] = {th[2], th[3]};
                    mma16816(s[np * 2], ah, bh0);
                    mma16816(s[np * 2 + 1], ah, bh1);
                }
            }
        }

        // ---- mask + scale + online softmax ----
        const unsigned char* mk = (const unsigned char*)(sm + A_MASK(st))
                                  + r0l * 64 + (l & 3) * 2;
        float mx0 = -1e30f, mx1 = -1e30f;
        #pragma unroll
        for (int nt = 0; nt < 8; nt++) {
            int cb = nt * 8;
            float t00 = mk[cb]       ? s[nt][0] * SCALE_F : -1e30f;
            float t01 = mk[cb + 1]   ? s[nt][1] * SCALE_F : -1e30f;
            float t10 = mk[cb + 512] ? s[nt][2] * SCALE_F : -1e30f;
            float t11 = mk[cb + 513] ? s[nt][3] * SCALE_F : -1e30f;
            s[nt][0] = t00; s[nt][1] = t01; s[nt][2] = t10; s[nt][3] = t11;
            mx0 = fmaxf(mx0, fmaxf(t00, t01));
            mx1 = fmaxf(mx1, fmaxf(t10, t11));
        }
        mx0 = fmaxf(mx0, __shfl_xor_sync(0xffffffffu, mx0, 1));
        mx0 = fmaxf(mx0, __shfl_xor_sync(0xffffffffu, mx0, 2));
        mx1 = fmaxf(mx1, __shfl_xor_sync(0xffffffffu, mx1, 1));
        mx1 = fmaxf(mx1, __shfl_xor_sync(0xffffffffu, mx1, 2));
        float mn0 = fmaxf(m0r, mx0), mn1 = fmaxf(m1r, mx1);
        float sc0 = __expf(m0r - mn0), sc1 = __expf(m1r - mn1);
        m0r = mn0; m1r = mn1;

        // ---- P = exp(S - m), write fp16 to smem (full-column swizzle) ----
        float sum0 = 0.0f, sum1 = 0.0f;
        int colb = (l & 3) * 4;
        int sw0 = (r0l & 7) << 4;                 // same for r0l and r0l+8
        uint32_t rb0 = r0l * 128;
        uint32_t rb1 = (r0l + 8) * 128;
        #pragma unroll
        for (int nt = 0; nt < 8; nt++) {
            float p00 = __expf(s[nt][0] - mn0);
            float p01 = __expf(s[nt][1] - mn0);
            float p10 = __expf(s[nt][2] - mn1);
            float p11 = __expf(s[nt][3] - mn1);
            sum0 += p00 + p01;
            sum1 += p10 + p11;
            uint32_t colsw = (uint32_t)((nt * 16 + colb) ^ sw0);
            *(uint32_t*)(sm + A_P + rb0 + colsw) = pack_h2(p00, p01);
            *(uint32_t*)(sm + A_P + rb1 + colsw) = pack_h2(p10, p11);
        }
        sum0 += __shfl_xor_sync(0xffffffffu, sum0, 1);
        sum0 += __shfl_xor_sync(0xffffffffu, sum0, 2);
        sum1 += __shfl_xor_sync(0xffffffffu, sum1, 1);
        sum1 += __shfl_xor_sync(0xffffffffu, sum1, 2);
        l0r = l0r * sc0 + sum0;
        l1r = l1r * sc1 + sum1;

        // ---- O rescale + O += P @ Vt (fp16) ----
        #pragma unroll
        for (int nt = 0; nt < 16; nt++) {
            o[nt][0] *= sc0; o[nt][1] *= sc0;
            o[nt][2] *= sc1; o[nt][3] *= sc1;
        }
        __syncwarp();

        uint32_t bPh = sb + A_P;
        uint32_t bVh = kvb + 16384;
        #pragma unroll
        for (int ks = 0; ks < 4; ks++) {
            int kk = ks * 32;
            int rowA = qrow0 + rrA;
            uint32_t offA = rowA * 128 + ((kk + kbA) ^ ((rowA & 7) << 4));
            uint32_t ph[4];
            ldsm4(ph, bPh + offA);
            #pragma unroll
            for (int np = 0; np < 8; np++) {
                int rowB = np * 16 + rrB;
                uint32_t offB = rowB * 128 + ((kk + kbB) ^ ((rowB & 7) << 4));
                uint32_t th[4];
                ldsm4(th, bVh + offB);
                uint32_t vh0[2] = {th[0], th[1]}, vh1[2] = {th[2], th[3]};
                mma16816(o[np * 2], ph, vh0);
                mma16816(o[np * 2 + 1], ph, vh1);
            }
        }
    }

    // ---- epilogue: O /= l, write ctx fp16 ----
    float inv0 = 1.0f / l0r, inv1 = 1.0f / l1r;
    size_t row0 = (size_t)b * Ss + qb * 64 + qrow0 + (l >> 2);
    size_t row1 = row0 + 8;
    int cn0 = h * 128 + (l & 3) * 2;
    #pragma unroll
    for (int nt = 0; nt < 16; nt++) {
        int cn = cn0 + nt * 8;
        float v0 = o[nt][0] * inv0, v1 = o[nt][1] * inv0;
        float v2 = o[nt][2] * inv1, v3 = o[nt][3] * inv1;
        size_t i0 = row0 * HIDD + cn, i1 = row1 * HIDD + cn;
        *(uint32_t*)&g_chi[i0] = pack_h2(v0, v1);
        *(uint32_t*)&g_chi[i1] = pack_h2(v2, v3);
    }
}

// ---------------- launch ----------------
extern "C" void kernel_launch(void* const* d_in, const int* in_sizes, int n_in,
                              void* d_out, int out_size) {
    const float* X  = (const float*)d_in[0];
    const float* Wq = (const float*)d_in[1];
    const float* Wk = (const float*)d_in[2];
    const float* Wv = (const float*)d_in[3];
    const float* Wo = (const float*)d_in[4];
    const void*  Mraw = d_in[5];
    float* out = (float*)d_out;

    cudaFuncSetAttribute(gemm_qkv,
                         cudaFuncAttributeMaxDynamicSharedMemorySize, GSMEM_TOTAL);
    cudaFuncSetAttribute(gemm_out,
                         cudaFuncAttributeMaxDynamicSharedMemorySize, GSMEM_TOTAL);
    cudaFuncSetAttribute(attn_mma,
                         cudaFuncAttributeMaxDynamicSharedMemorySize, ATTN2_SMEM);

    __half* pxh;
    cudaGetSymbolAddress((void**)&pxh, g_xh);

    // 1: mask detect, 2: expand, 3: bany
    detect_kernel<<<1, 1>>>((const unsigned char*)Mraw);
    expand_kernel<<<(Ss * Ss) / 256, 256>>>(Mraw);
    bany_kernel<<<dim3(NBLK, NBLK), 64>>>();

    // 4: X convert, 5: W transposes (batched)
    cvt_kernel<<<(MROWS * HIDD / 4 + 255) / 256, 256>>>(X, pxh, MROWS * HIDD / 4);
    tsplit4_kernel<<<dim3(HIDD / 32, HIDD / 32, 4), dim3(32, 8)>>>(Wq, Wk, Wv, Wo);

    // 6: batched Q/K/V projections (fp16 HMMA, 128x256 tiles)
    gemm_qkv<<<dim3(GN / 256, MROWS / 128, 3), 256, GSMEM_TOTAL>>>();

    // 7: V transpose (fp16)
    vtsplit_kernel<<<dim3(HIDD / 32, MROWS / 32), dim3(32, 8)>>>();

    // 8: attention (fp16 single product)
    attn_mma<<<dim3(NBLK, Hh, Bb), 128, ATTN2_SMEM>>>();

    // 9: output projection
    gemm_out<<<dim3(GN / 256, MROWS / 128), 256, GSMEM_TOTAL>>>(out);
}

// round 12
// speedup vs baseline: 1.6790x; 1.0335x over previous
#include <cuda_runtime.h>
#include <cuda_fp16.h>
#include <stdint.h>
#include <math.h>

// Problem constants
#define Bb    2
#define Ss    2048
#define HIDD  2048
#define Hh    16
#define DHh   128
#define NBLK  32        // 2048 / 64
#define MROWS 4096      // B*S
#define SCALE_F 0.08838834764831845f   // 1/sqrt(128)

// ---------------- scratch (static device allocations) ----------------
__device__ __half g_xh [(size_t)MROWS * HIDD];    // X fp16
__device__ __half g_qhi[(size_t)MROWS * HIDD];
__device__ __half g_khi[(size_t)MROWS * HIDD];
__device__ __half g_vh [(size_t)MROWS * HIDD];    // V projection, [m][n] fp16
__device__ __half g_vthi[(size_t)MROWS * HIDD];   // [b][h*dh][s]
__device__ __half g_chi[(size_t)MROWS * HIDD];    // ctx fp16
__device__ __half g_wthi[4][(size_t)HIDD * HIDD]; // W^T [N][K] fp16
__device__ unsigned char g_mask[(size_t)Ss * Ss];
__device__ unsigned char g_bany[NBLK * NBLK];

// ======================= PTX helpers (family-portable) =======================
__device__ __forceinline__ uint32_t smem_u32(const void* p) {
    uint32_t a;
    asm("{ .reg .u64 t; cvta.to.shared.u64 t, %1; cvt.u32.u64 %0, t; }"
        : "=r"(a) : "l"(p));
    return a;
}
__device__ __forceinline__ void cp_async16(uint32_t dst, const void* src) {
    asm volatile("cp.async.cg.shared.global [%0], [%1], 16;"
                 :: "r"(dst), "l"(src) : "memory");
}
#define CP_COMMIT() asm volatile("cp.async.commit_group;" ::: "memory")
#define CP_WAIT(n)  asm volatile("cp.async.wait_group %0;" :: "n"(n) : "memory")

__device__ __forceinline__ void ldsm4(uint32_t* r, uint32_t addr) {
    asm volatile("ldmatrix.sync.aligned.m8n8.x4.shared.b16 {%0,%1,%2,%3}, [%4];"
                 : "=r"(r[0]), "=r"(r[1]), "=r"(r[2]), "=r"(r[3]) : "r"(addr));
}
__device__ __forceinline__ void mma16816(float* c, const uint32_t* a, const uint32_t* b) {
    asm volatile(
        "mma.sync.aligned.m16n8k16.row.col.f32.f16.f16.f32 "
        "{%0,%1,%2,%3}, {%4,%5,%6,%7}, {%8,%9}, {%0,%1,%2,%3};"
        : "+f"(c[0]), "+f"(c[1]), "+f"(c[2]), "+f"(c[3])
        : "r"(a[0]), "r"(a[1]), "r"(a[2]), "r"(a[3]), "r"(b[0]), "r"(b[1]));
}

#define SW128(o) ((o) ^ (((o) >> 3) & 0x70))

__device__ __forceinline__ uint32_t pack_h2(float a, float b) {
    __half2 t = __floats2half2_rn(a, b);
    return *(uint32_t*)&t;
}

// ---------------- fused mask canonicalization + block-any ----------------
// grid (kb=32, qb=32), 256 threads; CTA handles one 64x64 mask block.
// Inline dtype detect: raw[0],raw[1] are both True (global row 0).
__global__ void mask_kernel(const unsigned char* __restrict__ raw) {
    int qb = blockIdx.y, kb = blockIdx.x;
    int tid = threadIdx.x;
    int r = tid >> 2, c0 = (tid & 3) * 16;
    size_t e0 = (size_t)(qb * 64 + r) * Ss + kb * 64 + c0;

    int f;
    if (raw[0] == 1 && raw[1] == 1) f = 0;       // u8 / bool
    else if (raw[0] == 1)           f = 1;       // int32
    else                            f = 2;       // float32

    union { unsigned char v[16]; int4 vec; } u;
    if (f == 0) {
        int4 d = *(const int4*)(raw + e0);
        const unsigned char* p = (const unsigned char*)&d;
        #pragma unroll
        for (int c = 0; c < 16; c++) u.v[c] = p[c] != 0;
    } else if (f == 1) {
        const int* p32 = (const int*)raw + e0;
        #pragma unroll
        for (int c = 0; c < 16; c++) u.v[c] = p32[c] != 0;
    } else {
        const float* pf = (const float*)raw + e0;
        #pragma unroll
        for (int c = 0; c < 16; c++) u.v[c] = pf[c] != 0.0f;
    }
    int any = 0;
    #pragma unroll
    for (int c = 0; c < 16; c++) any |= u.v[c];
    *(int4*)(g_mask + e0) = u.vec;
    int res = __syncthreads_or(any);
    if (tid == 0) g_bany[qb * NBLK + kb] = res ? 1 : 0;
}

// ---------------- fp32 -> fp16 convert ----------------
__global__ void cvt_kernel(const float* __restrict__ in,
                           __half* __restrict__ hi, int n4) {
    int i = blockIdx.x * blockDim.x + threadIdx.x;
    if (i >= n4) return;
    float4 v = ((const float4*)in)[i];
    ushort4 hv = make_ushort4(__half_as_ushort(__float2half_rn(v.x)),
                              __half_as_ushort(__float2half_rn(v.y)),
                              __half_as_ushort(__float2half_rn(v.z)),
                              __half_as_ushort(__float2half_rn(v.w)));
    ((ushort4*)hi)[i] = hv;
}

// ---------------- batched transpose: W[K][N] -> T[N][K] fp16, z = which W ----
__global__ void tsplit4_kernel(const float* __restrict__ W0,
                               const float* __restrict__ W1,
                               const float* __restrict__ W2,
                               const float* __restrict__ W3) {
    __shared__ float t[32][33];
    int z = blockIdx.z;
    const float* W = (z == 0) ? W0 : (z == 1) ? W1 : (z == 2) ? W2 : W3;
    __half* Thi = g_wthi[z];
    int n0 = blockIdx.x * 32, k0 = blockIdx.y * 32;
    int tx = threadIdx.x, ty = threadIdx.y;   // block (32, 8)
    #pragma unroll
    for (int i = 0; i < 4; i++)
        t[ty + i * 8][tx] = W[(size_t)(k0 + ty + i * 8) * HIDD + n0 + tx];
    __syncthreads();
    #pragma unroll
    for (int i = 0; i < 4; i++)
        Thi[(size_t)(n0 + ty + i * 8) * HIDD + k0 + tx] =
            __float2half_rn(t[tx][ty + i * 8]);
}

// ---------------- transpose V (fp16): g_vh[m][n] -> vt[(b*2048+n)][s] ---------
// 64x64 tile, half2 loads/stores (128B per warp both directions).
__global__ void vtsplit_kernel() {
    __shared__ __half t[64][66];
    int n0 = blockIdx.x * 64, m0 = blockIdx.y * 64;
    int tx = threadIdx.x, ty = threadIdx.y;   // block (32, 8)
    #pragma unroll
    for (int i = 0; i < 8; i++) {
        int r = ty + i * 8;
        __half2 v = *(const __half2*)&g_vh[(size_t)(m0 + r) * HIDD + n0 + 2 * tx];
        t[r][2 * tx]     = __low2half(v);
        t[r][2 * tx + 1] = __high2half(v);
    }
    __syncthreads();
    int b = m0 >> 11;
    int s0 = m0 & 2047;
    #pragma unroll
    for (int i = 0; i < 8; i++) {
        int n = ty + i * 8;
        __half2 v = __halves2half2(t[2 * tx][n], t[2 * tx + 1][n]);
        *(__half2*)&g_vthi[((size_t)b * 2048 + n0 + n) * 2048 + s0 + 2 * tx] = v;
    }
}

// ---------------- HMMA fp16 GEMM core (128x256 CTA tile, 256 thr) ------------
// C = A @ B^T;  A [M][K] fp16, B [N][K] K-major fp16.  Single product, fp32 accum.
// 8 warps: warp_m = wid&1 (2), warp_n = wid>>1 (4); warp tile 64x64.
// 3-stage cp.async ring, ONE __syncthreads per iteration:
//   wait(g_i) -> sync -> load(i+2) -> compute(i)
// (any warp past sync_i implies all warps finished compute(i-1), the only
//  reader of slot (i+2)%3, so the overwrite is race-free)
#define GK 2048
#define GN 2048
#define NIT 32
#define GTB_A 16384                       // 128 rows x 128 B
#define GTB_B 32768                       // 256 rows x 128 B
#define GSTAGE (GTB_A + GTB_B)            // 49152
#define GSMEM_TOTAL (3 * GSTAGE)          // 147456

__device__ __forceinline__
void gemm_body(const __half* __restrict__ Ah,
               const __half* __restrict__ Bh,
               float* __restrict__ C,
               __half* __restrict__ Chi,
               char* smem) {
    uint32_t sb = smem_u32(smem);
    int tid = threadIdx.x, l = tid & 31, wid = tid >> 5;
    int warp_m = wid & 1, warp_n = wid >> 1;
    int bm = blockIdx.y * 128, bn = blockIdx.x * 256;

    const char* srcA = (const char*)(Ah + (size_t)bm * GK);
    const char* srcB = (const char*)(Bh + (size_t)bn * GK);

    float c[4][8][4];
    #pragma unroll
    for (int i = 0; i < 4; i++)
        #pragma unroll
        for (int j = 0; j < 8; j++)
            #pragma unroll
            for (int k = 0; k < 4; k++) c[i][j][k] = 0.0f;

    auto stage_load = [&](int ci, int st) {
        int koff = ci * 128;
        uint32_t dstA = sb + st * GSTAGE;
        #pragma unroll
        for (int j = 0; j < 4; j++) {              // A: 4 vec
            int vec = tid + j * 256;
            int row = vec >> 3, col = (vec & 7) * 16;
            cp_async16(dstA + SW128(row * 128 + col),
                       srcA + (size_t)row * (GK * 2) + koff + col);
        }
        uint32_t dstB = dstA + GTB_A;
        #pragma unroll
        for (int j = 0; j < 8; j++) {              // B: 8 vec
            int vec = tid + j * 256;
            int row = vec >> 3, col = (vec & 7) * 16;
            cp_async16(dstB + SW128(row * 128 + col),
                       srcB + (size_t)row * (GK * 2) + koff + col);
        }
    };

    int rrA = (l & 7) + ((l >> 3) & 1) * 8;
    int kbA = ((l >> 4) & 1) * 16;
    int rrB = (l & 7) + ((l >> 4) & 1) * 8;
    int kbB = ((l >> 3) & 1) * 16;

    stage_load(0, 0);
    CP_COMMIT();
    stage_load(1, 1);
    CP_COMMIT();

    for (int i = 0; i < NIT; i++) {
        if (i + 1 < NIT) { CP_WAIT(1); } else { CP_WAIT(0); }
        __syncthreads();
        if (i + 2 < NIT) {
            stage_load(i + 2, (i + 2) % 3);
            CP_COMMIT();
        }

        uint32_t bA = sb + (i % 3) * GSTAGE;
        uint32_t bB = bA + GTB_A;

        #pragma unroll
        for (int ks = 0; ks < 4; ks++) {
            int kk = ks * 32;
            uint32_t bf[8][2];
            #pragma unroll
            for (int np = 0; np < 4; np++) {
                int rb = (warp_n * 64 + np * 16 + rrB) * 128;
                uint32_t off = rb + ((kk + kbB) ^ ((rb >> 3) & 0x70));
                uint32_t t[4];
                ldsm4(t, bB + off);
                bf[np * 2][0] = t[0]; bf[np * 2][1] = t[1];
                bf[np * 2 + 1][0] = t[2]; bf[np * 2 + 1][1] = t[3];
            }
            #pragma unroll
            for (int mt = 0; mt < 4; mt++) {
                int rb = (warp_m * 64 + mt * 16 + rrA) * 128;
                uint32_t off = rb + ((kk + kbA) ^ ((rb >> 3) & 0x70));
                uint32_t af[4];
                ldsm4(af, bA + off);
                #pragma unroll
                for (int nt = 0; nt < 8; nt++)
                    mma16816(c[mt][nt], af, bf[nt]);
            }
        }
    }

    // epilogue
    #pragma unroll
    for (int mt = 0; mt < 4; mt++) {
        #pragma unroll
        for (int nt = 0; nt < 8; nt++) {
            int m0 = bm + warp_m * 64 + mt * 16 + (l >> 2);
            int cn = bn + warp_n * 64 + nt * 8 + (l & 3) * 2;
            size_t i0 = (size_t)m0 * GN + cn, i1 = (size_t)(m0 + 8) * GN + cn;
            float v0 = c[mt][nt][0], v1 = c[mt][nt][1];
            float v2 = c[mt][nt][2], v3 = c[mt][nt][3];
            if (Chi) {
                *(uint32_t*)&Chi[i0] = pack_h2(v0, v1);
                *(uint32_t*)&Chi[i1] = pack_h2(v2, v3);
            } else {
                *(float2*)&C[i0] = make_float2(v0, v1);
                *(float2*)&C[i1] = make_float2(v2, v3);
            }
        }
    }
}

// batched QKV projection: z=0 -> Q, z=1 -> K, z=2 -> V (all fp16 hi)
__global__ __launch_bounds__(256, 1)
void gemm_qkv() {
    extern __shared__ char smem[];
    int z = blockIdx.z;
    const __half* B = g_wthi[z];
    __half* Chi = (z == 0) ? g_qhi : (z == 1) ? g_khi : g_vh;
    gemm_body(g_xh, B, nullptr, Chi, smem);
}

// output projection: fp32 out
__global__ __launch_bounds__(256, 1)
void gemm_out(float* __restrict__ C) {
    extern __shared__ char smem[];
    gemm_body(g_chi, g_wthi[3], C, nullptr, smem);
}

// ---------------- HMMA fp16 flash attention (single product) ----------------
// grid (qb=32, h=16, b=2), 128 threads (4 warps). Warp w owns q rows [w*16, w*16+16).
// S = Q·K ; O += P·V (all fp16, fp32 accum)
#define A_SQ       0                       // Q: c0, c1 (2 x 8KB)
#define A_KV(st)   (16384 + (st) * 32768)  // K c0 (8KB), K c1 (8KB), V (16KB)
#define A_P        81920                   // P 8KB
#define A_MASK(st) (90112 + (st) * 4096)
#define A_LIST     98304                   // int count + int[32]
#define ATTN2_SMEM 98560

__global__ __launch_bounds__(128, 1)
void attn_mma() {
    extern __shared__ char sm[];
    uint32_t sb = smem_u32(sm);
    int tid = threadIdx.x, l = tid & 31, w = tid >> 5;
    int qb = blockIdx.x, h = blockIdx.y, b = blockIdx.z;

    int rrA = (l & 7) + ((l >> 3) & 1) * 8;
    int kbA = ((l >> 4) & 1) * 16;
    int rrB = (l & 7) + ((l >> 4) & 1) * 8;
    int kbB = ((l >> 3) & 1) * 16;

    const size_t qrow_base = ((size_t)b * Ss + qb * 64) * HIDD;   // elements
    const size_t colb_base = (size_t)h * 256;                     // bytes within row

    // ---- load Q tiles (c0, c1) ----
    {
        #pragma unroll
        for (int t = 0; t < 2; t++) {
            const char* base = (const char*)g_qhi + qrow_base * 2
                               + colb_base + t * 128;
            uint32_t dst = sb + A_SQ + t * 8192;
            #pragma unroll
            for (int j = 0; j < 4; j++) {
                int vec = tid + j * 128;
                int row = vec >> 3, cbt = (vec & 7) * 16;
                cp_async16(dst + SW128(row * 128 + cbt),
                           base + (size_t)row * 4096 + cbt);
            }
        }
        CP_COMMIT();
    }

    // ---- build visible-kb list ----
    int* sList = (int*)(sm + A_LIST);
    if (tid == 0) {
        int c = 0;
        for (int kb = 0; kb < NBLK; kb++)
            if (g_bany[qb * NBLK + kb]) sList[1 + c++] = kb;
        sList[0] = c;
    }
    __syncthreads();
    int cnt = sList[0];

    // ---- KV + mask prefetch ----
    auto prefetch = [&](int kb, int st) {
        uint32_t kvb = sb + A_KV(st);
        size_t krow = ((size_t)b * Ss + kb * 64) * HIDD * 2;   // bytes
        #pragma unroll
        for (int t = 0; t < 2; t++) {     // K chunk 0, chunk 1
            const char* base = (const char*)g_khi + krow + colb_base + t * 128;
            uint32_t dst = kvb + t * 8192;
            #pragma unroll
            for (int j = 0; j < 4; j++) {
                int vec = tid + j * 128;
                int row = vec >> 3, cbt = (vec & 7) * 16;
                cp_async16(dst + SW128(row * 128 + cbt),
                           base + (size_t)row * 4096 + cbt);
            }
        }
        size_t vrow = ((size_t)b * 2048 + h * 128) * 2048 * 2;  // bytes; +dh*4096
        {
            const char* base = (const char*)g_vthi + vrow + kb * 128;
            uint32_t dst = kvb + 16384;
            #pragma unroll
            for (int j = 0; j < 8; j++) {
                int vec = tid + j * 128;
                int row = vec >> 3, cbt = (vec & 7) * 16;
                cp_async16(dst + SW128(row * 128 + cbt),
                           base + (size_t)row * 4096 + cbt);
            }
        }
        {
            const char* base = (const char*)g_mask + (size_t)(qb * 64) * Ss + kb * 64;
            uint32_t dst = sb + A_MASK(st);
            #pragma unroll
            for (int j = 0; j < 2; j++) {
                int vec = tid + j * 128;
                int row = vec >> 2, cbt = (vec & 3) * 16;
                cp_async16(dst + row * 64 + cbt, base + (size_t)row * Ss + cbt);
            }
        }
    };

    prefetch(sList[1], 0);
    CP_COMMIT();

    // ---- state ----
    float o[16][4];
    #pragma unroll
    for (int i = 0; i < 16; i++)
        #pragma unroll
        for (int j = 0; j < 4; j++) o[i][j] = 0.0f;
    float m0r = -1e30f, m1r = -1e30f, l0r = 0.0f, l1r = 0.0f;

    int qrow0 = w * 16;
    int r0l = qrow0 + (l >> 2);

    for (int i = 0; i < cnt; i++) {
        int st = i & 1;
        __syncthreads();   // all warps done with stage st^1 (iter i-1) before refill
        if (i + 1 < cnt) {
            prefetch(sList[1 + i + 1], st ^ 1);
            CP_COMMIT();
            CP_WAIT(1);
        } else {
            CP_WAIT(0);
        }
        __syncthreads();

        uint32_t kvb = sb + A_KV(st);

        // ---- S = Q @ K^T (fp16) ----
        float s[8][4];
        #pragma unroll
        for (int nt = 0; nt < 8; nt++)
            #pragma unroll
            for (int j = 0; j < 4; j++) s[nt][j] = 0.0f;

        #pragma unroll
        for (int chunk = 0; chunk < 2; chunk++) {
            uint32_t bQh = sb + A_SQ + chunk * 8192;
            uint32_t bKh = kvb + chunk * 8192;
            #pragma unroll
            for (int ks = 0; ks < 4; ks++) {
                int kk = ks * 32;
                int rowA = qrow0 + rrA;
                uint32_t offA = rowA * 128 + ((kk + kbA) ^ ((rowA & 7) << 4));
                uint32_t ah[4];
                ldsm4(ah, bQh + offA);
                #pragma unroll
                for (int np = 0; np < 4; np++) {
                    int rowB = np * 16 + rrB;
                    uint32_t offB = rowB * 128 + ((kk + kbB) ^ ((rowB & 7) << 4));
                    uint32_t th[4];
                    ldsm4(th, bKh + offB);
                    uint32_t bh0[2] = {th[0], th[1]}, bh1[2] = {th[2], th[3]};
                    mma16816(s[np * 2], ah, bh0);
                    mma16816(s[np * 2 + 1], ah, bh1);
                }
            }
        }

        // ---- mask + scale + online softmax ----
        const unsigned char* mk = (const unsigned char*)(sm + A_MASK(st))
                                  + r0l * 64 + (l & 3) * 2;
        float mx0 = -1e30f, mx1 = -1e30f;
        #pragma unroll
        for (int nt = 0; nt < 8; nt++) {
            int cb = nt * 8;
            float t00 = mk[cb]       ? s[nt][0] * SCALE_F : -1e30f;
            float t01 = mk[cb + 1]   ? s[nt][1] * SCALE_F : -1e30f;
            float t10 = mk[cb + 512] ? s[nt][2] * SCALE_F : -1e30f;
            float t11 = mk[cb + 513] ? s[nt][3] * SCALE_F : -1e30f;
            s[nt][0] = t00; s[nt][1] = t01; s[nt][2] = t10; s[nt][3] = t11;
            mx0 = fmaxf(mx0, fmaxf(t00, t01));
            mx1 = fmaxf(mx1, fmaxf(t10, t11));
        }
        mx0 = fmaxf(mx0, __shfl_xor_sync(0xffffffffu, mx0, 1));
        mx0 = fmaxf(mx0, __shfl_xor_sync(0xffffffffu, mx0, 2));
        mx1 = fmaxf(mx1, __shfl_xor_sync(0xffffffffu, mx1, 1));
        mx1 = fmaxf(mx1, __shfl_xor_sync(0xffffffffu, mx1, 2));
        float mn0 = fmaxf(m0r, mx0), mn1 = fmaxf(m1r, mx1);
        float sc0 = __expf(m0r - mn0), sc1 = __expf(m1r - mn1);
        m0r = mn0; m1r = mn1;

        // ---- P = exp(S - m), write fp16 to smem (full-column swizzle) ----
        float sum0 = 0.0f, sum1 = 0.0f;
        int colb = (l & 3) * 4;
        int sw0 = (r0l & 7) << 4;                 // same for r0l and r0l+8
        uint32_t rb0 = r0l * 128;
        uint32_t rb1 = (r0l + 8) * 128;
        #pragma unroll
        for (int nt = 0; nt < 8; nt++) {
            float p00 = __expf(s[nt][0] - mn0);
            float p01 = __expf(s[nt][1] - mn0);
            float p10 = __expf(s[nt][2] - mn1);
            float p11 = __expf(s[nt][3] - mn1);
            sum0 += p00 + p01;
            sum1 += p10 + p11;
            uint32_t colsw = (uint32_t)((nt * 16 + colb) ^ sw0);
            *(uint32_t*)(sm + A_P + rb0 + colsw) = pack_h2(p00, p01);
            *(uint32_t*)(sm + A_P + rb1 + colsw) = pack_h2(p10, p11);
        }
        sum0 += __shfl_xor_sync(0xffffffffu, sum0, 1);
        sum0 += __shfl_xor_sync(0xffffffffu, sum0, 2);
        sum1 += __shfl_xor_sync(0xffffffffu, sum1, 1);
        sum1 += __shfl_xor_sync(0xffffffffu, sum1, 2);
        l0r = l0r * sc0 + sum0;
        l1r = l1r * sc1 + sum1;

        // ---- O rescale + O += P @ Vt (fp16) ----
        #pragma unroll
        for (int nt = 0; nt < 16; nt++) {
            o[nt][0] *= sc0; o[nt][1] *= sc0;
            o[nt][2] *= sc1; o[nt][3] *= sc1;
        }
        __syncwarp();

        uint32_t bPh = sb + A_P;
        uint32_t bVh = kvb + 16384;
        #pragma unroll
        for (int ks = 0; ks < 4; ks++) {
            int kk = ks * 32;
            int rowA = qrow0 + rrA;
            uint32_t offA = rowA * 128 + ((kk + kbA) ^ ((rowA & 7) << 4));
            uint32_t ph[4];
            ldsm4(ph, bPh + offA);
            #pragma unroll
            for (int np = 0; np < 8; np++) {
                int rowB = np * 16 + rrB;
                uint32_t offB = rowB * 128 + ((kk + kbB) ^ ((rowB & 7) << 4));
                uint32_t th[4];
                ldsm4(th, bVh + offB);
                uint32_t vh0[2] = {th[0], th[1]}, vh1[2] = {th[2], th[3]};
                mma16816(o[np * 2], ph, vh0);
                mma16816(o[np * 2 + 1], ph, vh1);
            }
        }
    }

    // ---- epilogue: O /= l, write ctx fp16 ----
    float inv0 = 1.0f / l0r, inv1 = 1.0f / l1r;
    size_t row0 = (size_t)b * Ss + qb * 64 + qrow0 + (l >> 2);
    size_t row1 = row0 + 8;
    int cn0 = h * 128 + (l & 3) * 2;
    #pragma unroll
    for (int nt = 0; nt < 16; nt++) {
        int cn = cn0 + nt * 8;
        float v0 = o[nt][0] * inv0, v1 = o[nt][1] * inv0;
        float v2 = o[nt][2] * inv1, v3 = o[nt][3] * inv1;
        size_t i0 = row0 * HIDD + cn, i1 = row1 * HIDD + cn;
        *(uint32_t*)&g_chi[i0] = pack_h2(v0, v1);
        *(uint32_t*)&g_chi[i1] = pack_h2(v2, v3);
    }
}

// ---------------- launch ----------------
extern "C" void kernel_launch(void* const* d_in, const int* in_sizes, int n_in,
                              void* d_out, int out_size) {
    const float* X  = (const float*)d_in[0];
    const float* Wq = (const float*)d_in[1];
    const float* Wk = (const float*)d_in[2];
    const float* Wv = (const float*)d_in[3];
    const float* Wo = (const float*)d_in[4];
    const void*  Mraw = d_in[5];
    float* out = (float*)d_out;

    cudaFuncSetAttribute(gemm_qkv,
                         cudaFuncAttributeMaxDynamicSharedMemorySize, GSMEM_TOTAL);
    cudaFuncSetAttribute(gemm_out,
                         cudaFuncAttributeMaxDynamicSharedMemorySize, GSMEM_TOTAL);
    cudaFuncSetAttribute(attn_mma,
                         cudaFuncAttributeMaxDynamicSharedMemorySize, ATTN2_SMEM);

    __half* pxh;
    cudaGetSymbolAddress((void**)&pxh, g_xh);

    // 1: fused mask canonicalize + block-any
    mask_kernel<<<dim3(NBLK, NBLK), 256>>>((const unsigned char*)Mraw);

    // 2: X convert, 3: W transposes (batched)
    cvt_kernel<<<(MROWS * HIDD / 4 + 255) / 256, 256>>>(X, pxh, MROWS * HIDD / 4);
    tsplit4_kernel<<<dim3(HIDD / 32, HIDD / 32, 4), dim3(32, 8)>>>(Wq, Wk, Wv, Wo);

    // 4: batched Q/K/V projections (fp16 HMMA, 128x256 tiles)
    gemm_qkv<<<dim3(GN / 256, MROWS / 128, 3), 256, GSMEM_TOTAL>>>();

    // 5: V transpose (fp16, vectorized)
    vtsplit_kernel<<<dim3(HIDD / 64, MROWS / 64), dim3(32, 8)>>>();

    // 6: attention (fp16 single product)
    attn_mma<<<dim3(NBLK, Hh, Bb), 128, ATTN2_SMEM>>>();

    // 7: output projection
    gemm_out<<<dim3(GN / 256, MROWS / 128), 256, GSMEM_TOTAL>>>(out);
}

// round 13
// speedup vs baseline: 1.7478x; 1.0410x over previous
#include <cuda_runtime.h>
#include <cuda_fp16.h>
#include <stdint.h>
#include <math.h>

// Problem constants
#define Bb    2
#define Ss    2048
#define HIDD  2048
#define Hh    16
#define DHh   128
#define NBLK  32        // 2048 / 64
#define MROWS 4096      // B*S
#define SCALE_F 0.08838834764831845f   // 1/sqrt(128)

// ---------------- scratch (static device allocations) ----------------
__device__ __half g_xh [(size_t)MROWS * HIDD];    // X fp16
__device__ __half g_qhi[(size_t)MROWS * HIDD];
__device__ __half g_khi[(size_t)MROWS * HIDD];
__device__ __half g_vh [(size_t)MROWS * HIDD];    // V projection, [m][n] fp16
__device__ __half g_vthi[(size_t)MROWS * HIDD];   // [b][h*dh][s]
__device__ __half g_chi[(size_t)MROWS * HIDD];    // ctx fp16
__device__ __half g_wthi[4][(size_t)HIDD * HIDD]; // W^T [N][K] fp16
__device__ unsigned char g_mask[(size_t)Ss * Ss];
__device__ unsigned char g_bany[NBLK * NBLK];

// ======================= PTX helpers (family-portable) =======================
__device__ __forceinline__ uint32_t smem_u32(const void* p) {
    uint32_t a;
    asm("{ .reg .u64 t; cvta.to.shared.u64 t, %1; cvt.u32.u64 %0, t; }"
        : "=r"(a) : "l"(p));
    return a;
}
__device__ __forceinline__ void cp_async16(uint32_t dst, const void* src) {
    asm volatile("cp.async.cg.shared.global [%0], [%1], 16;"
                 :: "r"(dst), "l"(src) : "memory");
}
#define CP_COMMIT() asm volatile("cp.async.commit_group;" ::: "memory")
#define CP_WAIT(n)  asm volatile("cp.async.wait_group %0;" :: "n"(n) : "memory")

__device__ __forceinline__ void ldsm4(uint32_t* r, uint32_t addr) {
    asm volatile("ldmatrix.sync.aligned.m8n8.x4.shared.b16 {%0,%1,%2,%3}, [%4];"
                 : "=r"(r[0]), "=r"(r[1]), "=r"(r[2]), "=r"(r[3]) : "r"(addr));
}
__device__ __forceinline__ void mma16816(float* c, const uint32_t* a, const uint32_t* b) {
    asm volatile(
        "mma.sync.aligned.m16n8k16.row.col.f32.f16.f16.f32 "
        "{%0,%1,%2,%3}, {%4,%5,%6,%7}, {%8,%9}, {%0,%1,%2,%3};"
        : "+f"(c[0]), "+f"(c[1]), "+f"(c[2]), "+f"(c[3])
        : "r"(a[0]), "r"(a[1]), "r"(a[2]), "r"(a[3]), "r"(b[0]), "r"(b[1]));
}

#define SW128(o) ((o) ^ (((o) >> 3) & 0x70))

__device__ __forceinline__ uint32_t pack_h2(float a, float b) {
    __half2 t = __floats2half2_rn(a, b);
    return *(uint32_t*)&t;
}

// ---------------- fused mask canonicalization + block-any ----------------
__global__ void mask_kernel(const unsigned char* __restrict__ raw) {
    int qb = blockIdx.y, kb = blockIdx.x;
    int tid = threadIdx.x;
    int r = tid >> 2, c0 = (tid & 3) * 16;
    size_t e0 = (size_t)(qb * 64 + r) * Ss + kb * 64 + c0;

    int f;
    if (raw[0] == 1 && raw[1] == 1) f = 0;       // u8 / bool
    else if (raw[0] == 1)           f = 1;       // int32
    else                            f = 2;       // float32

    union { unsigned char v[16]; int4 vec; } u;
    if (f == 0) {
        int4 d = *(const int4*)(raw + e0);
        const unsigned char* p = (const unsigned char*)&d;
        #pragma unroll
        for (int c = 0; c < 16; c++) u.v[c] = p[c] != 0;
    } else if (f == 1) {
        const int* p32 = (const int*)raw + e0;
        #pragma unroll
        for (int c = 0; c < 16; c++) u.v[c] = p32[c] != 0;
    } else {
        const float* pf = (const float*)raw + e0;
        #pragma unroll
        for (int c = 0; c < 16; c++) u.v[c] = pf[c] != 0.0f;
    }
    int any = 0;
    #pragma unroll
    for (int c = 0; c < 16; c++) any |= u.v[c];
    *(int4*)(g_mask + e0) = u.vec;
    int res = __syncthreads_or(any);
    if (tid == 0) g_bany[qb * NBLK + kb] = res ? 1 : 0;
}

// ---------------- fp32 -> fp16 convert ----------------
__global__ void cvt_kernel(const float* __restrict__ in,
                           __half* __restrict__ hi, int n4) {
    int i = blockIdx.x * blockDim.x + threadIdx.x;
    if (i >= n4) return;
    float4 v = ((const float4*)in)[i];
    ushort4 hv = make_ushort4(__half_as_ushort(__float2half_rn(v.x)),
                              __half_as_ushort(__float2half_rn(v.y)),
                              __half_as_ushort(__float2half_rn(v.z)),
                              __half_as_ushort(__float2half_rn(v.w)));
    ((ushort4*)hi)[i] = hv;
}

// ---------------- batched transpose: W[K][N] -> T[N][K] fp16, z = which W ----
__global__ void tsplit4_kernel(const float* __restrict__ W0,
                               const float* __restrict__ W1,
                               const float* __restrict__ W2,
                               const float* __restrict__ W3) {
    __shared__ float t[32][33];
    int z = blockIdx.z;
    const float* W = (z == 0) ? W0 : (z == 1) ? W1 : (z == 2) ? W2 : W3;
    __half* Thi = g_wthi[z];
    int n0 = blockIdx.x * 32, k0 = blockIdx.y * 32;
    int tx = threadIdx.x, ty = threadIdx.y;   // block (32, 8)
    #pragma unroll
    for (int i = 0; i < 4; i++)
        t[ty + i * 8][tx] = W[(size_t)(k0 + ty + i * 8) * HIDD + n0 + tx];
    __syncthreads();
    #pragma unroll
    for (int i = 0; i < 4; i++)
        Thi[(size_t)(n0 + ty + i * 8) * HIDD + k0 + tx] =
            __float2half_rn(t[tx][ty + i * 8]);
}

// ---------------- transpose V (fp16): g_vh[m][n] -> vt[(b*2048+n)][s] ---------
__global__ void vtsplit_kernel() {
    __shared__ __half t[64][66];
    int n0 = blockIdx.x * 64, m0 = blockIdx.y * 64;
    int tx = threadIdx.x, ty = threadIdx.y;   // block (32, 8)
    #pragma unroll
    for (int i = 0; i < 8; i++) {
        int r = ty + i * 8;
        __half2 v = *(const __half2*)&g_vh[(size_t)(m0 + r) * HIDD + n0 + 2 * tx];
        t[r][2 * tx]     = __low2half(v);
        t[r][2 * tx + 1] = __high2half(v);
    }
    __syncthreads();
    int b = m0 >> 11;
    int s0 = m0 & 2047;
    #pragma unroll
    for (int i = 0; i < 8; i++) {
        int n = ty + i * 8;
        __half2 v = __halves2half2(t[2 * tx][n], t[2 * tx + 1][n]);
        *(__half2*)&g_vthi[((size_t)b * 2048 + n0 + n) * 2048 + s0 + 2 * tx] = v;
    }
}

// ---------------- HMMA fp16 GEMM core (128x256 CTA tile, 512 thr) ------------
// C = A @ B^T;  A [M][K] fp16, B [N][K] K-major fp16.  Single product, fp32 accum.
// 16 warps: warp_m = wid&3 (4), warp_n = wid>>2 (4); warp tile 32x64.
// 3-stage cp.async ring, one __syncthreads per iteration.
#define GK 2048
#define GN 2048
#define NIT 32
#define GTB_A 16384                       // 128 rows x 128 B
#define GTB_B 32768                       // 256 rows x 128 B
#define GSTAGE (GTB_A + GTB_B)            // 49152
#define GSMEM_TOTAL (3 * GSTAGE)          // 147456

__device__ __forceinline__
void gemm_body(const __half* __restrict__ Ah,
               const __half* __restrict__ Bh,
               float* __restrict__ C,
               __half* __restrict__ Chi,
               char* smem) {
    uint32_t sb = smem_u32(smem);
    int tid = threadIdx.x, l = tid & 31, wid = tid >> 5;
    int warp_m = wid & 3, warp_n = wid >> 2;
    int bm = blockIdx.y * 128, bn = blockIdx.x * 256;

    const char* srcA = (const char*)(Ah + (size_t)bm * GK);
    const char* srcB = (const char*)(Bh + (size_t)bn * GK);

    float c[2][8][4];
    #pragma unroll
    for (int i = 0; i < 2; i++)
        #pragma unroll
        for (int j = 0; j < 8; j++)
            #pragma unroll
            for (int k = 0; k < 4; k++) c[i][j][k] = 0.0f;

    auto stage_load = [&](int ci, int st) {
        int koff = ci * 128;
        uint32_t dstA = sb + st * GSTAGE;
        #pragma unroll
        for (int j = 0; j < 2; j++) {              // A: 2 vec / thread
            int vec = tid + j * 512;
            int row = vec >> 3, col = (vec & 7) * 16;
            cp_async16(dstA + SW128(row * 128 + col),
                       srcA + (size_t)row * (GK * 2) + koff + col);
        }
        uint32_t dstB = dstA + GTB_A;
        #pragma unroll
        for (int j = 0; j < 4; j++) {              // B: 4 vec / thread
            int vec = tid + j * 512;
            int row = vec >> 3, col = (vec & 7) * 16;
            cp_async16(dstB + SW128(row * 128 + col),
                       srcB + (size_t)row * (GK * 2) + koff + col);
        }
    };

    int rrA = (l & 7) + ((l >> 3) & 1) * 8;
    int kbA = ((l >> 4) & 1) * 16;
    int rrB = (l & 7) + ((l >> 4) & 1) * 8;
    int kbB = ((l >> 3) & 1) * 16;

    stage_load(0, 0);
    CP_COMMIT();
    stage_load(1, 1);
    CP_COMMIT();

    for (int i = 0; i < NIT; i++) {
        if (i + 1 < NIT) { CP_WAIT(1); } else { CP_WAIT(0); }
        __syncthreads();
        if (i + 2 < NIT) {
            stage_load(i + 2, (i + 2) % 3);
            CP_COMMIT();
        }

        uint32_t bA = sb + (i % 3) * GSTAGE;
        uint32_t bB = bA + GTB_A;

        #pragma unroll
        for (int ks = 0; ks < 4; ks++) {
            int kk = ks * 32;
            uint32_t bf[8][2];
            #pragma unroll
            for (int np = 0; np < 4; np++) {
                int rb = (warp_n * 64 + np * 16 + rrB) * 128;
                uint32_t off = rb + ((kk + kbB) ^ ((rb >> 3) & 0x70));
                uint32_t t[4];
                ldsm4(t, bB + off);
                bf[np * 2][0] = t[0]; bf[np * 2][1] = t[1];
                bf[np * 2 + 1][0] = t[2]; bf[np * 2 + 1][1] = t[3];
            }
            #pragma unroll
            for (int mt = 0; mt < 2; mt++) {
                int rb = (warp_m * 32 + mt * 16 + rrA) * 128;
                uint32_t off = rb + ((kk + kbA) ^ ((rb >> 3) & 0x70));
                uint32_t af[4];
                ldsm4(af, bA + off);
                #pragma unroll
                for (int nt = 0; nt < 8; nt++)
                    mma16816(c[mt][nt], af, bf[nt]);
            }
        }
    }

    // epilogue
    #pragma unroll
    for (int mt = 0; mt < 2; mt++) {
        #pragma unroll
        for (int nt = 0; nt < 8; nt++) {
            int m0 = bm + warp_m * 32 + mt * 16 + (l >> 2);
            int cn = bn + warp_n * 64 + nt * 8 + (l & 3) * 2;
            size_t i0 = (size_t)m0 * GN + cn, i1 = (size_t)(m0 + 8) * GN + cn;
            float v0 = c[mt][nt][0], v1 = c[mt][nt][1];
            float v2 = c[mt][nt][2], v3 = c[mt][nt][3];
            if (Chi) {
                *(uint32_t*)&Chi[i0] = pack_h2(v0, v1);
                *(uint32_t*)&Chi[i1] = pack_h2(v2, v3);
            } else {
                *(float2*)&C[i0] = make_float2(v0, v1);
                *(float2*)&C[i1] = make_float2(v2, v3);
            }
        }
    }
}

// batched QKV projection: z=0 -> Q, z=1 -> K, z=2 -> V (all fp16 hi)
__global__ __launch_bounds__(512, 1)
void gemm_qkv() {
    extern __shared__ char smem[];
    int z = blockIdx.z;
    const __half* B = g_wthi[z];
    __half* Chi = (z == 0) ? g_qhi : (z == 1) ? g_khi : g_vh;
    gemm_body(g_xh, B, nullptr, Chi, smem);
}

// output projection: fp32 out
__global__ __launch_bounds__(512, 1)
void gemm_out(float* __restrict__ C) {
    extern __shared__ char smem[];
    gemm_body(g_chi, g_wthi[3], C, nullptr, smem);
}

// ---------------- HMMA fp16 flash attention (single product) ----------------
// grid (qb=32, h=16, b=2), 128 threads (4 warps). Warp w owns q rows [w*16, w*16+16).
#define A_SQ       0                       // Q: c0, c1 (2 x 8KB)
#define A_KV(st)   (16384 + (st) * 32768)  // K c0 (8KB), K c1 (8KB), V (16KB)
#define A_P        81920                   // P 8KB
#define A_MASK(st) (90112 + (st) * 4096)
#define A_LIST     98304                   // int count + int[32]
#define ATTN2_SMEM 98560

__global__ __launch_bounds__(128, 1)
void attn_mma() {
    extern __shared__ char sm[];
    uint32_t sb = smem_u32(sm);
    int tid = threadIdx.x, l = tid & 31, w = tid >> 5;
    int qb = blockIdx.x, h = blockIdx.y, b = blockIdx.z;

    int rrA = (l & 7) + ((l >> 3) & 1) * 8;
    int kbA = ((l >> 4) & 1) * 16;
    int rrB = (l & 7) + ((l >> 4) & 1) * 8;
    int kbB = ((l >> 3) & 1) * 16;

    const size_t qrow_base = ((size_t)b * Ss + qb * 64) * HIDD;   // elements
    const size_t colb_base = (size_t)h * 256;                     // bytes within row

    // ---- load Q tiles (c0, c1) ----
    {
        #pragma unroll
        for (int t = 0; t < 2; t++) {
            const char* base = (const char*)g_qhi + qrow_base * 2
                               + colb_base + t * 128;
            uint32_t dst = sb + A_SQ + t * 8192;
            #pragma unroll
            for (int j = 0; j < 4; j++) {
                int vec = tid + j * 128;
                int row = vec >> 3, cbt = (vec & 7) * 16;
                cp_async16(dst + SW128(row * 128 + cbt),
                           base + (size_t)row * 4096 + cbt);
            }
        }
        CP_COMMIT();
    }

    // ---- build visible-kb list ----
    int* sList = (int*)(sm + A_LIST);
    if (tid == 0) {
        int c = 0;
        for (int kb = 0; kb < NBLK; kb++)
            if (g_bany[qb * NBLK + kb]) sList[1 + c++] = kb;
        sList[0] = c;
    }
    __syncthreads();
    int cnt = sList[0];

    // ---- KV + mask prefetch ----
    auto prefetch = [&](int kb, int st) {
        uint32_t kvb = sb + A_KV(st);
        size_t krow = ((size_t)b * Ss + kb * 64) * HIDD * 2;   // bytes
        #pragma unroll
        for (int t = 0; t < 2; t++) {     // K chunk 0, chunk 1
            const char* base = (const char*)g_khi + krow + colb_base + t * 128;
            uint32_t dst = kvb + t * 8192;
            #pragma unroll
            for (int j = 0; j < 4; j++) {
                int vec = tid + j * 128;
                int row = vec >> 3, cbt = (vec & 7) * 16;
                cp_async16(dst + SW128(row * 128 + cbt),
                           base + (size_t)row * 4096 + cbt);
            }
        }
        size_t vrow = ((size_t)b * 2048 + h * 128) * 2048 * 2;  // bytes; +dh*4096
        {
            const char* base = (const char*)g_vthi + vrow + kb * 128;
            uint32_t dst = kvb + 16384;
            #pragma unroll
            for (int j = 0; j < 8; j++) {
                int vec = tid + j * 128;
                int row = vec >> 3, cbt = (vec & 7) * 16;
                cp_async16(dst + SW128(row * 128 + cbt),
                           base + (size_t)row * 4096 + cbt);
            }
        }
        {
            const char* base = (const char*)g_mask + (size_t)(qb * 64) * Ss + kb * 64;
            uint32_t dst = sb + A_MASK(st);
            #pragma unroll
            for (int j = 0; j < 2; j++) {
                int vec = tid + j * 128;
                int row = vec >> 2, cbt = (vec & 3) * 16;
                cp_async16(dst + row * 64 + cbt, base + (size_t)row * Ss + cbt);
            }
        }
    };

    prefetch(sList[1], 0);
    CP_COMMIT();

    // ---- state ----
    float o[16][4];
    #pragma unroll
    for (int i = 0; i < 16; i++)
        #pragma unroll
        for (int j = 0; j < 4; j++) o[i][j] = 0.0f;
    float m0r = -1e30f, m1r = -1e30f, l0r = 0.0f, l1r = 0.0f;

    int qrow0 = w * 16;
    int r0l = qrow0 + (l >> 2);

    for (int i = 0; i < cnt; i++) {
        int st = i & 1;
        __syncthreads();   // all warps done with stage st^1 (iter i-1) before refill
        if (i + 1 < cnt) {
            prefetch(sList[1 + i + 1], st ^ 1);
            CP_COMMIT();
            CP_WAIT(1);
        } else {
            CP_WAIT(0);
        }
        __syncthreads();

        uint32_t kvb = sb + A_KV(st);

        // ---- S = Q @ K^T (fp16) ----
        float s[8][4];
        #pragma unroll
        for (int nt = 0; nt < 8; nt++)
            #pragma unroll
            for (int j = 0; j < 4; j++) s[nt][j] = 0.0f;

        #pragma unroll
        for (int chunk = 0; chunk < 2; chunk++) {
            uint32_t bQh = sb + A_SQ + chunk * 8192;
            uint32_t bKh = kvb + chunk * 8192;
            #pragma unroll
            for (int ks = 0; ks < 4; ks++) {
                int kk = ks * 32;
                int rowA = qrow0 + rrA;
                uint32_t offA = rowA * 128 + ((kk + kbA) ^ ((rowA & 7) << 4));
                uint32_t ah[4];
                ldsm4(ah, bQh + offA);
                #pragma unroll
                for (int np = 0; np < 4; np++) {
                    int rowB = np * 16 + rrB;
                    uint32_t offB = rowB * 128 + ((kk + kbB) ^ ((rowB & 7) << 4));
                    uint32_t th[4];
                    ldsm4(th, bKh + offB);
                    uint32_t bh0[2] = {th[0], th[1]}, bh1[2] = {th[2], th[3]};
                    mma16816(s[np * 2], ah, bh0);
                    mma16816(s[np * 2 + 1], ah, bh1);
                }
            }
        }

        // ---- mask + scale + online softmax ----
        const unsigned char* mk = (const unsigned char*)(sm + A_MASK(st))
                                  + r0l * 64 + (l & 3) * 2;
        float mx0 = -1e30f, mx1 = -1e30f;
        #pragma unroll
        for (int nt = 0; nt < 8; nt++) {
            int cb = nt * 8;
            float t00 = mk[cb]       ? s[nt][0] * SCALE_F : -1e30f;
            float t01 = mk[cb + 1]   ? s[nt][1] * SCALE_F : -1e30f;
            float t10 = mk[cb + 512] ? s[nt][2] * SCALE_F : -1e30f;
            float t11 = mk[cb + 513] ? s[nt][3] * SCALE_F : -1e30f;
            s[nt][0] = t00; s[nt][1] = t01; s[nt][2] = t10; s[nt][3] = t11;
            mx0 = fmaxf(mx0, fmaxf(t00, t01));
            mx1 = fmaxf(mx1, fmaxf(t10, t11));
        }
        mx0 = fmaxf(mx0, __shfl_xor_sync(0xffffffffu, mx0, 1));
        mx0 = fmaxf(mx0, __shfl_xor_sync(0xffffffffu, mx0, 2));
        mx1 = fmaxf(mx1, __shfl_xor_sync(0xffffffffu, mx1, 1));
        mx1 = fmaxf(mx1, __shfl_xor_sync(0xffffffffu, mx1, 2));
        float mn0 = fmaxf(m0r, mx0), mn1 = fmaxf(m1r, mx1);
        float sc0 = __expf(m0r - mn0), sc1 = __expf(m1r - mn1);
        m0r = mn0; m1r = mn1;

        // ---- P = exp(S - m), write fp16 to smem (full-column swizzle) ----
        float sum0 = 0.0f, sum1 = 0.0f;
        int colb = (l & 3) * 4;
        int sw0 = (r0l & 7) << 4;                 // same for r0l and r0l+8
        uint32_t rb0 = r0l * 128;
        uint32_t rb1 = (r0l + 8) * 128;
        #pragma unroll
        for (int nt = 0; nt < 8; nt++) {
            float p00 = __expf(s[nt][0] - mn0);
            float p01 = __expf(s[nt][1] - mn0);
            float p10 = __expf(s[nt][2] - mn1);
            float p11 = __expf(s[nt][3] - mn1);
            sum0 += p00 + p01;
            sum1 += p10 + p11;
            uint32_t colsw = (uint32_t)((nt * 16 + colb) ^ sw0);
            *(uint32_t*)(sm + A_P + rb0 + colsw) = pack_h2(p00, p01);
            *(uint32_t*)(sm + A_P + rb1 + colsw) = pack_h2(p10, p11);
        }
        sum0 += __shfl_xor_sync(0xffffffffu, sum0, 1);
        sum0 += __shfl_xor_sync(0xffffffffu, sum0, 2);
        sum1 += __shfl_xor_sync(0xffffffffu, sum1, 1);
        sum1 += __shfl_xor_sync(0xffffffffu, sum1, 2);
        l0r = l0r * sc0 + sum0;
        l1r = l1r * sc1 + sum1;

        // ---- O rescale + O += P @ Vt (fp16) ----
        #pragma unroll
        for (int nt = 0; nt < 16; nt++) {
            o[nt][0] *= sc0; o[nt][1] *= sc0;
            o[nt][2] *= sc1; o[nt][3] *= sc1;
        }
        __syncwarp();

        uint32_t bPh = sb + A_P;
        uint32_t bVh = kvb + 16384;
        #pragma unroll
        for (int ks = 0; ks < 4; ks++) {
            int kk = ks * 32;
            int rowA = qrow0 + rrA;
            uint32_t offA = rowA * 128 + ((kk + kbA) ^ ((rowA & 7) << 4));
            uint32_t ph[4];
            ldsm4(ph, bPh + offA);
            #pragma unroll
            for (int np = 0; np < 8; np++) {
                int rowB = np * 16 + rrB;
                uint32_t offB = rowB * 128 + ((kk + kbB) ^ ((rowB & 7) << 4));
                uint32_t th[4];
                ldsm4(th, bVh + offB);
                uint32_t vh0[2] = {th[0], th[1]}, vh1[2] = {th[2], th[3]};
                mma16816(o[np * 2], ph, vh0);
                mma16816(o[np * 2 + 1], ph, vh1);
            }
        }
    }

    // ---- epilogue: O /= l, write ctx fp16 ----
    float inv0 = 1.0f / l0r, inv1 = 1.0f / l1r;
    size_t row0 = (size_t)b * Ss + qb * 64 + qrow0 + (l >> 2);
    size_t row1 = row0 + 8;
    int cn0 = h * 128 + (l & 3) * 2;
    #pragma unroll
    for (int nt = 0; nt < 16; nt++) {
        int cn = cn0 + nt * 8;
        float v0 = o[nt][0] * inv0, v1 = o[nt][1] * inv0;
        float v2 = o[nt][2] * inv1, v3 = o[nt][3] * inv1;
        size_t i0 = row0 * HIDD + cn, i1 = row1 * HIDD + cn;
        *(uint32_t*)&g_chi[i0] = pack_h2(v0, v1);
        *(uint32_t*)&g_chi[i1] = pack_h2(v2, v3);
    }
}

// ---------------- launch ----------------
extern "C" void kernel_launch(void* const* d_in, const int* in_sizes, int n_in,
                              void* d_out, int out_size) {
    const float* X  = (const float*)d_in[0];
    const float* Wq = (const float*)d_in[1];
    const float* Wk = (const float*)d_in[2];
    const float* Wv = (const float*)d_in[3];
    const float* Wo = (const float*)d_in[4];
    const void*  Mraw = d_in[5];
    float* out = (float*)d_out;

    cudaFuncSetAttribute(gemm_qkv,
                         cudaFuncAttributeMaxDynamicSharedMemorySize, GSMEM_TOTAL);
    cudaFuncSetAttribute(gemm_out,
                         cudaFuncAttributeMaxDynamicSharedMemorySize, GSMEM_TOTAL);
    cudaFuncSetAttribute(attn_mma,
                         cudaFuncAttributeMaxDynamicSharedMemorySize, ATTN2_SMEM);

    __half* pxh;
    cudaGetSymbolAddress((void**)&pxh, g_xh);

    // 1: fused mask canonicalize + block-any
    mask_kernel<<<dim3(NBLK, NBLK), 256>>>((const unsigned char*)Mraw);

    // 2: X convert, 3: W transposes (batched)
    cvt_kernel<<<(MROWS * HIDD / 4 + 255) / 256, 256>>>(X, pxh, MROWS * HIDD / 4);
    tsplit4_kernel<<<dim3(HIDD / 32, HIDD / 32, 4), dim3(32, 8)>>>(Wq, Wk, Wv, Wo);

    // 4: batched Q/K/V projections (fp16 HMMA, 128x256 tiles, 512 thr)
    gemm_qkv<<<dim3(GN / 256, MROWS / 128, 3), 512, GSMEM_TOTAL>>>();

    // 5: V transpose (fp16, vectorized)
    vtsplit_kernel<<<dim3(HIDD / 64, MROWS / 64), dim3(32, 8)>>>();

    // 6: attention (fp16 single product)
    attn_mma<<<dim3(NBLK, Hh, Bb), 128, ATTN2_SMEM>>>();

    // 7: output projection
    gemm_out<<<dim3(GN / 256, MROWS / 128), 512, GSMEM_TOTAL>>>(out);
}

// round 14
// speedup vs baseline: 1.7986x; 1.0290x over previous
#include <cuda_runtime.h>
#include <cuda_fp16.h>
#include <stdint.h>
#include <math.h>

// Problem constants
#define Bb    2
#define Ss    2048
#define HIDD  2048
#define Hh    16
#define DHh   128
#define NBLK  32        // 2048 / 64
#define MROWS 4096      // B*S
#define SCALE_F 0.08838834764831845f   // 1/sqrt(128)

// ---------------- scratch (static device allocations) ----------------
__device__ __half g_xh [(size_t)MROWS * HIDD];    // X fp16
__device__ __half g_qhi[(size_t)MROWS * HIDD];
__device__ __half g_khi[(size_t)MROWS * HIDD];
__device__ __half g_vh [(size_t)MROWS * HIDD];    // V projection, [m][n] fp16
__device__ __half g_vthi[(size_t)MROWS * HIDD];   // [b][h*dh][s]
__device__ __half g_chi[(size_t)MROWS * HIDD];    // ctx fp16
__device__ __half g_wthi[4][(size_t)HIDD * HIDD]; // W^T [N][K] fp16
__device__ unsigned char g_mask[(size_t)Ss * Ss];
__device__ unsigned char g_bany[NBLK * NBLK];

// ======================= PTX helpers (family-portable) =======================
__device__ __forceinline__ uint32_t smem_u32(const void* p) {
    uint32_t a;
    asm("{ .reg .u64 t; cvta.to.shared.u64 t, %1; cvt.u32.u64 %0, t; }"
        : "=r"(a) : "l"(p));
    return a;
}
__device__ __forceinline__ void cp_async16(uint32_t dst, const void* src) {
    asm volatile("cp.async.cg.shared.global [%0], [%1], 16;"
                 :: "r"(dst), "l"(src) : "memory");
}
#define CP_COMMIT() asm volatile("cp.async.commit_group;" ::: "memory")
#define CP_WAIT(n)  asm volatile("cp.async.wait_group %0;" :: "n"(n) : "memory")

__device__ __forceinline__ void ldsm4(uint32_t* r, uint32_t addr) {
    asm volatile("ldmatrix.sync.aligned.m8n8.x4.shared.b16 {%0,%1,%2,%3}, [%4];"
                 : "=r"(r[0]), "=r"(r[1]), "=r"(r[2]), "=r"(r[3]) : "r"(addr));
}
__device__ __forceinline__ void mma16816(float* c, const uint32_t* a, const uint32_t* b) {
    asm volatile(
        "mma.sync.aligned.m16n8k16.row.col.f32.f16.f16.f32 "
        "{%0,%1,%2,%3}, {%4,%5,%6,%7}, {%8,%9}, {%0,%1,%2,%3};"
        : "+f"(c[0]), "+f"(c[1]), "+f"(c[2]), "+f"(c[3])
        : "r"(a[0]), "r"(a[1]), "r"(a[2]), "r"(a[3]), "r"(b[0]), "r"(b[1]));
}

#define SW128(o) ((o) ^ (((o) >> 3) & 0x70))

__device__ __forceinline__ uint32_t pack_h2(float a, float b) {
    __half2 t = __floats2half2_rn(a, b);
    return *(uint32_t*)&t;
}

// ---------------- fused mask canonicalization + block-any ----------------
__global__ void mask_kernel(const unsigned char* __restrict__ raw) {
    int qb = blockIdx.y, kb = blockIdx.x;
    int tid = threadIdx.x;
    int r = tid >> 2, c0 = (tid & 3) * 16;
    size_t e0 = (size_t)(qb * 64 + r) * Ss + kb * 64 + c0;

    int f;
    if (raw[0] == 1 && raw[1] == 1) f = 0;       // u8 / bool
    else if (raw[0] == 1)           f = 1;       // int32
    else                            f = 2;       // float32

    union { unsigned char v[16]; int4 vec; } u;
    if (f == 0) {
        int4 d = *(const int4*)(raw + e0);
        const unsigned char* p = (const unsigned char*)&d;
        #pragma unroll
        for (int c = 0; c < 16; c++) u.v[c] = p[c] != 0;
    } else if (f == 1) {
        const int* p32 = (const int*)raw + e0;
        #pragma unroll
        for (int c = 0; c < 16; c++) u.v[c] = p32[c] != 0;
    } else {
        const float* pf = (const float*)raw + e0;
        #pragma unroll
        for (int c = 0; c < 16; c++) u.v[c] = pf[c] != 0.0f;
    }
    int any = 0;
    #pragma unroll
    for (int c = 0; c < 16; c++) any |= u.v[c];
    *(int4*)(g_mask + e0) = u.vec;
    int res = __syncthreads_or(any);
    if (tid == 0) g_bany[qb * NBLK + kb] = res ? 1 : 0;
}

// ---------------- fp32 -> fp16 convert ----------------
__global__ void cvt_kernel(const float* __restrict__ in,
                           __half* __restrict__ hi, int n4) {
    int i = blockIdx.x * blockDim.x + threadIdx.x;
    if (i >= n4) return;
    float4 v = ((const float4*)in)[i];
    ushort4 hv = make_ushort4(__half_as_ushort(__float2half_rn(v.x)),
                              __half_as_ushort(__float2half_rn(v.y)),
                              __half_as_ushort(__float2half_rn(v.z)),
                              __half_as_ushort(__float2half_rn(v.w)));
    ((ushort4*)hi)[i] = hv;
}

// ---------------- batched transpose: W[K][N] -> T[N][K] fp16, z = which W ----
__global__ void tsplit4_kernel(const float* __restrict__ W0,
                               const float* __restrict__ W1,
                               const float* __restrict__ W2,
                               const float* __restrict__ W3) {
    __shared__ float t[32][33];
    int z = blockIdx.z;
    const float* W = (z == 0) ? W0 : (z == 1) ? W1 : (z == 2) ? W2 : W3;
    __half* Thi = g_wthi[z];
    int n0 = blockIdx.x * 32, k0 = blockIdx.y * 32;
    int tx = threadIdx.x, ty = threadIdx.y;   // block (32, 8)
    #pragma unroll
    for (int i = 0; i < 4; i++)
        t[ty + i * 8][tx] = W[(size_t)(k0 + ty + i * 8) * HIDD + n0 + tx];
    __syncthreads();
    #pragma unroll
    for (int i = 0; i < 4; i++)
        Thi[(size_t)(n0 + ty + i * 8) * HIDD + k0 + tx] =
            __float2half_rn(t[tx][ty + i * 8]);
}

// ---------------- transpose V (fp16): g_vh[m][n] -> vt[(b*2048+n)][s] ---------
__global__ void vtsplit_kernel() {
    __shared__ __half t[64][66];
    int n0 = blockIdx.x * 64, m0 = blockIdx.y * 64;
    int tx = threadIdx.x, ty = threadIdx.y;   // block (32, 8)
    #pragma unroll
    for (int i = 0; i < 8; i++) {
        int r = ty + i * 8;
        __half2 v = *(const __half2*)&g_vh[(size_t)(m0 + r) * HIDD + n0 + 2 * tx];
        t[r][2 * tx]     = __low2half(v);
        t[r][2 * tx + 1] = __high2half(v);
    }
    __syncthreads();
    int b = m0 >> 11;
    int s0 = m0 & 2047;
    #pragma unroll
    for (int i = 0; i < 8; i++) {
        int n = ty + i * 8;
        __half2 v = __halves2half2(t[2 * tx][n], t[2 * tx + 1][n]);
        *(__half2*)&g_vthi[((size_t)b * 2048 + n0 + n) * 2048 + s0 + 2 * tx] = v;
    }
}

// ---------------- HMMA fp16 GEMM core (128x256 CTA tile, 512 thr) ------------
// C = A @ B^T;  A [M][K] fp16, B [N][K] K-major fp16.  Single product, fp32 accum.
// 16 warps: warp_m = wid&3 (4), warp_n = wid>>2 (4); warp tile 32x64.
// 2-stage ring, K=128 per iteration (two 64-fp16 sub-chunks per stage),
// ONE __syncthreads per iteration:  wait(0) -> sync -> load(i+1) -> compute(i)
#define GK 2048
#define GN 2048
#define NIT 16
#define GSUB_A 16384                      // A sub-tile: 128 rows x 128 B
#define GSUB_B 32768                      // B sub-tile: 256 rows x 128 B
#define GSTAGE (2 * GSUB_A + 2 * GSUB_B)  // 98304
#define GSMEM_TOTAL (2 * GSTAGE)          // 196608

__device__ __forceinline__
void gemm_body(const __half* __restrict__ Ah,
               const __half* __restrict__ Bh,
               float* __restrict__ C,
               __half* __restrict__ Chi,
               char* smem) {
    uint32_t sb = smem_u32(smem);
    int tid = threadIdx.x, l = tid & 31, wid = tid >> 5;
    int warp_m = wid & 3, warp_n = wid >> 2;
    int bm = blockIdx.y * 128, bn = blockIdx.x * 256;

    const char* srcA = (const char*)(Ah + (size_t)bm * GK);
    const char* srcB = (const char*)(Bh + (size_t)bn * GK);

    float c[2][8][4];
    #pragma unroll
    for (int i = 0; i < 2; i++)
        #pragma unroll
        for (int j = 0; j < 8; j++)
            #pragma unroll
            for (int k = 0; k < 4; k++) c[i][j][k] = 0.0f;

    // load one K=128 chunk (256 bytes/row) as two 128B sub-tiles per operand
    auto stage_load = [&](int ci, int st) {
        int koff = ci * 256;
        #pragma unroll
        for (int sub = 0; sub < 2; sub++) {
            uint32_t dstA = sb + st * GSTAGE + sub * GSUB_A;
            int kb = koff + sub * 128;
            #pragma unroll
            for (int j = 0; j < 2; j++) {          // A sub: 2 vec / thread
                int vec = tid + j * 512;
                int row = vec >> 3, col = (vec & 7) * 16;
                cp_async16(dstA + SW128(row * 128 + col),
                           srcA + (size_t)row * (GK * 2) + kb + col);
            }
            uint32_t dstB = sb + st * GSTAGE + 2 * GSUB_A + sub * GSUB_B;
            #pragma unroll
            for (int j = 0; j < 4; j++) {          // B sub: 4 vec / thread
                int vec = tid + j * 512;
                int row = vec >> 3, col = (vec & 7) * 16;
                cp_async16(dstB + SW128(row * 128 + col),
                           srcB + (size_t)row * (GK * 2) + kb + col);
            }
        }
    };

    int rrA = (l & 7) + ((l >> 3) & 1) * 8;
    int kbA = ((l >> 4) & 1) * 16;
    int rrB = (l & 7) + ((l >> 4) & 1) * 8;
    int kbB = ((l >> 3) & 1) * 16;

    stage_load(0, 0);
    CP_COMMIT();

    for (int i = 0; i < NIT; i++) {
        CP_WAIT(0);
        __syncthreads();
        if (i + 1 < NIT) {
            stage_load(i + 1, (i + 1) & 1);
            CP_COMMIT();
        }

        uint32_t stg = sb + (i & 1) * GSTAGE;

        #pragma unroll
        for (int sub = 0; sub < 2; sub++) {
            uint32_t bA = stg + sub * GSUB_A;
            uint32_t bB = stg + 2 * GSUB_A + sub * GSUB_B;
            #pragma unroll
            for (int ks = 0; ks < 4; ks++) {
                int kk = ks * 32;
                uint32_t bf[8][2];
                #pragma unroll
                for (int np = 0; np < 4; np++) {
                    int rb = (warp_n * 64 + np * 16 + rrB) * 128;
                    uint32_t off = rb + ((kk + kbB) ^ ((rb >> 3) & 0x70));
                    uint32_t t[4];
                    ldsm4(t, bB + off);
                    bf[np * 2][0] = t[0]; bf[np * 2][1] = t[1];
                    bf[np * 2 + 1][0] = t[2]; bf[np * 2 + 1][1] = t[3];
                }
                #pragma unroll
                for (int mt = 0; mt < 2; mt++) {
                    int rb = (warp_m * 32 + mt * 16 + rrA) * 128;
                    uint32_t off = rb + ((kk + kbA) ^ ((rb >> 3) & 0x70));
                    uint32_t af[4];
                    ldsm4(af, bA + off);
                    #pragma unroll
                    for (int nt = 0; nt < 8; nt++)
                        mma16816(c[mt][nt], af, bf[nt]);
                }
            }
        }
    }

    // epilogue
    #pragma unroll
    for (int mt = 0; mt < 2; mt++) {
        #pragma unroll
        for (int nt = 0; nt < 8; nt++) {
            int m0 = bm + warp_m * 32 + mt * 16 + (l >> 2);
            int cn = bn + warp_n * 64 + nt * 8 + (l & 3) * 2;
            size_t i0 = (size_t)m0 * GN + cn, i1 = (size_t)(m0 + 8) * GN + cn;
            float v0 = c[mt][nt][0], v1 = c[mt][nt][1];
            float v2 = c[mt][nt][2], v3 = c[mt][nt][3];
            if (Chi) {
                *(uint32_t*)&Chi[i0] = pack_h2(v0, v1);
                *(uint32_t*)&Chi[i1] = pack_h2(v2, v3);
            } else {
                *(float2*)&C[i0] = make_float2(v0, v1);
                *(float2*)&C[i1] = make_float2(v2, v3);
            }
        }
    }
}

// batched QKV projection: z=0 -> Q, z=1 -> K, z=2 -> V (all fp16 hi)
__global__ __launch_bounds__(512, 1)
void gemm_qkv() {
    extern __shared__ char smem[];
    int z = blockIdx.z;
    const __half* B = g_wthi[z];
    __half* Chi = (z == 0) ? g_qhi : (z == 1) ? g_khi : g_vh;
    gemm_body(g_xh, B, nullptr, Chi, smem);
}

// output projection: fp32 out
__global__ __launch_bounds__(512, 1)
void gemm_out(float* __restrict__ C) {
    extern __shared__ char smem[];
    gemm_body(g_chi, g_wthi[3], C, nullptr, smem);
}

// ---------------- HMMA fp16 flash attention (single product) ----------------
// grid (qb=32, h=16, b=2), 128 threads (4 warps). Warp w owns q rows [w*16, w*16+16).
#define A_SQ       0                       // Q: c0, c1 (2 x 8KB)
#define A_KV(st)   (16384 + (st) * 32768)  // K c0 (8KB), K c1 (8KB), V (16KB)
#define A_P        81920                   // P 8KB
#define A_MASK(st) (90112 + (st) * 4096)
#define A_LIST     98304                   // int count + int[32]
#define ATTN2_SMEM 98560

__global__ __launch_bounds__(128, 1)
void attn_mma() {
    extern __shared__ char sm[];
    uint32_t sb = smem_u32(sm);
    int tid = threadIdx.x, l = tid & 31, w = tid >> 5;
    int qb = blockIdx.x, h = blockIdx.y, b = blockIdx.z;

    int rrA = (l & 7) + ((l >> 3) & 1) * 8;
    int kbA = ((l >> 4) & 1) * 16;
    int rrB = (l & 7) + ((l >> 4) & 1) * 8;
    int kbB = ((l >> 3) & 1) * 16;

    const size_t qrow_base = ((size_t)b * Ss + qb * 64) * HIDD;   // elements
    const size_t colb_base = (size_t)h * 256;                     // bytes within row

    // ---- load Q tiles (c0, c1) ----
    {
        #pragma unroll
        for (int t = 0; t < 2; t++) {
            const char* base = (const char*)g_qhi + qrow_base * 2
                               + colb_base + t * 128;
            uint32_t dst = sb + A_SQ + t * 8192;
            #pragma unroll
            for (int j = 0; j < 4; j++) {
                int vec = tid + j * 128;
                int row = vec >> 3, cbt = (vec & 7) * 16;
                cp_async16(dst + SW128(row * 128 + cbt),
                           base + (size_t)row * 4096 + cbt);
            }
        }
        CP_COMMIT();
    }

    // ---- build visible-kb list ----
    int* sList = (int*)(sm + A_LIST);
    if (tid == 0) {
        int c = 0;
        for (int kb = 0; kb < NBLK; kb++)
            if (g_bany[qb * NBLK + kb]) sList[1 + c++] = kb;
        sList[0] = c;
    }
    __syncthreads();
    int cnt = sList[0];

    // ---- KV + mask prefetch ----
    auto prefetch = [&](int kb, int st) {
        uint32_t kvb = sb + A_KV(st);
        size_t krow = ((size_t)b * Ss + kb * 64) * HIDD * 2;   // bytes
        #pragma unroll
        for (int t = 0; t < 2; t++) {     // K chunk 0, chunk 1
            const char* base = (const char*)g_khi + krow + colb_base + t * 128;
            uint32_t dst = kvb + t * 8192;
            #pragma unroll
            for (int j = 0; j < 4; j++) {
                int vec = tid + j * 128;
                int row = vec >> 3, cbt = (vec & 7) * 16;
                cp_async16(dst + SW128(row * 128 + cbt),
                           base + (size_t)row * 4096 + cbt);
            }
        }
        size_t vrow = ((size_t)b * 2048 + h * 128) * 2048 * 2;  // bytes; +dh*4096
        {
            const char* base = (const char*)g_vthi + vrow + kb * 128;
            uint32_t dst = kvb + 16384;
            #pragma unroll
            for (int j = 0; j < 8; j++) {
                int vec = tid + j * 128;
                int row = vec >> 3, cbt = (vec & 7) * 16;
                cp_async16(dst + SW128(row * 128 + cbt),
                           base + (size_t)row * 4096 + cbt);
            }
        }
        {
            const char* base = (const char*)g_mask + (size_t)(qb * 64) * Ss + kb * 64;
            uint32_t dst = sb + A_MASK(st);
            #pragma unroll
            for (int j = 0; j < 2; j++) {
                int vec = tid + j * 128;
                int row = vec >> 2, cbt = (vec & 3) * 16;
                cp_async16(dst + row * 64 + cbt, base + (size_t)row * Ss + cbt);
            }
        }
    };

    prefetch(sList[1], 0);
    CP_COMMIT();

    // ---- state ----
    float o[16][4];
    #pragma unroll
    for (int i = 0; i < 16; i++)
        #pragma unroll
        for (int j = 0; j < 4; j++) o[i][j] = 0.0f;
    float m0r = -1e30f, m1r = -1e30f, l0r = 0.0f, l1r = 0.0f;

    int qrow0 = w * 16;
    int r0l = qrow0 + (l >> 2);

    for (int i = 0; i < cnt; i++) {
        int st = i & 1;
        __syncthreads();   // all warps done with stage st^1 (iter i-1) before refill
        if (i + 1 < cnt) {
            prefetch(sList[1 + i + 1], st ^ 1);
            CP_COMMIT();
            CP_WAIT(1);
        } else {
            CP_WAIT(0);
        }
        __syncthreads();

        uint32_t kvb = sb + A_KV(st);

        // ---- S = Q @ K^T (fp16) ----
        float s[8][4];
        #pragma unroll
        for (int nt = 0; nt < 8; nt++)
            #pragma unroll
            for (int j = 0; j < 4; j++) s[nt][j] = 0.0f;

        #pragma unroll
        for (int chunk = 0; chunk < 2; chunk++) {
            uint32_t bQh = sb + A_SQ + chunk * 8192;
            uint32_t bKh = kvb + chunk * 8192;
            #pragma unroll
            for (int ks = 0; ks < 4; ks++) {
                int kk = ks * 32;
                int rowA = qrow0 + rrA;
                uint32_t offA = rowA * 128 + ((kk + kbA) ^ ((rowA & 7) << 4));
                uint32_t ah[4];
                ldsm4(ah, bQh + offA);
                #pragma unroll
                for (int np = 0; np < 4; np++) {
                    int rowB = np * 16 + rrB;
                    uint32_t offB = rowB * 128 + ((kk + kbB) ^ ((rowB & 7) << 4));
                    uint32_t th[4];
                    ldsm4(th, bKh + offB);
                    uint32_t bh0[2] = {th[0], th[1]}, bh1[2] = {th[2], th[3]};
                    mma16816(s[np * 2], ah, bh0);
                    mma16816(s[np * 2 + 1], ah, bh1);
                }
            }
        }

        // ---- mask + scale + online softmax ----
        const unsigned char* mk = (const unsigned char*)(sm + A_MASK(st))
                                  + r0l * 64 + (l & 3) * 2;
        float mx0 = -1e30f, mx1 = -1e30f;
        #pragma unroll
        for (int nt = 0; nt < 8; nt++) {
            int cb = nt * 8;
            float t00 = mk[cb]       ? s[nt][0] * SCALE_F : -1e30f;
            float t01 = mk[cb + 1]   ? s[nt][1] * SCALE_F : -1e30f;
            float t10 = mk[cb + 512] ? s[nt][2] * SCALE_F : -1e30f;
            float t11 = mk[cb + 513] ? s[nt][3] * SCALE_F : -1e30f;
            s[nt][0] = t00; s[nt][1] = t01; s[nt][2] = t10; s[nt][3] = t11;
            mx0 = fmaxf(mx0, fmaxf(t00, t01));
            mx1 = fmaxf(mx1, fmaxf(t10, t11));
        }
        mx0 = fmaxf(mx0, __shfl_xor_sync(0xffffffffu, mx0, 1));
        mx0 = fmaxf(mx0, __shfl_xor_sync(0xffffffffu, mx0, 2));
        mx1 = fmaxf(mx1, __shfl_xor_sync(0xffffffffu, mx1, 1));
        mx1 = fmaxf(mx1, __shfl_xor_sync(0xffffffffu, mx1, 2));
        float mn0 = fmaxf(m0r, mx0), mn1 = fmaxf(m1r, mx1);
        float sc0 = __expf(m0r - mn0), sc1 = __expf(m1r - mn1);
        m0r = mn0; m1r = mn1;

        // ---- P = exp(S - m), write fp16 to smem (full-column swizzle) ----
        float sum0 = 0.0f, sum1 = 0.0f;
        int colb = (l & 3) * 4;
        int sw0 = (r0l & 7) << 4;                 // same for r0l and r0l+8
        uint32_t rb0 = r0l * 128;
        uint32_t rb1 = (r0l + 8) * 128;
        #pragma unroll
        for (int nt = 0; nt < 8; nt++) {
            float p00 = __expf(s[nt][0] - mn0);
            float p01 = __expf(s[nt][1] - mn0);
            float p10 = __expf(s[nt][2] - mn1);
            float p11 = __expf(s[nt][3] - mn1);
            sum0 += p00 + p01;
            sum1 += p10 + p11;
            uint32_t colsw = (uint32_t)((nt * 16 + colb) ^ sw0);
            *(uint32_t*)(sm + A_P + rb0 + colsw) = pack_h2(p00, p01);
            *(uint32_t*)(sm + A_P + rb1 + colsw) = pack_h2(p10, p11);
        }
        sum0 += __shfl_xor_sync(0xffffffffu, sum0, 1);
        sum0 += __shfl_xor_sync(0xffffffffu, sum0, 2);
        sum1 += __shfl_xor_sync(0xffffffffu, sum1, 1);
        sum1 += __shfl_xor_sync(0xffffffffu, sum1, 2);
        l0r = l0r * sc0 + sum0;
        l1r = l1r * sc1 + sum1;

        // ---- O rescale + O += P @ Vt (fp16) ----
        #pragma unroll
        for (int nt = 0; nt < 16; nt++) {
            o[nt][0] *= sc0; o[nt][1] *= sc0;
            o[nt][2] *= sc1; o[nt][3] *= sc1;
        }
        __syncwarp();

        uint32_t bPh = sb + A_P;
        uint32_t bVh = kvb + 16384;
        #pragma unroll
        for (int ks = 0; ks < 4; ks++) {
            int kk = ks * 32;
            int rowA = qrow0 + rrA;
            uint32_t offA = rowA * 128 + ((kk + kbA) ^ ((rowA & 7) << 4));
            uint32_t ph[4];
            ldsm4(ph, bPh + offA);
            #pragma unroll
            for (int np = 0; np < 8; np++) {
                int rowB = np * 16 + rrB;
                uint32_t offB = rowB * 128 + ((kk + kbB) ^ ((rowB & 7) << 4));
                uint32_t th[4];
                ldsm4(th, bVh + offB);
                uint32_t vh0[2] = {th[0], th[1]}, vh1[2] = {th[2], th[3]};
                mma16816(o[np * 2], ph, vh0);
                mma16816(o[np * 2 + 1], ph, vh1);
            }
        }
    }

    // ---- epilogue: O /= l, write ctx fp16 ----
    float inv0 = 1.0f / l0r, inv1 = 1.0f / l1r;
    size_t row0 = (size_t)b * Ss + qb * 64 + qrow0 + (l >> 2);
    size_t row1 = row0 + 8;
    int cn0 = h * 128 + (l & 3) * 2;
    #pragma unroll
    for (int nt = 0; nt < 16; nt++) {
        int cn = cn0 + nt * 8;
        float v0 = o[nt][0] * inv0, v1 = o[nt][1] * inv0;
        float v2 = o[nt][2] * inv1, v3 = o[nt][3] * inv1;
        size_t i0 = row0 * HIDD + cn, i1 = row1 * HIDD + cn;
        *(uint32_t*)&g_chi[i0] = pack_h2(v0, v1);
        *(uint32_t*)&g_chi[i1] = pack_h2(v2, v3);
    }
}

// ---------------- launch ----------------
extern "C" void kernel_launch(void* const* d_in, const int* in_sizes, int n_in,
                              void* d_out, int out_size) {
    const float* X  = (const float*)d_in[0];
    const float* Wq = (const float*)d_in[1];
    const float* Wk = (const float*)d_in[2];
    const float* Wv = (const float*)d_in[3];
    const float* Wo = (const float*)d_in[4];
    const void*  Mraw = d_in[5];
    float* out = (float*)d_out;

    cudaFuncSetAttribute(gemm_qkv,
                         cudaFuncAttributeMaxDynamicSharedMemorySize, GSMEM_TOTAL);
    cudaFuncSetAttribute(gemm_out,
                         cudaFuncAttributeMaxDynamicSharedMemorySize, GSMEM_TOTAL);
    cudaFuncSetAttribute(attn_mma,
                         cudaFuncAttributeMaxDynamicSharedMemorySize, ATTN2_SMEM);

    __half* pxh;
    cudaGetSymbolAddress((void**)&pxh, g_xh);

    // 1: fused mask canonicalize + block-any
    mask_kernel<<<dim3(NBLK, NBLK), 256>>>((const unsigned char*)Mraw);

    // 2: X convert, 3: W transposes (batched)
    cvt_kernel<<<(MROWS * HIDD / 4 + 255) / 256, 256>>>(X, pxh, MROWS * HIDD / 4);
    tsplit4_kernel<<<dim3(HIDD / 32, HIDD / 32, 4), dim3(32, 8)>>>(Wq, Wk, Wv, Wo);

    // 4: batched Q/K/V projections (fp16 HMMA, 128x256 tiles, 512 thr, NIT=16)
    gemm_qkv<<<dim3(GN / 256, MROWS / 128, 3), 512, GSMEM_TOTAL>>>();

    // 5: V transpose (fp16, vectorized)
    vtsplit_kernel<<<dim3(HIDD / 64, MROWS / 64), dim3(32, 8)>>>();

    // 6: attention (fp16 single product)
    attn_mma<<<dim3(NBLK, Hh, Bb), 128, ATTN2_SMEM>>>();

    // 7: output projection
    gemm_out<<<dim3(GN / 256, MROWS / 128), 512, GSMEM_TOTAL>>>(out);
}

// round 15
// speedup vs baseline: 1.8400x; 1.0231x over previous
#include <cuda_runtime.h>
#include <cuda_fp16.h>
#include <stdint.h>
#include <math.h>

// Problem constants
#define Bb    2
#define Ss    2048
#define HIDD  2048
#define Hh    16
#define DHh   128
#define NBLK  32        // 2048 / 64
#define MROWS 4096      // B*S
#define SCALE_F 0.08838834764831845f   // 1/sqrt(128)

// ---------------- scratch (static device allocations) ----------------
__device__ __half g_xh [(size_t)MROWS * HIDD];    // X fp16
__device__ __half g_qhi[(size_t)MROWS * HIDD];
__device__ __half g_khi[(size_t)MROWS * HIDD];
__device__ __half g_vh [(size_t)MROWS * HIDD];    // V projection, [m][n] fp16
__device__ __half g_vthi[(size_t)MROWS * HIDD];   // [b][h*dh][s]
__device__ __half g_chi[(size_t)MROWS * HIDD];    // ctx fp16
__device__ __half g_wthi[4][(size_t)HIDD * HIDD]; // W^T [N][K] fp16
__device__ unsigned char g_mask[(size_t)Ss * Ss];
__device__ unsigned char g_bany[NBLK * NBLK];

// ======================= PTX helpers (family-portable) =======================
__device__ __forceinline__ uint32_t smem_u32(const void* p) {
    uint32_t a;
    asm("{ .reg .u64 t; cvta.to.shared.u64 t, %1; cvt.u32.u64 %0, t; }"
        : "=r"(a) : "l"(p));
    return a;
}
__device__ __forceinline__ void cp_async16(uint32_t dst, const void* src) {
    asm volatile("cp.async.cg.shared.global [%0], [%1], 16;"
                 :: "r"(dst), "l"(src) : "memory");
}
#define CP_COMMIT() asm volatile("cp.async.commit_group;" ::: "memory")
#define CP_WAIT(n)  asm volatile("cp.async.wait_group %0;" :: "n"(n) : "memory")

__device__ __forceinline__ void ldsm4(uint32_t* r, uint32_t addr) {
    asm volatile("ldmatrix.sync.aligned.m8n8.x4.shared.b16 {%0,%1,%2,%3}, [%4];"
                 : "=r"(r[0]), "=r"(r[1]), "=r"(r[2]), "=r"(r[3]) : "r"(addr));
}
__device__ __forceinline__ void mma16816(float* c, const uint32_t* a, const uint32_t* b) {
    asm volatile(
        "mma.sync.aligned.m16n8k16.row.col.f32.f16.f16.f32 "
        "{%0,%1,%2,%3}, {%4,%5,%6,%7}, {%8,%9}, {%0,%1,%2,%3};"
        : "+f"(c[0]), "+f"(c[1]), "+f"(c[2]), "+f"(c[3])
        : "r"(a[0]), "r"(a[1]), "r"(a[2]), "r"(a[3]), "r"(b[0]), "r"(b[1]));
}

#define SW128(o) ((o) ^ (((o) >> 3) & 0x70))

__device__ __forceinline__ uint32_t pack_h2(float a, float b) {
    __half2 t = __floats2half2_rn(a, b);
    return *(uint32_t*)&t;
}

// ---------------- fused mask canonicalization + block-any ----------------
__global__ void mask_kernel(const unsigned char* __restrict__ raw) {
    int qb = blockIdx.y, kb = blockIdx.x;
    int tid = threadIdx.x;
    int r = tid >> 2, c0 = (tid & 3) * 16;
    size_t e0 = (size_t)(qb * 64 + r) * Ss + kb * 64 + c0;

    int f;
    if (raw[0] == 1 && raw[1] == 1) f = 0;       // u8 / bool
    else if (raw[0] == 1)           f = 1;       // int32
    else                            f = 2;       // float32

    union { unsigned char v[16]; int4 vec; } u;
    if (f == 0) {
        int4 d = *(const int4*)(raw + e0);
        const unsigned char* p = (const unsigned char*)&d;
        #pragma unroll
        for (int c = 0; c < 16; c++) u.v[c] = p[c] != 0;
    } else if (f == 1) {
        const int* p32 = (const int*)raw + e0;
        #pragma unroll
        for (int c = 0; c < 16; c++) u.v[c] = p32[c] != 0;
    } else {
        const float* pf = (const float*)raw + e0;
        #pragma unroll
        for (int c = 0; c < 16; c++) u.v[c] = pf[c] != 0.0f;
    }
    int any = 0;
    #pragma unroll
    for (int c = 0; c < 16; c++) any |= u.v[c];
    *(int4*)(g_mask + e0) = u.vec;
    int res = __syncthreads_or(any);
    if (tid == 0) g_bany[qb * NBLK + kb] = res ? 1 : 0;
}

// ---------------- fp32 -> fp16 convert ----------------
__global__ void cvt_kernel(const float* __restrict__ in,
                           __half* __restrict__ hi, int n4) {
    int i = blockIdx.x * blockDim.x + threadIdx.x;
    if (i >= n4) return;
    float4 v = ((const float4*)in)[i];
    ushort4 hv = make_ushort4(__half_as_ushort(__float2half_rn(v.x)),
                              __half_as_ushort(__float2half_rn(v.y)),
                              __half_as_ushort(__float2half_rn(v.z)),
                              __half_as_ushort(__float2half_rn(v.w)));
    ((ushort4*)hi)[i] = hv;
}

// ---------------- batched transpose: W[K][N] -> T[N][K] fp16, z = which W ----
__global__ void tsplit4_kernel(const float* __restrict__ W0,
                               const float* __restrict__ W1,
                               const float* __restrict__ W2,
                               const float* __restrict__ W3) {
    __shared__ float t[32][33];
    int z = blockIdx.z;
    const float* W = (z == 0) ? W0 : (z == 1) ? W1 : (z == 2) ? W2 : W3;
    __half* Thi = g_wthi[z];
    int n0 = blockIdx.x * 32, k0 = blockIdx.y * 32;
    int tx = threadIdx.x, ty = threadIdx.y;   // block (32, 8)
    #pragma unroll
    for (int i = 0; i < 4; i++)
        t[ty + i * 8][tx] = W[(size_t)(k0 + ty + i * 8) * HIDD + n0 + tx];
    __syncthreads();
    #pragma unroll
    for (int i = 0; i < 4; i++)
        Thi[(size_t)(n0 + ty + i * 8) * HIDD + k0 + tx] =
            __float2half_rn(t[tx][ty + i * 8]);
}

// ---------------- transpose V (fp16): g_vh[m][n] -> vt[(b*2048+n)][s] ---------
__global__ void vtsplit_kernel() {
    __shared__ __half t[64][66];
    int n0 = blockIdx.x * 64, m0 = blockIdx.y * 64;
    int tx = threadIdx.x, ty = threadIdx.y;   // block (32, 8)
    #pragma unroll
    for (int i = 0; i < 8; i++) {
        int r = ty + i * 8;
        __half2 v = *(const __half2*)&g_vh[(size_t)(m0 + r) * HIDD + n0 + 2 * tx];
        t[r][2 * tx]     = __low2half(v);
        t[r][2 * tx + 1] = __high2half(v);
    }
    __syncthreads();
    int b = m0 >> 11;
    int s0 = m0 & 2047;
    #pragma unroll
    for (int i = 0; i < 8; i++) {
        int n = ty + i * 8;
        __half2 v = __halves2half2(t[2 * tx][n], t[2 * tx + 1][n]);
        *(__half2*)&g_vthi[((size_t)b * 2048 + n0 + n) * 2048 + s0 + 2 * tx] = v;
    }
}

// ---------------- HMMA fp16 GEMM core (128x128 CTA tile, 256 thr) ------------
// C = A @ B^T;  A [M][K] fp16, B [N][K] K-major fp16.  Single product, fp32 accum.
// 8 warps: warp_m = wid&1 (2), warp_n = wid>>1 (4); warp tile 64x32.
// K=64 per stage, 3-stage ring, one __syncthreads per iteration.
// smem 96KB/CTA -> 2 CTAs/SM: interleaved barrier domains hide sync bubbles.
#define GK 2048
#define GN 2048
#define NIT 32
#define GTB 16384                         // 128 rows x 128 B (A or B sub-tile)
#define GSTAGE (2 * GTB)                  // 32768
#define GSMEM_TOTAL (3 * GSTAGE)          // 98304

__device__ __forceinline__
void gemm_body(const __half* __restrict__ Ah,
               const __half* __restrict__ Bh,
               float* __restrict__ C,
               __half* __restrict__ Chi,
               char* smem) {
    uint32_t sb = smem_u32(smem);
    int tid = threadIdx.x, l = tid & 31, wid = tid >> 5;
    int warp_m = wid & 1, warp_n = wid >> 1;
    int bm = blockIdx.y * 128, bn = blockIdx.x * 128;

    const char* srcA = (const char*)(Ah + (size_t)bm * GK);
    const char* srcB = (const char*)(Bh + (size_t)bn * GK);

    float c[4][4][4];
    #pragma unroll
    for (int i = 0; i < 4; i++)
        #pragma unroll
        for (int j = 0; j < 4; j++)
            #pragma unroll
            for (int k = 0; k < 4; k++) c[i][j][k] = 0.0f;

    auto stage_load = [&](int ci, int st) {
        int koff = ci * 128;
        uint32_t dstA = sb + st * GSTAGE;
        uint32_t dstB = dstA + GTB;
        #pragma unroll
        for (int j = 0; j < 4; j++) {              // A: 4 vec / thread
            int vec = tid + j * 256;
            int row = vec >> 3, col = (vec & 7) * 16;
            uint32_t so = SW128(row * 128 + col);
            size_t go = (size_t)row * (GK * 2) + koff + col;
            cp_async16(dstA + so, srcA + go);
            cp_async16(dstB + so, srcB + go);
        }
    };

    int rrA = (l & 7) + ((l >> 3) & 1) * 8;
    int kbA = ((l >> 4) & 1) * 16;
    int rrB = (l & 7) + ((l >> 4) & 1) * 8;
    int kbB = ((l >> 3) & 1) * 16;

    stage_load(0, 0);
    CP_COMMIT();
    stage_load(1, 1);
    CP_COMMIT();

    for (int i = 0; i < NIT; i++) {
        if (i + 1 < NIT) { CP_WAIT(1); } else { CP_WAIT(0); }
        __syncthreads();
        if (i + 2 < NIT) {
            stage_load(i + 2, (i + 2) % 3);
            CP_COMMIT();
        }

        uint32_t bA = sb + (i % 3) * GSTAGE;
        uint32_t bB = bA + GTB;

        #pragma unroll
        for (int ks = 0; ks < 4; ks++) {
            int kk = ks * 32;
            uint32_t bf[4][2];
            #pragma unroll
            for (int np = 0; np < 2; np++) {
                int rb = (warp_n * 32 + np * 16 + rrB) * 128;
                uint32_t off = rb + ((kk + kbB) ^ ((rb >> 3) & 0x70));
                uint32_t t[4];
                ldsm4(t, bB + off);
                bf[np * 2][0] = t[0]; bf[np * 2][1] = t[1];
                bf[np * 2 + 1][0] = t[2]; bf[np * 2 + 1][1] = t[3];
            }
            #pragma unroll
            for (int mt = 0; mt < 4; mt++) {
                int rb = (warp_m * 64 + mt * 16 + rrA) * 128;
                uint32_t off = rb + ((kk + kbA) ^ ((rb >> 3) & 0x70));
                uint32_t af[4];
                ldsm4(af, bA + off);
                #pragma unroll
                for (int nt = 0; nt < 4; nt++)
                    mma16816(c[mt][nt], af, bf[nt]);
            }
        }
    }

    // epilogue
    #pragma unroll
    for (int mt = 0; mt < 4; mt++) {
        #pragma unroll
        for (int nt = 0; nt < 4; nt++) {
            int m0 = bm + warp_m * 64 + mt * 16 + (l >> 2);
            int cn = bn + warp_n * 32 + nt * 8 + (l & 3) * 2;
            size_t i0 = (size_t)m0 * GN + cn, i1 = (size_t)(m0 + 8) * GN + cn;
            float v0 = c[mt][nt][0], v1 = c[mt][nt][1];
            float v2 = c[mt][nt][2], v3 = c[mt][nt][3];
            if (Chi) {
                *(uint32_t*)&Chi[i0] = pack_h2(v0, v1);
                *(uint32_t*)&Chi[i1] = pack_h2(v2, v3);
            } else {
                *(float2*)&C[i0] = make_float2(v0, v1);
                *(float2*)&C[i1] = make_float2(v2, v3);
            }
        }
    }
}

// batched QKV projection: z=0 -> Q, z=1 -> K, z=2 -> V (all fp16 hi)
__global__ __launch_bounds__(256, 2)
void gemm_qkv() {
    extern __shared__ char smem[];
    int z = blockIdx.z;
    const __half* B = g_wthi[z];
    __half* Chi = (z == 0) ? g_qhi : (z == 1) ? g_khi : g_vh;
    gemm_body(g_xh, B, nullptr, Chi, smem);
}

// output projection: fp32 out
__global__ __launch_bounds__(256, 2)
void gemm_out(float* __restrict__ C) {
    extern __shared__ char smem[];
    gemm_body(g_chi, g_wthi[3], C, nullptr, smem);
}

// ---------------- HMMA fp16 flash attention (single product) ----------------
// grid (qb=32, h=16, b=2), 128 threads (4 warps). Warp w owns q rows [w*16, w*16+16).
// smem 98.5KB -> 2 CTAs/SM to hide barrier bubbles.
#define A_SQ       0                       // Q: c0, c1 (2 x 8KB)
#define A_KV(st)   (16384 + (st) * 32768)  // K c0 (8KB), K c1 (8KB), V (16KB)
#define A_P        81920                   // P 8KB
#define A_MASK(st) (90112 + (st) * 4096)
#define A_LIST     98304                   // int count + int[32]
#define ATTN2_SMEM 98560

__global__ __launch_bounds__(128, 2)
void attn_mma() {
    extern __shared__ char sm[];
    uint32_t sb = smem_u32(sm);
    int tid = threadIdx.x, l = tid & 31, w = tid >> 5;
    int qb = blockIdx.x, h = blockIdx.y, b = blockIdx.z;

    int rrA = (l & 7) + ((l >> 3) & 1) * 8;
    int kbA = ((l >> 4) & 1) * 16;
    int rrB = (l & 7) + ((l >> 4) & 1) * 8;
    int kbB = ((l >> 3) & 1) * 16;

    const size_t qrow_base = ((size_t)b * Ss + qb * 64) * HIDD;   // elements
    const size_t colb_base = (size_t)h * 256;                     // bytes within row

    // ---- load Q tiles (c0, c1) ----
    {
        #pragma unroll
        for (int t = 0; t < 2; t++) {
            const char* base = (const char*)g_qhi + qrow_base * 2
                               + colb_base + t * 128;
            uint32_t dst = sb + A_SQ + t * 8192;
            #pragma unroll
            for (int j = 0; j < 4; j++) {
                int vec = tid + j * 128;
                int row = vec >> 3, cbt = (vec & 7) * 16;
                cp_async16(dst + SW128(row * 128 + cbt),
                           base + (size_t)row * 4096 + cbt);
            }
        }
        CP_COMMIT();
    }

    // ---- build visible-kb list ----
    int* sList = (int*)(sm + A_LIST);
    if (tid == 0) {
        int c = 0;
        for (int kb = 0; kb < NBLK; kb++)
            if (g_bany[qb * NBLK + kb]) sList[1 + c++] = kb;
        sList[0] = c;
    }
    __syncthreads();
    int cnt = sList[0];

    // ---- KV + mask prefetch ----
    auto prefetch = [&](int kb, int st) {
        uint32_t kvb = sb + A_KV(st);
        size_t krow = ((size_t)b * Ss + kb * 64) * HIDD * 2;   // bytes
        #pragma unroll
        for (int t = 0; t < 2; t++) {     // K chunk 0, chunk 1
            const char* base = (const char*)g_khi + krow + colb_base + t * 128;
            uint32_t dst = kvb + t * 8192;
            #pragma unroll
            for (int j = 0; j < 4; j++) {
                int vec = tid + j * 128;
                int row = vec >> 3, cbt = (vec & 7) * 16;
                cp_async16(dst + SW128(row * 128 + cbt),
                           base + (size_t)row * 4096 + cbt);
            }
        }
        size_t vrow = ((size_t)b * 2048 + h * 128) * 2048 * 2;  // bytes; +dh*4096
        {
            const char* base = (const char*)g_vthi + vrow + kb * 128;
            uint32_t dst = kvb + 16384;
            #pragma unroll
            for (int j = 0; j < 8; j++) {
                int vec = tid + j * 128;
                int row = vec >> 3, cbt = (vec & 7) * 16;
                cp_async16(dst + SW128(row * 128 + cbt),
                           base + (size_t)row * 4096 + cbt);
            }
        }
        {
            const char* base = (const char*)g_mask + (size_t)(qb * 64) * Ss + kb * 64;
            uint32_t dst = sb + A_MASK(st);
            #pragma unroll
            for (int j = 0; j < 2; j++) {
                int vec = tid + j * 128;
                int row = vec >> 2, cbt = (vec & 3) * 16;
                cp_async16(dst + row * 64 + cbt, base + (size_t)row * Ss + cbt);
            }
        }
    };

    prefetch(sList[1], 0);
    CP_COMMIT();

    // ---- state ----
    float o[16][4];
    #pragma unroll
    for (int i = 0; i < 16; i++)
        #pragma unroll
        for (int j = 0; j < 4; j++) o[i][j] = 0.0f;
    float m0r = -1e30f, m1r = -1e30f, l0r = 0.0f, l1r = 0.0f;

    int qrow0 = w * 16;
    int r0l = qrow0 + (l >> 2);

    for (int i = 0; i < cnt; i++) {
        int st = i & 1;
        __syncthreads();   // all warps done with stage st^1 (iter i-1) before refill
        if (i + 1 < cnt) {
            prefetch(sList[1 + i + 1], st ^ 1);
            CP_COMMIT();
            CP_WAIT(1);
        } else {
            CP_WAIT(0);
        }
        __syncthreads();

        uint32_t kvb = sb + A_KV(st);

        // ---- S = Q @ K^T (fp16) ----
        float s[8][4];
        #pragma unroll
        for (int nt = 0; nt < 8; nt++)
            #pragma unroll
            for (int j = 0; j < 4; j++) s[nt][j] = 0.0f;

        #pragma unroll
        for (int chunk = 0; chunk < 2; chunk++) {
            uint32_t bQh = sb + A_SQ + chunk * 8192;
            uint32_t bKh = kvb + chunk * 8192;
            #pragma unroll
            for (int ks = 0; ks < 4; ks++) {
                int kk = ks * 32;
                int rowA = qrow0 + rrA;
                uint32_t offA = rowA * 128 + ((kk + kbA) ^ ((rowA & 7) << 4));
                uint32_t ah[4];
                ldsm4(ah, bQh + offA);
                #pragma unroll
                for (int np = 0; np < 4; np++) {
                    int rowB = np * 16 + rrB;
                    uint32_t offB = rowB * 128 + ((kk + kbB) ^ ((rowB & 7) << 4));
                    uint32_t th[4];
                    ldsm4(th, bKh + offB);
                    uint32_t bh0[2] = {th[0], th[1]}, bh1[2] = {th[2], th[3]};
                    mma16816(s[np * 2], ah, bh0);
                    mma16816(s[np * 2 + 1], ah, bh1);
                }
            }
        }

        // ---- mask + scale + online softmax ----
        const unsigned char* mk = (const unsigned char*)(sm + A_MASK(st))
                                  + r0l * 64 + (l & 3) * 2;
        float mx0 = -1e30f, mx1 = -1e30f;
        #pragma unroll
        for (int nt = 0; nt < 8; nt++) {
            int cb = nt * 8;
            float t00 = mk[cb]       ? s[nt][0] * SCALE_F : -1e30f;
            float t01 = mk[cb + 1]   ? s[nt][1] * SCALE_F : -1e30f;
            float t10 = mk[cb + 512] ? s[nt][2] * SCALE_F : -1e30f;
            float t11 = mk[cb + 513] ? s[nt][3] * SCALE_F : -1e30f;
            s[nt][0] = t00; s[nt][1] = t01; s[nt][2] = t10; s[nt][3] = t11;
            mx0 = fmaxf(mx0, fmaxf(t00, t01));
            mx1 = fmaxf(mx1, fmaxf(t10, t11));
        }
        mx0 = fmaxf(mx0, __shfl_xor_sync(0xffffffffu, mx0, 1));
        mx0 = fmaxf(mx0, __shfl_xor_sync(0xffffffffu, mx0, 2));
        mx1 = fmaxf(mx1, __shfl_xor_sync(0xffffffffu, mx1, 1));
        mx1 = fmaxf(mx1, __shfl_xor_sync(0xffffffffu, mx1, 2));
        float mn0 = fmaxf(m0r, mx0), mn1 = fmaxf(m1r, mx1);
        float sc0 = __expf(m0r - mn0), sc1 = __expf(m1r - mn1);
        m0r = mn0; m1r = mn1;

        // ---- P = exp(S - m), write fp16 to smem (full-column swizzle) ----
        float sum0 = 0.0f, sum1 = 0.0f;
        int colb = (l & 3) * 4;
        int sw0 = (r0l & 7) << 4;                 // same for r0l and r0l+8
        uint32_t rb0 = r0l * 128;
        uint32_t rb1 = (r0l + 8) * 128;
        #pragma unroll
        for (int nt = 0; nt < 8; nt++) {
            float p00 = __expf(s[nt][0] - mn0);
            float p01 = __expf(s[nt][1] - mn0);
            float p10 = __expf(s[nt][2] - mn1);
            float p11 = __expf(s[nt][3] - mn1);
            sum0 += p00 + p01;
            sum1 += p10 + p11;
            uint32_t colsw = (uint32_t)((nt * 16 + colb) ^ sw0);
            *(uint32_t*)(sm + A_P + rb0 + colsw) = pack_h2(p00, p01);
            *(uint32_t*)(sm + A_P + rb1 + colsw) = pack_h2(p10, p11);
        }
        sum0 += __shfl_xor_sync(0xffffffffu, sum0, 1);
        sum0 += __shfl_xor_sync(0xffffffffu, sum0, 2);
        sum1 += __shfl_xor_sync(0xffffffffu, sum1, 1);
        sum1 += __shfl_xor_sync(0xffffffffu, sum1, 2);
        l0r = l0r * sc0 + sum0;
        l1r = l1r * sc1 + sum1;

        // ---- O rescale + O += P @ Vt (fp16) ----
        #pragma unroll
        for (int nt = 0; nt < 16; nt++) {
            o[nt][0] *= sc0; o[nt][1] *= sc0;
            o[nt][2] *= sc1; o[nt][3] *= sc1;
        }
        __syncwarp();

        uint32_t bPh = sb + A_P;
        uint32_t bVh = kvb + 16384;
        #pragma unroll
        for (int ks = 0; ks < 4; ks++) {
            int kk = ks * 32;
            int rowA = qrow0 + rrA;
            uint32_t offA = rowA * 128 + ((kk + kbA) ^ ((rowA & 7) << 4));
            uint32_t ph[4];
            ldsm4(ph, bPh + offA);
            #pragma unroll
            for (int np = 0; np < 8; np++) {
                int rowB = np * 16 + rrB;
                uint32_t offB = rowB * 128 + ((kk + kbB) ^ ((rowB & 7) << 4));
                uint32_t th[4];
                ldsm4(th, bVh + offB);
                uint32_t vh0[2] = {th[0], th[1]}, vh1[2] = {th[2], th[3]};
                mma16816(o[np * 2], ph, vh0);
                mma16816(o[np * 2 + 1], ph, vh1);
            }
        }
    }

    // ---- epilogue: O /= l, write ctx fp16 ----
    float inv0 = 1.0f / l0r, inv1 = 1.0f / l1r;
    size_t row0 = (size_t)b * Ss + qb * 64 + qrow0 + (l >> 2);
    size_t row1 = row0 + 8;
    int cn0 = h * 128 + (l & 3) * 2;
    #pragma unroll
    for (int nt = 0; nt < 16; nt++) {
        int cn = cn0 + nt * 8;
        float v0 = o[nt][0] * inv0, v1 = o[nt][1] * inv0;
        float v2 = o[nt][2] * inv1, v3 = o[nt][3] * inv1;
        size_t i0 = row0 * HIDD + cn, i1 = row1 * HIDD + cn;
        *(uint32_t*)&g_chi[i0] = pack_h2(v0, v1);
        *(uint32_t*)&g_chi[i1] = pack_h2(v2, v3);
    }
}

// ---------------- launch ----------------
extern "C" void kernel_launch(void* const* d_in, const int* in_sizes, int n_in,
                              void* d_out, int out_size) {
    const float* X  = (const float*)d_in[0];
    const float* Wq = (const float*)d_in[1];
    const float* Wk = (const float*)d_in[2];
    const float* Wv = (const float*)d_in[3];
    const float* Wo = (const float*)d_in[4];
    const void*  Mraw = d_in[5];
    float* out = (float*)d_out;

    cudaFuncSetAttribute(gemm_qkv,
                         cudaFuncAttributeMaxDynamicSharedMemorySize, GSMEM_TOTAL);
    cudaFuncSetAttribute(gemm_out,
                         cudaFuncAttributeMaxDynamicSharedMemorySize, GSMEM_TOTAL);
    cudaFuncSetAttribute(attn_mma,
                         cudaFuncAttributeMaxDynamicSharedMemorySize, ATTN2_SMEM);

    __half* pxh;
    cudaGetSymbolAddress((void**)&pxh, g_xh);

    // 1: fused mask canonicalize + block-any
    mask_kernel<<<dim3(NBLK, NBLK), 256>>>((const unsigned char*)Mraw);

    // 2: X convert, 3: W transposes (batched)
    cvt_kernel<<<(MROWS * HIDD / 4 + 255) / 256, 256>>>(X, pxh, MROWS * HIDD / 4);
    tsplit4_kernel<<<dim3(HIDD / 32, HIDD / 32, 4), dim3(32, 8)>>>(Wq, Wk, Wv, Wo);

    // 4: batched Q/K/V projections (fp16 HMMA, 128x128 tiles, 2 CTA/SM)
    gemm_qkv<<<dim3(GN / 128, MROWS / 128, 3), 256, GSMEM_TOTAL>>>();

    // 5: V transpose (fp16, vectorized)
    vtsplit_kernel<<<dim3(HIDD / 64, MROWS / 64), dim3(32, 8)>>>();

    // 6: attention (fp16 single product, 2 CTA/SM)
    attn_mma<<<dim3(NBLK, Hh, Bb), 128, ATTN2_SMEM>>>();

    // 7: output projection
    gemm_out<<<dim3(GN / 128, MROWS / 128), 256, GSMEM_TOTAL>>>(out);
}

// round 16
// speedup vs baseline: 1.9172x; 1.0419x over previous
#include <cuda_runtime.h>
#include <cuda_fp16.h>
#include <stdint.h>
#include <math.h>

// Problem constants
#define Bb    2
#define Ss    2048
#define HIDD  2048
#define Hh    16
#define DHh   128
#define NBLK  32        // 2048 / 64
#define MROWS 4096      // B*S
#define SCALE_F 0.08838834764831845f   // 1/sqrt(128)

// ---------------- scratch (static device allocations) ----------------
__device__ __half g_xh [(size_t)MROWS * HIDD];    // X fp16
__device__ __half g_qhi[(size_t)MROWS * HIDD];
__device__ __half g_khi[(size_t)MROWS * HIDD];
__device__ __half g_vh [(size_t)MROWS * HIDD];    // V projection, [m][n] fp16
__device__ __half g_vthi[(size_t)MROWS * HIDD];   // [b][h*dh][s]
__device__ __half g_chi[(size_t)MROWS * HIDD];    // ctx fp16
__device__ __half g_wthi[4][(size_t)HIDD * HIDD]; // W^T [N][K] fp16
__device__ unsigned char g_mask[(size_t)Ss * Ss];
__device__ unsigned char g_bany[NBLK * NBLK];

// ======================= PTX helpers (family-portable) =======================
__device__ __forceinline__ uint32_t smem_u32(const void* p) {
    uint32_t a;
    asm("{ .reg .u64 t; cvta.to.shared.u64 t, %1; cvt.u32.u64 %0, t; }"
        : "=r"(a) : "l"(p));
    return a;
}
__device__ __forceinline__ void cp_async16(uint32_t dst, const void* src) {
    asm volatile("cp.async.cg.shared.global [%0], [%1], 16;"
                 :: "r"(dst), "l"(src) : "memory");
}
#define CP_COMMIT() asm volatile("cp.async.commit_group;" ::: "memory")
#define CP_WAIT(n)  asm volatile("cp.async.wait_group %0;" :: "n"(n) : "memory")

__device__ __forceinline__ void ldsm4(uint32_t* r, uint32_t addr) {
    asm volatile("ldmatrix.sync.aligned.m8n8.x4.shared.b16 {%0,%1,%2,%3}, [%4];"
                 : "=r"(r[0]), "=r"(r[1]), "=r"(r[2]), "=r"(r[3]) : "r"(addr));
}
__device__ __forceinline__ void mma16816(float* c, const uint32_t* a, const uint32_t* b) {
    asm volatile(
        "mma.sync.aligned.m16n8k16.row.col.f32.f16.f16.f32 "
        "{%0,%1,%2,%3}, {%4,%5,%6,%7}, {%8,%9}, {%0,%1,%2,%3};"
        : "+f"(c[0]), "+f"(c[1]), "+f"(c[2]), "+f"(c[3])
        : "r"(a[0]), "r"(a[1]), "r"(a[2]), "r"(a[3]), "r"(b[0]), "r"(b[1]));
}

#define SW128(o) ((o) ^ (((o) >> 3) & 0x70))

__device__ __forceinline__ uint32_t pack_h2(float a, float b) {
    __half2 t = __floats2half2_rn(a, b);
    return *(uint32_t*)&t;
}

// ---------------- fused mask canonicalization + block-any ----------------
__global__ void mask_kernel(const unsigned char* __restrict__ raw) {
    int qb = blockIdx.y, kb = blockIdx.x;
    int tid = threadIdx.x;
    int r = tid >> 2, c0 = (tid & 3) * 16;
    size_t e0 = (size_t)(qb * 64 + r) * Ss + kb * 64 + c0;

    int f;
    if (raw[0] == 1 && raw[1] == 1) f = 0;       // u8 / bool
    else if (raw[0] == 1)           f = 1;       // int32
    else                            f = 2;       // float32

    union { unsigned char v[16]; int4 vec; } u;
    if (f == 0) {
        int4 d = *(const int4*)(raw + e0);
        const unsigned char* p = (const unsigned char*)&d;
        #pragma unroll
        for (int c = 0; c < 16; c++) u.v[c] = p[c] != 0;
    } else if (f == 1) {
        const int* p32 = (const int*)raw + e0;
        #pragma unroll
        for (int c = 0; c < 16; c++) u.v[c] = p32[c] != 0;
    } else {
        const float* pf = (const float*)raw + e0;
        #pragma unroll
        for (int c = 0; c < 16; c++) u.v[c] = pf[c] != 0.0f;
    }
    int any = 0;
    #pragma unroll
    for (int c = 0; c < 16; c++) any |= u.v[c];
    *(int4*)(g_mask + e0) = u.vec;
    int res = __syncthreads_or(any);
    if (tid == 0) g_bany[qb * NBLK + kb] = res ? 1 : 0;
}

// ---------------- fp32 -> fp16 convert ----------------
__global__ void cvt_kernel(const float* __restrict__ in,
                           __half* __restrict__ hi, int n4) {
    int i = blockIdx.x * blockDim.x + threadIdx.x;
    if (i >= n4) return;
    float4 v = ((const float4*)in)[i];
    ushort4 hv = make_ushort4(__half_as_ushort(__float2half_rn(v.x)),
                              __half_as_ushort(__float2half_rn(v.y)),
                              __half_as_ushort(__float2half_rn(v.z)),
                              __half_as_ushort(__float2half_rn(v.w)));
    ((ushort4*)hi)[i] = hv;
}

// ---------------- batched transpose: W[K][N] -> T[N][K] fp16, z = which W ----
__global__ void tsplit4_kernel(const float* __restrict__ W0,
                               const float* __restrict__ W1,
                               const float* __restrict__ W2,
                               const float* __restrict__ W3) {
    __shared__ float t[32][33];
    int z = blockIdx.z;
    const float* W = (z == 0) ? W0 : (z == 1) ? W1 : (z == 2) ? W2 : W3;
    __half* Thi = g_wthi[z];
    int n0 = blockIdx.x * 32, k0 = blockIdx.y * 32;
    int tx = threadIdx.x, ty = threadIdx.y;   // block (32, 8)
    #pragma unroll
    for (int i = 0; i < 4; i++)
        t[ty + i * 8][tx] = W[(size_t)(k0 + ty + i * 8) * HIDD + n0 + tx];
    __syncthreads();
    #pragma unroll
    for (int i = 0; i < 4; i++)
        Thi[(size_t)(n0 + ty + i * 8) * HIDD + k0 + tx] =
            __float2half_rn(t[tx][ty + i * 8]);
}

// ---------------- transpose V (fp16): g_vh[m][n] -> vt[(b*2048+n)][s] ---------
__global__ void vtsplit_kernel() {
    __shared__ __half t[64][66];
    int n0 = blockIdx.x * 64, m0 = blockIdx.y * 64;
    int tx = threadIdx.x, ty = threadIdx.y;   // block (32, 8)
    #pragma unroll
    for (int i = 0; i < 8; i++) {
        int r = ty + i * 8;
        __half2 v = *(const __half2*)&g_vh[(size_t)(m0 + r) * HIDD + n0 + 2 * tx];
        t[r][2 * tx]     = __low2half(v);
        t[r][2 * tx + 1] = __high2half(v);
    }
    __syncthreads();
    int b = m0 >> 11;
    int s0 = m0 & 2047;
    #pragma unroll
    for (int i = 0; i < 8; i++) {
        int n = ty + i * 8;
        __half2 v = __halves2half2(t[2 * tx][n], t[2 * tx + 1][n]);
        *(__half2*)&g_vthi[((size_t)b * 2048 + n0 + n) * 2048 + s0 + 2 * tx] = v;
    }
}

// ---------------- HMMA fp16 GEMM core (128x128 CTA tile, 128 thr) ------------
// C = A @ B^T;  A [M][K] fp16, B [N][K] K-major fp16.  Single product, fp32 accum.
// 4 warps: warp_m = wid&1 (2), warp_n = wid>>1 (2); warp tile 64x64.
// K=64 per stage, 3-stage ring, one __syncthreads per iteration.
// smem 96KB/CTA -> 2 CTAs/SM (independent barrier domains).
#define GK 2048
#define GN 2048
#define NIT 32
#define GTB 16384                         // 128 rows x 128 B (A or B sub-tile)
#define GSTAGE (2 * GTB)                  // 32768
#define GSMEM_TOTAL (3 * GSTAGE)          // 98304

__device__ __forceinline__
void gemm_body(const __half* __restrict__ Ah,
               const __half* __restrict__ Bh,
               float* __restrict__ C,
               __half* __restrict__ Chi,
               char* smem) {
    uint32_t sb = smem_u32(smem);
    int tid = threadIdx.x, l = tid & 31, wid = tid >> 5;
    int warp_m = wid & 1, warp_n = wid >> 1;
    int bm = blockIdx.y * 128, bn = blockIdx.x * 128;

    const char* srcA = (const char*)(Ah + (size_t)bm * GK);
    const char* srcB = (const char*)(Bh + (size_t)bn * GK);

    float c[4][8][4];
    #pragma unroll
    for (int i = 0; i < 4; i++)
        #pragma unroll
        for (int j = 0; j < 8; j++)
            #pragma unroll
            for (int k = 0; k < 4; k++) c[i][j][k] = 0.0f;

    auto stage_load = [&](int ci, int st) {
        int koff = ci * 128;
        uint32_t dstA = sb + st * GSTAGE;
        uint32_t dstB = dstA + GTB;
        #pragma unroll
        for (int j = 0; j < 8; j++) {              // A + B: 8 vec each / thread
            int vec = tid + j * 128;
            int row = vec >> 3, col = (vec & 7) * 16;
            uint32_t so = SW128(row * 128 + col);
            size_t go = (size_t)row * (GK * 2) + koff + col;
            cp_async16(dstA + so, srcA + go);
            cp_async16(dstB + so, srcB + go);
        }
    };

    int rrA = (l & 7) + ((l >> 3) & 1) * 8;
    int kbA = ((l >> 4) & 1) * 16;
    int rrB = (l & 7) + ((l >> 4) & 1) * 8;
    int kbB = ((l >> 3) & 1) * 16;

    stage_load(0, 0);
    CP_COMMIT();
    stage_load(1, 1);
    CP_COMMIT();

    for (int i = 0; i < NIT; i++) {
        if (i + 1 < NIT) { CP_WAIT(1); } else { CP_WAIT(0); }
        __syncthreads();
        if (i + 2 < NIT) {
            stage_load(i + 2, (i + 2) % 3);
            CP_COMMIT();
        }

        uint32_t bA = sb + (i % 3) * GSTAGE;
        uint32_t bB = bA + GTB;

        #pragma unroll
        for (int ks = 0; ks < 4; ks++) {
            int kk = ks * 32;
            uint32_t bf[8][2];
            #pragma unroll
            for (int np = 0; np < 4; np++) {
                int rb = (warp_n * 64 + np * 16 + rrB) * 128;
                uint32_t off = rb + ((kk + kbB) ^ ((rb >> 3) & 0x70));
                uint32_t t[4];
                ldsm4(t, bB + off);
                bf[np * 2][0] = t[0]; bf[np * 2][1] = t[1];
                bf[np * 2 + 1][0] = t[2]; bf[np * 2 + 1][1] = t[3];
            }
            #pragma unroll
            for (int mt = 0; mt < 4; mt++) {
                int rb = (warp_m * 64 + mt * 16 + rrA) * 128;
                uint32_t off = rb + ((kk + kbA) ^ ((rb >> 3) & 0x70));
                uint32_t af[4];
                ldsm4(af, bA + off);
                #pragma unroll
                for (int nt = 0; nt < 8; nt++)
                    mma16816(c[mt][nt], af, bf[nt]);
            }
        }
    }

    // epilogue
    #pragma unroll
    for (int mt = 0; mt < 4; mt++) {
        #pragma unroll
        for (int nt = 0; nt < 8; nt++) {
            int m0 = bm + warp_m * 64 + mt * 16 + (l >> 2);
            int cn = bn + warp_n * 64 + nt * 8 + (l & 3) * 2;
            size_t i0 = (size_t)m0 * GN + cn, i1 = (size_t)(m0 + 8) * GN + cn;
            float v0 = c[mt][nt][0], v1 = c[mt][nt][1];
            float v2 = c[mt][nt][2], v3 = c[mt][nt][3];
            if (Chi) {
                *(uint32_t*)&Chi[i0] = pack_h2(v0, v1);
                *(uint32_t*)&Chi[i1] = pack_h2(v2, v3);
            } else {
                *(float2*)&C[i0] = make_float2(v0, v1);
                *(float2*)&C[i1] = make_float2(v2, v3);
            }
        }
    }
}

// batched QKV projection: z=0 -> Q, z=1 -> K, z=2 -> V (all fp16 hi)
__global__ __launch_bounds__(128, 2)
void gemm_qkv() {
    extern __shared__ char smem[];
    int z = blockIdx.z;
    const __half* B = g_wthi[z];
    __half* Chi = (z == 0) ? g_qhi : (z == 1) ? g_khi : g_vh;
    gemm_body(g_xh, B, nullptr, Chi, smem);
}

// output projection: fp32 out
__global__ __launch_bounds__(128, 2)
void gemm_out(float* __restrict__ C) {
    extern __shared__ char smem[];
    gemm_body(g_chi, g_wthi[3], C, nullptr, smem);
}

// ---------------- HMMA fp16 flash attention (single product) ----------------
// grid (qb=32, h=16, b=2), 128 threads (4 warps). Warp w owns q rows [w*16, w*16+16).
// smem 98.5KB -> 2 CTAs/SM to hide barrier bubbles.
#define A_SQ       0                       // Q: c0, c1 (2 x 8KB)
#define A_KV(st)   (16384 + (st) * 32768)  // K c0 (8KB), K c1 (8KB), V (16KB)
#define A_P        81920                   // P 8KB
#define A_MASK(st) (90112 + (st) * 4096)
#define A_LIST     98304                   // int count + int[32]
#define ATTN2_SMEM 98560

__global__ __launch_bounds__(128, 2)
void attn_mma() {
    extern __shared__ char sm[];
    uint32_t sb = smem_u32(sm);
    int tid = threadIdx.x, l = tid & 31, w = tid >> 5;
    int qb = blockIdx.x, h = blockIdx.y, b = blockIdx.z;

    int rrA = (l & 7) + ((l >> 3) & 1) * 8;
    int kbA = ((l >> 4) & 1) * 16;
    int rrB = (l & 7) + ((l >> 4) & 1) * 8;
    int kbB = ((l >> 3) & 1) * 16;

    const size_t qrow_base = ((size_t)b * Ss + qb * 64) * HIDD;   // elements
    const size_t colb_base = (size_t)h * 256;                     // bytes within row

    // ---- load Q tiles (c0, c1) ----
    {
        #pragma unroll
        for (int t = 0; t < 2; t++) {
            const char* base = (const char*)g_qhi + qrow_base * 2
                               + colb_base + t * 128;
            uint32_t dst = sb + A_SQ + t * 8192;
            #pragma unroll
            for (int j = 0; j < 4; j++) {
                int vec = tid + j * 128;
                int row = vec >> 3, cbt = (vec & 7) * 16;
                cp_async16(dst + SW128(row * 128 + cbt),
                           base + (size_t)row * 4096 + cbt);
            }
        }
        CP_COMMIT();
    }

    // ---- build visible-kb list ----
    int* sList = (int*)(sm + A_LIST);
    if (tid == 0) {
        int c = 0;
        for (int kb = 0; kb < NBLK; kb++)
            if (g_bany[qb * NBLK + kb]) sList[1 + c++] = kb;
        sList[0] = c;
    }
    __syncthreads();
    int cnt = sList[0];

    // ---- KV + mask prefetch ----
    auto prefetch = [&](int kb, int st) {
        uint32_t kvb = sb + A_KV(st);
        size_t krow = ((size_t)b * Ss + kb * 64) * HIDD * 2;   // bytes
        #pragma unroll
        for (int t = 0; t < 2; t++) {     // K chunk 0, chunk 1
            const char* base = (const char*)g_khi + krow + colb_base + t * 128;
            uint32_t dst = kvb + t * 8192;
            #pragma unroll
            for (int j = 0; j < 4; j++) {
                int vec = tid + j * 128;
                int row = vec >> 3, cbt = (vec & 7) * 16;
                cp_async16(dst + SW128(row * 128 + cbt),
                           base + (size_t)row * 4096 + cbt);
            }
        }
        size_t vrow = ((size_t)b * 2048 + h * 128) * 2048 * 2;  // bytes; +dh*4096
        {
            const char* base = (const char*)g_vthi + vrow + kb * 128;
            uint32_t dst = kvb + 16384;
            #pragma unroll
            for (int j = 0; j < 8; j++) {
                int vec = tid + j * 128;
                int row = vec >> 3, cbt = (vec & 7) * 16;
                cp_async16(dst + SW128(row * 128 + cbt),
                           base + (size_t)row * 4096 + cbt);
            }
        }
        {
            const char* base = (const char*)g_mask + (size_t)(qb * 64) * Ss + kb * 64;
            uint32_t dst = sb + A_MASK(st);
            #pragma unroll
            for (int j = 0; j < 2; j++) {
                int vec = tid + j * 128;
                int row = vec >> 2, cbt = (vec & 3) * 16;
                cp_async16(dst + row * 64 + cbt, base + (size_t)row * Ss + cbt);
            }
        }
    };

    prefetch(sList[1], 0);
    CP_COMMIT();

    // ---- state ----
    float o[16][4];
    #pragma unroll
    for (int i = 0; i < 16; i++)
        #pragma unroll
        for (int j = 0; j < 4; j++) o[i][j] = 0.0f;
    float m0r = -1e30f, m1r = -1e30f, l0r = 0.0f, l1r = 0.0f;

    int qrow0 = w * 16;
    int r0l = qrow0 + (l >> 2);

    for (int i = 0; i < cnt; i++) {
        int st = i & 1;
        __syncthreads();   // all warps done with stage st^1 (iter i-1) before refill
        if (i + 1 < cnt) {
            prefetch(sList[1 + i + 1], st ^ 1);
            CP_COMMIT();
            CP_WAIT(1);
        } else {
            CP_WAIT(0);
        }
        __syncthreads();

        uint32_t kvb = sb + A_KV(st);

        // ---- S = Q @ K^T (fp16) ----
        float s[8][4];
        #pragma unroll
        for (int nt = 0; nt < 8; nt++)
            #pragma unroll
            for (int j = 0; j < 4; j++) s[nt][j] = 0.0f;

        #pragma unroll
        for (int chunk = 0; chunk < 2; chunk++) {
            uint32_t bQh = sb + A_SQ + chunk * 8192;
            uint32_t bKh = kvb + chunk * 8192;
            #pragma unroll
            for (int ks = 0; ks < 4; ks++) {
                int kk = ks * 32;
                int rowA = qrow0 + rrA;
                uint32_t offA = rowA * 128 + ((kk + kbA) ^ ((rowA & 7) << 4));
                uint32_t ah[4];
                ldsm4(ah, bQh + offA);
                #pragma unroll
                for (int np = 0; np < 4; np++) {
                    int rowB = np * 16 + rrB;
                    uint32_t offB = rowB * 128 + ((kk + kbB) ^ ((rowB & 7) << 4));
                    uint32_t th[4];
                    ldsm4(th, bKh + offB);
                    uint32_t bh0[2] = {th[0], th[1]}, bh1[2] = {th[2], th[3]};
                    mma16816(s[np * 2], ah, bh0);
                    mma16816(s[np * 2 + 1], ah, bh1);
                }
            }
        }

        // ---- mask + scale + online softmax ----
        const unsigned char* mk = (const unsigned char*)(sm + A_MASK(st))
                                  + r0l * 64 + (l & 3) * 2;
        float mx0 = -1e30f, mx1 = -1e30f;
        #pragma unroll
        for (int nt = 0; nt < 8; nt++) {
            int cb = nt * 8;
            float t00 = mk[cb]       ? s[nt][0] * SCALE_F : -1e30f;
            float t01 = mk[cb + 1]   ? s[nt][1] * SCALE_F : -1e30f;
            float t10 = mk[cb + 512] ? s[nt][2] * SCALE_F : -1e30f;
            float t11 = mk[cb + 513] ? s[nt][3] * SCALE_F : -1e30f;
            s[nt][0] = t00; s[nt][1] = t01; s[nt][2] = t10; s[nt][3] = t11;
            mx0 = fmaxf(mx0, fmaxf(t00, t01));
            mx1 = fmaxf(mx1, fmaxf(t10, t11));
        }
        mx0 = fmaxf(mx0, __shfl_xor_sync(0xffffffffu, mx0, 1));
        mx0 = fmaxf(mx0, __shfl_xor_sync(0xffffffffu, mx0, 2));
        mx1 = fmaxf(mx1, __shfl_xor_sync(0xffffffffu, mx1, 1));
        mx1 = fmaxf(mx1, __shfl_xor_sync(0xffffffffu, mx1, 2));
        float mn0 = fmaxf(m0r, mx0), mn1 = fmaxf(m1r, mx1);
        float sc0 = __expf(m0r - mn0), sc1 = __expf(m1r - mn1);
        m0r = mn0; m1r = mn1;

        // ---- P = exp(S - m), write fp16 to smem (full-column swizzle) ----
        float sum0 = 0.0f, sum1 = 0.0f;
        int colb = (l & 3) * 4;
        int sw0 = (r0l & 7) << 4;                 // same for r0l and r0l+8
        uint32_t rb0 = r0l * 128;
        uint32_t rb1 = (r0l + 8) * 128;
        #pragma unroll
        for (int nt = 0; nt < 8; nt++) {
            float p00 = __expf(s[nt][0] - mn0);
            float p01 = __expf(s[nt][1] - mn0);
            float p10 = __expf(s[nt][2] - mn1);
            float p11 = __expf(s[nt][3] - mn1);
            sum0 += p00 + p01;
            sum1 += p10 + p11;
            uint32_t colsw = (uint32_t)((nt * 16 + colb) ^ sw0);
            *(uint32_t*)(sm + A_P + rb0 + colsw) = pack_h2(p00, p01);
            *(uint32_t*)(sm + A_P + rb1 + colsw) = pack_h2(p10, p11);
        }
        sum0 += __shfl_xor_sync(0xffffffffu, sum0, 1);
        sum0 += __shfl_xor_sync(0xffffffffu, sum0, 2);
        sum1 += __shfl_xor_sync(0xffffffffu, sum1, 1);
        sum1 += __shfl_xor_sync(0xffffffffu, sum1, 2);
        l0r = l0r * sc0 + sum0;
        l1r = l1r * sc1 + sum1;

        // ---- O rescale + O += P @ Vt (fp16) ----
        #pragma unroll
        for (int nt = 0; nt < 16; nt++) {
            o[nt][0] *= sc0; o[nt][1] *= sc0;
            o[nt][2] *= sc1; o[nt][3] *= sc1;
        }
        __syncwarp();

        uint32_t bPh = sb + A_P;
        uint32_t bVh = kvb + 16384;
        #pragma unroll
        for (int ks = 0; ks < 4; ks++) {
            int kk = ks * 32;
            int rowA = qrow0 + rrA;
            uint32_t offA = rowA * 128 + ((kk + kbA) ^ ((rowA & 7) << 4));
            uint32_t ph[4];
            ldsm4(ph, bPh + offA);
            #pragma unroll
            for (int np = 0; np < 8; np++) {
                int rowB = np * 16 + rrB;
                uint32_t offB = rowB * 128 + ((kk + kbB) ^ ((rowB & 7) << 4));
                uint32_t th[4];
                ldsm4(th, bVh + offB);
                uint32_t vh0[2] = {th[0], th[1]}, vh1[2] = {th[2], th[3]};
                mma16816(o[np * 2], ph, vh0);
                mma16816(o[np * 2 + 1], ph, vh1);
            }
        }
    }

    // ---- epilogue: O /= l, write ctx fp16 ----
    float inv0 = 1.0f / l0r, inv1 = 1.0f / l1r;
    size_t row0 = (size_t)b * Ss + qb * 64 + qrow0 + (l >> 2);
    size_t row1 = row0 + 8;
    int cn0 = h * 128 + (l & 3) * 2;
    #pragma unroll
    for (int nt = 0; nt < 16; nt++) {
        int cn = cn0 + nt * 8;
        float v0 = o[nt][0] * inv0, v1 = o[nt][1] * inv0;
        float v2 = o[nt][2] * inv1, v3 = o[nt][3] * inv1;
        size_t i0 = row0 * HIDD + cn, i1 = row1 * HIDD + cn;
        *(uint32_t*)&g_chi[i0] = pack_h2(v0, v1);
        *(uint32_t*)&g_chi[i1] = pack_h2(v2, v3);
    }
}

// ---------------- launch ----------------
extern "C" void kernel_launch(void* const* d_in, const int* in_sizes, int n_in,
                              void* d_out, int out_size) {
    const float* X  = (const float*)d_in[0];
    const float* Wq = (const float*)d_in[1];
    const float* Wk = (const float*)d_in[2];
    const float* Wv = (const float*)d_in[3];
    const float* Wo = (const float*)d_in[4];
    const void*  Mraw = d_in[5];
    float* out = (float*)d_out;

    cudaFuncSetAttribute(gemm_qkv,
                         cudaFuncAttributeMaxDynamicSharedMemorySize, GSMEM_TOTAL);
    cudaFuncSetAttribute(gemm_out,
                         cudaFuncAttributeMaxDynamicSharedMemorySize, GSMEM_TOTAL);
    cudaFuncSetAttribute(attn_mma,
                         cudaFuncAttributeMaxDynamicSharedMemorySize, ATTN2_SMEM);

    __half* pxh;
    cudaGetSymbolAddress((void**)&pxh, g_xh);

    // 1: fused mask canonicalize + block-any
    mask_kernel<<<dim3(NBLK, NBLK), 256>>>((const unsigned char*)Mraw);

    // 2: X convert, 3: W transposes (batched)
    cvt_kernel<<<(MROWS * HIDD / 4 + 255) / 256, 256>>>(X, pxh, MROWS * HIDD / 4);
    tsplit4_kernel<<<dim3(HIDD / 32, HIDD / 32, 4), dim3(32, 8)>>>(Wq, Wk, Wv, Wo);

    // 4: batched Q/K/V projections (fp16 HMMA, 128x128 tiles, 4 warps, 2 CTA/SM)
    gemm_qkv<<<dim3(GN / 128, MROWS / 128, 3), 128, GSMEM_TOTAL>>>();

    // 5: V transpose (fp16, vectorized)
    vtsplit_kernel<<<dim3(HIDD / 64, MROWS / 64), dim3(32, 8)>>>();

    // 6: attention (fp16 single product, 2 CTA/SM)
    attn_mma<<<dim3(NBLK, Hh, Bb), 128, ATTN2_SMEM>>>();

    // 7: output projection
    gemm_out<<<dim3(GN / 128, MROWS / 128), 128, GSMEM_TOTAL>>>(out);
}